// round 8
// baseline (speedup 1.0000x reference)
#include <cuda_runtime.h>
#include <cuda_bf16.h>
#include <cstdint>

// Problem constants (fixed shapes per reference: N=8192, D=1024, 128 classes)
#define NMAX 8192
#define DMAX 1024
#define MARGIN 1.0f
#define EPS 1e-6f

// Scratch (static __device__ arrays; no allocation).
__device__ float g_G[(size_t)NMAX * (size_t)NMAX];          // 256 MB Gram
__device__ float g_sq[NMAX];                                // ||e_i||^2 (fp32)
__device__ float g_s[NMAX];                                 // sum_k e_ik
__device__ __nv_bfloat16 g_Ehi[(size_t)NMAX * DMAX];        // bf16 hi part
__device__ __nv_bfloat16 g_Elo[(size_t)NMAX * DMAX];        // bf16 lo part

// ===========================================================================
// Helpers
// ===========================================================================
__device__ __forceinline__ uint32_t smem_to_u32(const void* p) {
    uint32_t a;
    asm("{ .reg .u64 t; cvta.to.shared.u64 t, %1; cvt.u32.u64 %0, t; }" : "=r"(a) : "l"(p));
    return a;
}
__device__ __forceinline__ void cp_async16(uint32_t smem_dst, const void* gsrc) {
    asm volatile("cp.async.cg.shared.global [%0], [%1], 16;\n" :: "r"(smem_dst), "l"(gsrc));
}
#define CP_ASYNC_COMMIT() asm volatile("cp.async.commit_group;\n" ::: "memory")
#define CP_ASYNC_WAIT0()  asm volatile("cp.async.wait_group 0;\n" ::: "memory")

__device__ __forceinline__ void ldmatrix_x4(uint32_t& r0, uint32_t& r1, uint32_t& r2, uint32_t& r3,
                                            uint32_t addr) {
    asm volatile("ldmatrix.sync.aligned.m8n8.x4.shared.b16 {%0,%1,%2,%3}, [%4];"
                 : "=r"(r0), "=r"(r1), "=r"(r2), "=r"(r3) : "r"(addr));
}
__device__ __forceinline__ void mma_bf16(float& c0, float& c1, float& c2, float& c3,
                                         uint32_t a0, uint32_t a1, uint32_t a2, uint32_t a3,
                                         uint32_t b0, uint32_t b1) {
    asm volatile("mma.sync.aligned.m16n8k16.row.col.f32.bf16.bf16.f32 "
                 "{%0,%1,%2,%3}, {%4,%5,%6,%7}, {%8,%9}, {%0,%1,%2,%3};"
                 : "+f"(c0), "+f"(c1), "+f"(c2), "+f"(c3)
                 : "r"(a0), "r"(a1), "r"(a2), "r"(a3), "r"(b0), "r"(b1));
}

// ===========================================================================
// Fused prep: split fp32 -> (hi, lo) bf16 pair AND row stats (sq, s).
// One block per row; D/4 float4 elements handled by 256 threads.
// Block 0 thread 0 zeroes the output scalar.
// ===========================================================================
__global__ void __launch_bounds__(256) prep_kernel(const float* __restrict__ E,
                                                   int N, int D,
                                                   float* __restrict__ out) {
    int i = blockIdx.x;
    if (i == 0 && threadIdx.x == 0) out[0] = 0.0f;
    float a = 0.0f, b = 0.0f;
    for (int k = threadIdx.x; k < D / 4; k += blockDim.x) {
        int idx = i * (D / 4) + k;
        float4 v = ((const float4*)E)[idx];
        a = fmaf(v.x, v.x, a); a = fmaf(v.y, v.y, a);
        a = fmaf(v.z, v.z, a); a = fmaf(v.w, v.w, a);
        b += v.x + v.y + v.z + v.w;
        __nv_bfloat16 h0 = __float2bfloat16(v.x), h1 = __float2bfloat16(v.y);
        __nv_bfloat16 h2 = __float2bfloat16(v.z), h3 = __float2bfloat16(v.w);
        __nv_bfloat16 l0 = __float2bfloat16(v.x - __bfloat162float(h0));
        __nv_bfloat16 l1 = __float2bfloat16(v.y - __bfloat162float(h1));
        __nv_bfloat16 l2 = __float2bfloat16(v.z - __bfloat162float(h2));
        __nv_bfloat16 l3 = __float2bfloat16(v.w - __bfloat162float(h3));
        ushort4 hv, lv;
        hv.x = __bfloat16_as_ushort(h0); hv.y = __bfloat16_as_ushort(h1);
        hv.z = __bfloat16_as_ushort(h2); hv.w = __bfloat16_as_ushort(h3);
        lv.x = __bfloat16_as_ushort(l0); lv.y = __bfloat16_as_ushort(l1);
        lv.z = __bfloat16_as_ushort(l2); lv.w = __bfloat16_as_ushort(l3);
        ((ushort4*)g_Ehi)[idx] = hv;
        ((ushort4*)g_Elo)[idx] = lv;
    }
#pragma unroll
    for (int off = 16; off > 0; off >>= 1) {
        a += __shfl_down_sync(0xffffffffu, a, off);
        b += __shfl_down_sync(0xffffffffu, b, off);
    }
    __shared__ float sa[8], sb[8];
    int w = threadIdx.x >> 5, l = threadIdx.x & 31;
    if (l == 0) { sa[w] = a; sb[w] = b; }
    __syncthreads();
    if (threadIdx.x == 0) {
        float A = 0.0f, B = 0.0f;
        int nw = blockDim.x >> 5;
        for (int x = 0; x < nw; x++) { A += sa[x]; B += sb[x]; }
        g_sq[i] = A;
        g_s[i] = B;
    }
}

// ===========================================================================
// Gram GEMM via mma.sync bf16 (HMMA): G = E*E^T, split-bf16 3-pass
// (hi*hi + lo*hi + hi*lo), fp32 accumulators.
// CTA tile 128(M) x 256(N), 8 warps of 64x64, BK=64, 2-stage cp.async.
// Symmetric: tiles with 2*bj <= bi computed; mirror-scatter covers the rest
// (duplicate writes on diagonal-straddling tiles are bitwise-identical).
// ===========================================================================
#define GSTAGES 2
#define A_BYTES (128 * 128)              /* 16 KB */
#define B_BYTES (256 * 128)              /* 32 KB */
#define STAGE_BYTES (A_BYTES + B_BYTES)  /* 48 KB */
#define GRAM_SMEM (GSTAGES * STAGE_BYTES + 1024)

__global__ void __launch_bounds__(256, 1) gram_mma_kernel(int N, int D) {
    int bi = blockIdx.y, bj = blockIdx.x;
    if (bj * 2 > bi) return;

    extern __shared__ char dsmem[];
    uint32_t base = (smem_to_u32(dsmem) + 1023u) & ~1023u;

    const int tid = threadIdx.x;
    const int wid = tid >> 5, lane = tid & 31;
    const int wm = wid & 1;       // warp row (2 x 64 = 128 M)
    const int wn = wid >> 1;      // warp col (4 x 64 = 256 N)

    const int KC = D / 64;        // k-chunks per pass (16)
    const int NC = 3 * KC;        // total chunks (48)
    const size_t rowstride = (size_t)D * 2;  // bytes per bf16 row

    const int l_kk = tid & 7;     // 16B segment within 128B row
    const int l_r0 = tid >> 3;    // base row 0..31
    auto load_chunk = [&](int c) {
        int pass = c / KC;
        int kc = c - pass * KC;
        const char* Asrc = (const char*)((pass == 1) ? g_Elo : g_Ehi);
        const char* Bsrc = (const char*)((pass == 2) ? g_Elo : g_Ehi);
        uint32_t sb = base + (uint32_t)(c & 1) * STAGE_BYTES;
        const char* ga = Asrc + (size_t)(bi * 128) * rowstride + (size_t)kc * 128 + l_kk * 16;
        const char* gb = Bsrc + (size_t)(bj * 256) * rowstride + (size_t)kc * 128 + l_kk * 16;
        uint32_t swb = (uint32_t)((l_kk * 16) ^ ((l_r0 & 7) << 4));
#pragma unroll
        for (int i = 0; i < 4; i++) {
            int r = l_r0 + i * 32;
            cp_async16(sb + (uint32_t)(r * 128) + swb, ga + (size_t)r * rowstride);
        }
        uint32_t sbb = sb + A_BYTES;
#pragma unroll
        for (int i = 0; i < 8; i++) {
            int r = l_r0 + i * 32;
            cp_async16(sbb + (uint32_t)(r * 128) + swb, gb + (size_t)r * rowstride);
        }
        CP_ASYNC_COMMIT();
    };

    // A fragments: 4 m16 tiles at rows wm*64 + mt*16
    uint32_t a_row[4], a_xor[4];
#pragma unroll
    for (int mt = 0; mt < 4; mt++) {
        int r = wm * 64 + mt * 16 + (lane & 15);
        a_row[mt] = (uint32_t)(r * 128);
        a_xor[mt] = (uint32_t)((r & 7) << 4);
    }
    const uint32_t a_cb = (uint32_t)((lane >> 4) * 16);

    // B fragments: 4 n16 groups at rows wn*64 + g*16
    uint32_t b_row[4], b_xor[4];
#pragma unroll
    for (int g = 0; g < 4; g++) {
        int r = wn * 64 + g * 16 + (lane & 7) + ((lane >> 4) & 1) * 8;
        b_row[g] = (uint32_t)(r * 128);
        b_xor[g] = (uint32_t)((r & 7) << 4);
    }
    const uint32_t b_cb = (uint32_t)(((lane >> 3) & 1) * 16);

    float acc[4][8][4];
#pragma unroll
    for (int mt = 0; mt < 4; mt++)
#pragma unroll
        for (int nt = 0; nt < 8; nt++)
#pragma unroll
            for (int x = 0; x < 4; x++) acc[mt][nt][x] = 0.0f;

    load_chunk(0);

    for (int c = 0; c < NC; c++) {
        CP_ASYNC_WAIT0();          // chunk c resident
        __syncthreads();           // all warps done computing previous chunk
        if (c + 1 < NC) load_chunk(c + 1);   // fill the other stage

        uint32_t sA = base + (uint32_t)(c & 1) * STAGE_BYTES;
        uint32_t sB = sA + A_BYTES;

#pragma unroll
        for (int ks = 0; ks < 4; ks++) {
            uint32_t kb = (uint32_t)(ks * 32);
            uint32_t af[4][4];
#pragma unroll
            for (int mt = 0; mt < 4; mt++) {
                uint32_t addr = sA + a_row[mt] + ((kb + a_cb) ^ a_xor[mt]);
                ldmatrix_x4(af[mt][0], af[mt][1], af[mt][2], af[mt][3], addr);
            }
            uint32_t bfr[4][4];
#pragma unroll
            for (int g = 0; g < 4; g++) {
                uint32_t addr = sB + b_row[g] + ((kb + b_cb) ^ b_xor[g]);
                ldmatrix_x4(bfr[g][0], bfr[g][1], bfr[g][2], bfr[g][3], addr);
            }
#pragma unroll
            for (int mt = 0; mt < 4; mt++)
#pragma unroll
                for (int g = 0; g < 4; g++) {
                    mma_bf16(acc[mt][g * 2][0], acc[mt][g * 2][1], acc[mt][g * 2][2], acc[mt][g * 2][3],
                             af[mt][0], af[mt][1], af[mt][2], af[mt][3], bfr[g][0], bfr[g][1]);
                    mma_bf16(acc[mt][g * 2 + 1][0], acc[mt][g * 2 + 1][1], acc[mt][g * 2 + 1][2], acc[mt][g * 2 + 1][3],
                             af[mt][0], af[mt][1], af[mt][2], af[mt][3], bfr[g][2], bfr[g][3]);
                }
        }
    }

    // Epilogue: direct stores + mirror scatter (always; duplicates identical).
    const int qr = lane >> 2;
    const int qc = (lane & 3) * 2;
#pragma unroll
    for (int mt = 0; mt < 4; mt++) {
        int gr0 = bi * 128 + wm * 64 + mt * 16 + qr;
#pragma unroll
        for (int nt = 0; nt < 8; nt++) {
            int gc = bj * 256 + wn * 64 + nt * 8 + qc;
            float* p0 = g_G + (size_t)gr0 * N + gc;
            float* p1 = g_G + (size_t)(gr0 + 8) * N + gc;
            *(float2*)p0 = make_float2(acc[mt][nt][0], acc[mt][nt][1]);
            *(float2*)p1 = make_float2(acc[mt][nt][2], acc[mt][nt][3]);
            g_G[(size_t)gc * N + gr0]           = acc[mt][nt][0];
            g_G[(size_t)(gc + 1) * N + gr0]     = acc[mt][nt][1];
            g_G[(size_t)gc * N + gr0 + 8]       = acc[mt][nt][2];
            g_G[(size_t)(gc + 1) * N + gr0 + 8] = acc[mt][nt][3];
        }
    }
}

// ===========================================================================
// Mining + loss. Selection on d^2 with packed 64-bit keys:
//   min-key  = (f32bits(d2) << 32) | j    -> min d2, first index tie-break
//   max-key  = (f32bits(d2) << 32) | ~j   -> max d2, first index tie-break
// Pass 1: d^2, hardest positive (max-key) AND overall min negative (min-key).
// Pass 2: semi-hard window min (min-key over d2 > dp2), bound (sqrt+margin)^2.
// Final dp/dn recomputed exactly with torch EPS correction.
// ===========================================================================
typedef unsigned long long u64;

__global__ void __launch_bounds__(256) mine_kernel(const int* __restrict__ target,
                                                   int N, int D,
                                                   float* __restrict__ out) {
    int i = blockIdx.x;
    __shared__ float ds[NMAX];          // d^2 for negatives, -1 sentinel else
    __shared__ u64 rk1[256];            // reduction buffers
    __shared__ u64 rk2[256];

    const int tid = threadIdx.x;
    const int ti = target[i];
    const float sqi = g_sq[i];
    const float* Gi = g_G + (size_t)i * N;
    const float4* Gi4 = (const float4*)Gi;
    const float4* sq4 = (const float4*)g_sq;
    const int4*   tg4 = (const int4*)target;

    u64 maxpos = 0ULL;                  // no-positive sentinel
    u64 minneg = ~0ULL;                 // no-negative sentinel
    const int NV = NMAX / 4 / 256;      // 8 iterations
#pragma unroll
    for (int v = 0; v < NV; v++) {
        int idx = tid + v * 256;
        float4 g = Gi4[idx];
        float4 s = sq4[idx];
        int4   t = tg4[idx];
        unsigned j = (unsigned)(idx * 4);
        float4 d2;
        d2.x = fmaxf(sqi + s.x - 2.0f * g.x, 0.0f);
        d2.y = fmaxf(sqi + s.y - 2.0f * g.y, 0.0f);
        d2.z = fmaxf(sqi + s.z - 2.0f * g.z, 0.0f);
        d2.w = fmaxf(sqi + s.w - 2.0f * g.w, 0.0f);
        float4 r = d2;
        u64 k;
        k = ((u64)__float_as_uint(d2.x) << 32);
        if (t.x == ti) { r.x = -1.0f; if ((int)j != i) { u64 kp = k | (unsigned)~(j); if (kp > maxpos) maxpos = kp; } }
        else           { u64 kn = k | j; if (kn < minneg) minneg = kn; }
        k = ((u64)__float_as_uint(d2.y) << 32);
        if (t.y == ti) { r.y = -1.0f; if ((int)(j + 1) != i) { u64 kp = k | (unsigned)~(j + 1); if (kp > maxpos) maxpos = kp; } }
        else           { u64 kn = k | (j + 1); if (kn < minneg) minneg = kn; }
        k = ((u64)__float_as_uint(d2.z) << 32);
        if (t.z == ti) { r.z = -1.0f; if ((int)(j + 2) != i) { u64 kp = k | (unsigned)~(j + 2); if (kp > maxpos) maxpos = kp; } }
        else           { u64 kn = k | (j + 2); if (kn < minneg) minneg = kn; }
        k = ((u64)__float_as_uint(d2.w) << 32);
        if (t.w == ti) { r.w = -1.0f; if ((int)(j + 3) != i) { u64 kp = k | (unsigned)~(j + 3); if (kp > maxpos) maxpos = kp; } }
        else           { u64 kn = k | (j + 3); if (kn < minneg) minneg = kn; }
        ((float4*)ds)[idx] = r;
    }
    rk1[tid] = maxpos; rk2[tid] = minneg;
    __syncthreads();
    for (int st = 128; st > 0; st >>= 1) {
        if (tid < st) {
            if (rk1[tid + st] > rk1[tid]) rk1[tid] = rk1[tid + st];
            if (rk2[tid + st] < rk2[tid]) rk2[tid] = rk2[tid + st];
        }
        __syncthreads();
    }
    const u64 posk = rk1[0];
    const u64 negk = rk2[0];
    const float dp2 = __uint_as_float((unsigned)(posk >> 32));
    __syncthreads();

    // Pass 2: semi-hard window min over { d2 > dp2 }.
    u64 minwin = ~0ULL;
#pragma unroll
    for (int v = 0; v < NV; v++) {
        int idx = tid + v * 256;
        float4 d = ((const float4*)ds)[idx];
        unsigned j = (unsigned)(idx * 4);
        if (d.x > dp2) { u64 k = ((u64)__float_as_uint(d.x) << 32) | j;       if (k < minwin) minwin = k; }
        if (d.y > dp2) { u64 k = ((u64)__float_as_uint(d.y) << 32) | (j + 1); if (k < minwin) minwin = k; }
        if (d.z > dp2) { u64 k = ((u64)__float_as_uint(d.z) << 32) | (j + 2); if (k < minwin) minwin = k; }
        if (d.w > dp2) { u64 k = ((u64)__float_as_uint(d.w) << 32) | (j + 3); if (k < minwin) minwin = k; }
    }
    rk1[tid] = minwin;
    __syncthreads();
    for (int st = 128; st > 0; st >>= 1) {
        if (tid < st) {
            if (rk1[tid + st] < rk1[tid]) rk1[tid] = rk1[tid + st];
        }
        __syncthreads();
    }

    if (tid == 0) {
        const u64 wink = rk1[0];
        int p = (posk == 0ULL) ? 0 : (int)(~(unsigned)posk);
        const float dpv = sqrtf(fmaxf(dp2, 0.0f));
        const float hi2 = (dpv + MARGIN) * (dpv + MARGIN);
        int neg;
        if (wink != ~0ULL && __uint_as_float((unsigned)(wink >> 32)) < hi2)
            neg = (int)(unsigned)wink;
        else
            neg = (negk == ~0ULL) ? 0 : (int)(unsigned)negk;

        float si = g_s[i];
        float epsC = (float)D * EPS * EPS;

        float d2p = sqi + g_sq[p] - 2.0f * Gi[p];
        float dp = sqrtf(fmaxf(d2p + 2.0f * EPS * (si - g_s[p]) + epsC, 0.0f));
        float d2n = sqi + g_sq[neg] - 2.0f * Gi[neg];
        float dn = sqrtf(fmaxf(d2n + 2.0f * EPS * (si - g_s[neg]) + epsC, 0.0f));

        float term = fmaxf(dp - dn + MARGIN, 0.0f);
        atomicAdd(out, term / (float)N);
    }
}

// ---------------------------------------------------------------------------
extern "C" void kernel_launch(void* const* d_in, const int* in_sizes, int n_in,
                              void* d_out, int out_size) {
    const float* E = (const float*)d_in[0];   // embeddings [N, D] fp32
    const int* target = (const int*)d_in[1];  // [N] int32
    float* out = (float*)d_out;

    int N = in_sizes[1];
    int D = in_sizes[0] / N;

    prep_kernel<<<N, 256>>>(E, N, D, out);

    cudaFuncSetAttribute(gram_mma_kernel, cudaFuncAttributeMaxDynamicSharedMemorySize, GRAM_SMEM);
    dim3 grid(N / 256, N / 128);
    gram_mma_kernel<<<grid, 256, GRAM_SMEM>>>(N, D);

    mine_kernel<<<N, 256>>>(target, N, D, out);
}

// round 9
// speedup vs baseline: 1.8187x; 1.8187x over previous
#include <cuda_runtime.h>
#include <cuda_fp16.h>
#include <cstdint>

// Problem constants (fixed shapes per reference: N=8192, D=1024, 128 classes)
#define NMAX 8192
#define DMAX 1024
#define MARGIN 1.0f
#define EPS 1e-6f

// Scratch (static __device__ arrays; no allocation).
__device__ float g_G[(size_t)NMAX * (size_t)NMAX];   // 256 MB Gram
__device__ float g_sq[NMAX];                         // ||e_i||^2 (fp32)
__device__ float g_s[NMAX];                          // sum_k e_ik
__device__ __half g_Eh[(size_t)NMAX * DMAX];         // fp16 embeddings

// ===========================================================================
// Helpers
// ===========================================================================
__device__ __forceinline__ uint32_t smem_to_u32(const void* p) {
    uint32_t a;
    asm("{ .reg .u64 t; cvta.to.shared.u64 t, %1; cvt.u32.u64 %0, t; }" : "=r"(a) : "l"(p));
    return a;
}
__device__ __forceinline__ void cp_async16(uint32_t smem_dst, const void* gsrc) {
    asm volatile("cp.async.cg.shared.global [%0], [%1], 16;\n" :: "r"(smem_dst), "l"(gsrc));
}
#define CP_ASYNC_COMMIT() asm volatile("cp.async.commit_group;\n" ::: "memory")
#define CP_ASYNC_WAIT1()  asm volatile("cp.async.wait_group 1;\n" ::: "memory")

__device__ __forceinline__ void ldmatrix_x4(uint32_t& r0, uint32_t& r1, uint32_t& r2, uint32_t& r3,
                                            uint32_t addr) {
    asm volatile("ldmatrix.sync.aligned.m8n8.x4.shared.b16 {%0,%1,%2,%3}, [%4];"
                 : "=r"(r0), "=r"(r1), "=r"(r2), "=r"(r3) : "r"(addr));
}
__device__ __forceinline__ void mma_f16(float& c0, float& c1, float& c2, float& c3,
                                        uint32_t a0, uint32_t a1, uint32_t a2, uint32_t a3,
                                        uint32_t b0, uint32_t b1) {
    asm volatile("mma.sync.aligned.m16n8k16.row.col.f32.f16.f16.f32 "
                 "{%0,%1,%2,%3}, {%4,%5,%6,%7}, {%8,%9}, {%0,%1,%2,%3};"
                 : "+f"(c0), "+f"(c1), "+f"(c2), "+f"(c3)
                 : "r"(a0), "r"(a1), "r"(a2), "r"(a3), "r"(b0), "r"(b1));
}

// ===========================================================================
// Fused prep: fp32 -> fp16 convert AND row stats (sq, s). One block per row.
// Block 0 thread 0 zeroes the output scalar.
// ===========================================================================
__global__ void __launch_bounds__(256) prep_kernel(const float* __restrict__ E,
                                                   int N, int D,
                                                   float* __restrict__ out) {
    int i = blockIdx.x;
    if (i == 0 && threadIdx.x == 0) out[0] = 0.0f;
    float a = 0.0f, b = 0.0f;
    for (int k = threadIdx.x; k < D / 4; k += blockDim.x) {
        int idx = i * (D / 4) + k;
        float4 v = ((const float4*)E)[idx];
        a = fmaf(v.x, v.x, a); a = fmaf(v.y, v.y, a);
        a = fmaf(v.z, v.z, a); a = fmaf(v.w, v.w, a);
        b += v.x + v.y + v.z + v.w;
        __half2 h01 = __floats2half2_rn(v.x, v.y);
        __half2 h23 = __floats2half2_rn(v.z, v.w);
        uint2 hv;
        hv.x = *(const uint32_t*)&h01;
        hv.y = *(const uint32_t*)&h23;
        ((uint2*)g_Eh)[idx] = hv;
    }
#pragma unroll
    for (int off = 16; off > 0; off >>= 1) {
        a += __shfl_down_sync(0xffffffffu, a, off);
        b += __shfl_down_sync(0xffffffffu, b, off);
    }
    __shared__ float sa[8], sb[8];
    int w = threadIdx.x >> 5, l = threadIdx.x & 31;
    if (l == 0) { sa[w] = a; sb[w] = b; }
    __syncthreads();
    if (threadIdx.x == 0) {
        float A = 0.0f, B = 0.0f;
        int nw = blockDim.x >> 5;
        for (int x = 0; x < nw; x++) { A += sa[x]; B += sb[x]; }
        g_sq[i] = A;
        g_s[i] = B;
    }
}

// ===========================================================================
// Gram GEMM via mma.sync fp16 (HMMA): G = E*E^T, SINGLE pass, fp32 accum.
// Structure identical to the proven R6/R7 kernel (3-stage cp.async, CTA tile
// 128x128, 8 warps of 32x64, 2 CTAs/SM) — only the dtype and chunk count
// changed (16 chunks instead of 48).
// Symmetric: only bj<=bi tile pairs computed; mirror tile scatter-written.
// ===========================================================================
#define GSTAGES 3
#define A_BYTES (128 * 128)              /* 16 KB */
#define B_BYTES (128 * 128)              /* 16 KB */
#define STAGE_BYTES (A_BYTES + B_BYTES)  /* 32 KB */
#define GRAM_SMEM (GSTAGES * STAGE_BYTES + 1024)

__global__ void __launch_bounds__(256) gram_mma_kernel(int N, int D) {
    int bi = blockIdx.y, bj = blockIdx.x;
    if (bj > bi) return;

    extern __shared__ char dsmem[];
    uint32_t base = (smem_to_u32(dsmem) + 1023u) & ~1023u;

    const int tid = threadIdx.x;
    const int wid = tid >> 5, lane = tid & 31;
    const int wm = wid & 3;       // warp row (4 x 32 = 128 M)
    const int wn = wid >> 2;      // warp col (2 x 64 = 128 N)

    const int NC = D / 64;        // 16 chunks, single pass
    const size_t rowstride = (size_t)D * 2;  // bytes per fp16 row

    const int l_kk = tid & 7;     // 16B segment within 128B row
    const int l_r0 = tid >> 3;    // rows l_r0 + 32*i
    auto load_chunk = [&](int c) {
        const char* Esrc = (const char*)g_Eh;
        uint32_t sb = base + (uint32_t)(c % GSTAGES) * STAGE_BYTES;
        const char* ga = Esrc + (size_t)(bi * 128) * rowstride + (size_t)c * 128 + l_kk * 16;
        const char* gb = Esrc + (size_t)(bj * 128) * rowstride + (size_t)c * 128 + l_kk * 16;
#pragma unroll
        for (int i = 0; i < 4; i++) {
            int r = l_r0 + i * 32;
            uint32_t sw = (uint32_t)(r * 128) + (uint32_t)((l_kk * 16) ^ ((r & 7) << 4));
            cp_async16(sb + sw, ga + (size_t)r * rowstride);
            cp_async16(sb + A_BYTES + sw, gb + (size_t)r * rowstride);
        }
        CP_ASYNC_COMMIT();
    };

    uint32_t a_row[2], a_xor[2];
#pragma unroll
    for (int mt = 0; mt < 2; mt++) {
        int r = wm * 32 + mt * 16 + (lane & 15);
        a_row[mt] = (uint32_t)(r * 128);
        a_xor[mt] = (uint32_t)((r & 7) << 4);
    }
    const uint32_t a_cb = (uint32_t)((lane >> 4) * 16);

    uint32_t b_row[4], b_xor[4];
#pragma unroll
    for (int g = 0; g < 4; g++) {
        int r = wn * 64 + g * 16 + (lane & 7) + ((lane >> 4) & 1) * 8;
        b_row[g] = (uint32_t)(r * 128);
        b_xor[g] = (uint32_t)((r & 7) << 4);
    }
    const uint32_t b_cb = (uint32_t)(((lane >> 3) & 1) * 16);

    float acc[2][8][4];
#pragma unroll
    for (int mt = 0; mt < 2; mt++)
#pragma unroll
        for (int nt = 0; nt < 8; nt++)
#pragma unroll
            for (int x = 0; x < 4; x++) acc[mt][nt][x] = 0.0f;

    load_chunk(0);
    load_chunk(1);

    for (int c = 0; c < NC; c++) {
        CP_ASYNC_WAIT1();
        __syncthreads();
        if (c + 2 < NC) load_chunk(c + 2);

        uint32_t sA = base + (uint32_t)(c % GSTAGES) * STAGE_BYTES;
        uint32_t sB = sA + A_BYTES;

#pragma unroll
        for (int ks = 0; ks < 4; ks++) {
            uint32_t kb = (uint32_t)(ks * 32);
            uint32_t af[2][4];
#pragma unroll
            for (int mt = 0; mt < 2; mt++) {
                uint32_t addr = sA + a_row[mt] + ((kb + a_cb) ^ a_xor[mt]);
                ldmatrix_x4(af[mt][0], af[mt][1], af[mt][2], af[mt][3], addr);
            }
            uint32_t bfr[4][4];
#pragma unroll
            for (int g = 0; g < 4; g++) {
                uint32_t addr = sB + b_row[g] + ((kb + b_cb) ^ b_xor[g]);
                ldmatrix_x4(bfr[g][0], bfr[g][1], bfr[g][2], bfr[g][3], addr);
            }
#pragma unroll
            for (int mt = 0; mt < 2; mt++)
#pragma unroll
                for (int g = 0; g < 4; g++) {
                    mma_f16(acc[mt][g * 2][0], acc[mt][g * 2][1], acc[mt][g * 2][2], acc[mt][g * 2][3],
                            af[mt][0], af[mt][1], af[mt][2], af[mt][3], bfr[g][0], bfr[g][1]);
                    mma_f16(acc[mt][g * 2 + 1][0], acc[mt][g * 2 + 1][1], acc[mt][g * 2 + 1][2], acc[mt][g * 2 + 1][3],
                            af[mt][0], af[mt][1], af[mt][2], af[mt][3], bfr[g][2], bfr[g][3]);
                }
        }
    }

    const int qr = lane >> 2;
    const int qc = (lane & 3) * 2;
#pragma unroll
    for (int mt = 0; mt < 2; mt++) {
        int gr0 = bi * 128 + wm * 32 + mt * 16 + qr;
#pragma unroll
        for (int nt = 0; nt < 8; nt++) {
            int gc = bj * 128 + wn * 64 + nt * 8 + qc;
            float* p0 = g_G + (size_t)gr0 * N + gc;
            float* p1 = g_G + (size_t)(gr0 + 8) * N + gc;
            *(float2*)p0 = make_float2(acc[mt][nt][0], acc[mt][nt][1]);
            *(float2*)p1 = make_float2(acc[mt][nt][2], acc[mt][nt][3]);
            if (bi != bj) {
                g_G[(size_t)gc * N + gr0]           = acc[mt][nt][0];
                g_G[(size_t)(gc + 1) * N + gr0]     = acc[mt][nt][1];
                g_G[(size_t)gc * N + gr0 + 8]       = acc[mt][nt][2];
                g_G[(size_t)(gc + 1) * N + gr0 + 8] = acc[mt][nt][3];
            }
        }
    }
}

// ===========================================================================
// Mining + loss (R8 version: packed u64 keys, selection on d^2, one sqrt/row).
// ===========================================================================
typedef unsigned long long u64;

__global__ void __launch_bounds__(256) mine_kernel(const int* __restrict__ target,
                                                   int N, int D,
                                                   float* __restrict__ out) {
    int i = blockIdx.x;
    __shared__ float ds[NMAX];          // d^2 for negatives, -1 sentinel else
    __shared__ u64 rk1[256];
    __shared__ u64 rk2[256];

    const int tid = threadIdx.x;
    const int ti = target[i];
    const float sqi = g_sq[i];
    const float* Gi = g_G + (size_t)i * N;
    const float4* Gi4 = (const float4*)Gi;
    const float4* sq4 = (const float4*)g_sq;
    const int4*   tg4 = (const int4*)target;

    u64 maxpos = 0ULL;                  // no-positive sentinel
    u64 minneg = ~0ULL;                 // no-negative sentinel
    const int NV = NMAX / 4 / 256;      // 8 iterations
#pragma unroll
    for (int v = 0; v < NV; v++) {
        int idx = tid + v * 256;
        float4 g = Gi4[idx];
        float4 s = sq4[idx];
        int4   t = tg4[idx];
        unsigned j = (unsigned)(idx * 4);
        float4 d2;
        d2.x = fmaxf(sqi + s.x - 2.0f * g.x, 0.0f);
        d2.y = fmaxf(sqi + s.y - 2.0f * g.y, 0.0f);
        d2.z = fmaxf(sqi + s.z - 2.0f * g.z, 0.0f);
        d2.w = fmaxf(sqi + s.w - 2.0f * g.w, 0.0f);
        float4 r = d2;
        u64 k;
        k = ((u64)__float_as_uint(d2.x) << 32);
        if (t.x == ti) { r.x = -1.0f; if ((int)j != i) { u64 kp = k | (unsigned)~(j); if (kp > maxpos) maxpos = kp; } }
        else           { u64 kn = k | j; if (kn < minneg) minneg = kn; }
        k = ((u64)__float_as_uint(d2.y) << 32);
        if (t.y == ti) { r.y = -1.0f; if ((int)(j + 1) != i) { u64 kp = k | (unsigned)~(j + 1); if (kp > maxpos) maxpos = kp; } }
        else           { u64 kn = k | (j + 1); if (kn < minneg) minneg = kn; }
        k = ((u64)__float_as_uint(d2.z) << 32);
        if (t.z == ti) { r.z = -1.0f; if ((int)(j + 2) != i) { u64 kp = k | (unsigned)~(j + 2); if (kp > maxpos) maxpos = kp; } }
        else           { u64 kn = k | (j + 2); if (kn < minneg) minneg = kn; }
        k = ((u64)__float_as_uint(d2.w) << 32);
        if (t.w == ti) { r.w = -1.0f; if ((int)(j + 3) != i) { u64 kp = k | (unsigned)~(j + 3); if (kp > maxpos) maxpos = kp; } }
        else           { u64 kn = k | (j + 3); if (kn < minneg) minneg = kn; }
        ((float4*)ds)[idx] = r;
    }
    rk1[tid] = maxpos; rk2[tid] = minneg;
    __syncthreads();
    for (int st = 128; st > 0; st >>= 1) {
        if (tid < st) {
            if (rk1[tid + st] > rk1[tid]) rk1[tid] = rk1[tid + st];
            if (rk2[tid + st] < rk2[tid]) rk2[tid] = rk2[tid + st];
        }
        __syncthreads();
    }
    const u64 posk = rk1[0];
    const u64 negk = rk2[0];
    const float dp2 = __uint_as_float((unsigned)(posk >> 32));
    __syncthreads();

    // Pass 2: semi-hard window min over { d2 > dp2 }.
    u64 minwin = ~0ULL;
#pragma unroll
    for (int v = 0; v < NV; v++) {
        int idx = tid + v * 256;
        float4 d = ((const float4*)ds)[idx];
        unsigned j = (unsigned)(idx * 4);
        if (d.x > dp2) { u64 k = ((u64)__float_as_uint(d.x) << 32) | j;       if (k < minwin) minwin = k; }
        if (d.y > dp2) { u64 k = ((u64)__float_as_uint(d.y) << 32) | (j + 1); if (k < minwin) minwin = k; }
        if (d.z > dp2) { u64 k = ((u64)__float_as_uint(d.z) << 32) | (j + 2); if (k < minwin) minwin = k; }
        if (d.w > dp2) { u64 k = ((u64)__float_as_uint(d.w) << 32) | (j + 3); if (k < minwin) minwin = k; }
    }
    rk1[tid] = minwin;
    __syncthreads();
    for (int st = 128; st > 0; st >>= 1) {
        if (tid < st) {
            if (rk1[tid + st] < rk1[tid]) rk1[tid] = rk1[tid + st];
        }
        __syncthreads();
    }

    if (tid == 0) {
        const u64 wink = rk1[0];
        int p = (posk == 0ULL) ? 0 : (int)(~(unsigned)posk);
        const float dpv = sqrtf(fmaxf(dp2, 0.0f));
        const float hi2 = (dpv + MARGIN) * (dpv + MARGIN);
        int neg;
        if (wink != ~0ULL && __uint_as_float((unsigned)(wink >> 32)) < hi2)
            neg = (int)(unsigned)wink;
        else
            neg = (negk == ~0ULL) ? 0 : (int)(unsigned)negk;

        float si = g_s[i];
        float epsC = (float)D * EPS * EPS;

        float d2p = sqi + g_sq[p] - 2.0f * Gi[p];
        float dp = sqrtf(fmaxf(d2p + 2.0f * EPS * (si - g_s[p]) + epsC, 0.0f));
        float d2n = sqi + g_sq[neg] - 2.0f * Gi[neg];
        float dn = sqrtf(fmaxf(d2n + 2.0f * EPS * (si - g_s[neg]) + epsC, 0.0f));

        float term = fmaxf(dp - dn + MARGIN, 0.0f);
        atomicAdd(out, term / (float)N);
    }
}

// ---------------------------------------------------------------------------
extern "C" void kernel_launch(void* const* d_in, const int* in_sizes, int n_in,
                              void* d_out, int out_size) {
    const float* E = (const float*)d_in[0];   // embeddings [N, D] fp32
    const int* target = (const int*)d_in[1];  // [N] int32
    float* out = (float*)d_out;

    int N = in_sizes[1];
    int D = in_sizes[0] / N;

    prep_kernel<<<N, 256>>>(E, N, D, out);

    cudaFuncSetAttribute(gram_mma_kernel, cudaFuncAttributeMaxDynamicSharedMemorySize, GRAM_SMEM);
    dim3 grid(N / 128, N / 128);
    gram_mma_kernel<<<grid, 256, GRAM_SMEM>>>(N, D);

    mine_kernel<<<N, 256>>>(target, N, D, out);
}

// round 10
// speedup vs baseline: 2.0759x; 1.1414x over previous
#include <cuda_runtime.h>
#include <cuda_fp16.h>
#include <cstdint>

// Problem constants (fixed shapes per reference: N=8192, D=1024, 128 classes)
#define NMAX 8192
#define DMAX 1024
#define MARGIN 1.0f
#define EPS 1e-6f

// Scratch (static __device__ arrays; no allocation).
__device__ float g_G[(size_t)NMAX * (size_t)NMAX];   // 256 MB Gram
__device__ float g_sq[NMAX];                         // ||e_i||^2 (fp32)
__device__ float g_s[NMAX];                          // sum_k e_ik
__device__ __half g_Eh[(size_t)NMAX * DMAX];         // fp16 embeddings

// ===========================================================================
// Helpers
// ===========================================================================
__device__ __forceinline__ uint32_t smem_to_u32(const void* p) {
    uint32_t a;
    asm("{ .reg .u64 t; cvta.to.shared.u64 t, %1; cvt.u32.u64 %0, t; }" : "=r"(a) : "l"(p));
    return a;
}
__device__ __forceinline__ void cp_async16(uint32_t smem_dst, const void* gsrc) {
    asm volatile("cp.async.cg.shared.global [%0], [%1], 16;\n" :: "r"(smem_dst), "l"(gsrc));
}
#define CP_ASYNC_COMMIT() asm volatile("cp.async.commit_group;\n" ::: "memory")
#define CP_ASYNC_WAIT1()  asm volatile("cp.async.wait_group 1;\n" ::: "memory")

__device__ __forceinline__ void ldmatrix_x4(uint32_t& r0, uint32_t& r1, uint32_t& r2, uint32_t& r3,
                                            uint32_t addr) {
    asm volatile("ldmatrix.sync.aligned.m8n8.x4.shared.b16 {%0,%1,%2,%3}, [%4];"
                 : "=r"(r0), "=r"(r1), "=r"(r2), "=r"(r3) : "r"(addr));
}
__device__ __forceinline__ void mma_f16(float& c0, float& c1, float& c2, float& c3,
                                        uint32_t a0, uint32_t a1, uint32_t a2, uint32_t a3,
                                        uint32_t b0, uint32_t b1) {
    asm volatile("mma.sync.aligned.m16n8k16.row.col.f32.f16.f16.f32 "
                 "{%0,%1,%2,%3}, {%4,%5,%6,%7}, {%8,%9}, {%0,%1,%2,%3};"
                 : "+f"(c0), "+f"(c1), "+f"(c2), "+f"(c3)
                 : "r"(a0), "r"(a1), "r"(a2), "r"(a3), "r"(b0), "r"(b1));
}

// ===========================================================================
// Fused prep: fp32 -> fp16 convert AND row stats (sq, s). One block per row.
// Block 0 thread 0 zeroes the output scalar.
// ===========================================================================
__global__ void __launch_bounds__(256) prep_kernel(const float* __restrict__ E,
                                                   int N, int D,
                                                   float* __restrict__ out) {
    int i = blockIdx.x;
    if (i == 0 && threadIdx.x == 0) out[0] = 0.0f;
    float a = 0.0f, b = 0.0f;
    for (int k = threadIdx.x; k < D / 4; k += blockDim.x) {
        int idx = i * (D / 4) + k;
        float4 v = ((const float4*)E)[idx];
        a = fmaf(v.x, v.x, a); a = fmaf(v.y, v.y, a);
        a = fmaf(v.z, v.z, a); a = fmaf(v.w, v.w, a);
        b += v.x + v.y + v.z + v.w;
        __half2 h01 = __floats2half2_rn(v.x, v.y);
        __half2 h23 = __floats2half2_rn(v.z, v.w);
        uint2 hv;
        hv.x = *(const uint32_t*)&h01;
        hv.y = *(const uint32_t*)&h23;
        ((uint2*)g_Eh)[idx] = hv;
    }
#pragma unroll
    for (int off = 16; off > 0; off >>= 1) {
        a += __shfl_down_sync(0xffffffffu, a, off);
        b += __shfl_down_sync(0xffffffffu, b, off);
    }
    __shared__ float sa[8], sb[8];
    int w = threadIdx.x >> 5, l = threadIdx.x & 31;
    if (l == 0) { sa[w] = a; sb[w] = b; }
    __syncthreads();
    if (threadIdx.x == 0) {
        float A = 0.0f, B = 0.0f;
        int nw = blockDim.x >> 5;
        for (int x = 0; x < nw; x++) { A += sa[x]; B += sb[x]; }
        g_sq[i] = A;
        g_s[i] = B;
    }
}

// ===========================================================================
// Gram GEMM via mma.sync fp16 (HMMA): G = E*E^T, single pass, fp32 accum.
// 3-stage cp.async, CTA tile 128x128, 8 warps of 32x64, 2 CTAs/SM.
// Triangular 1D grid: one CTA per (bi >= bj) tile pair.
// Mirror tile staged through SMEM (transpose) -> coalesced float4 stores.
// ===========================================================================
#define GSTAGES 3
#define A_BYTES (128 * 128)              /* 16 KB */
#define B_BYTES (128 * 128)              /* 16 KB */
#define STAGE_BYTES (A_BYTES + B_BYTES)  /* 32 KB */
#define GRAM_SMEM (GSTAGES * STAGE_BYTES + 1024)
/* Epilogue staging reuses the pipeline buffer: 128 x 132 fp32 = 67.6 KB < 96 KB */
#define SPAD 132

__global__ void __launch_bounds__(256) gram_mma_kernel(int N, int D) {
    // Triangular index -> (bi, bj), bi >= bj.
    {
        // block count per row r is r+1; idx = bi*(bi+1)/2 + bj
    }
    unsigned idx = blockIdx.x;
    int bi = (int)((sqrt(8.0 * (double)idx + 1.0) - 1.0) * 0.5);
    while ((size_t)(bi + 1) * (bi + 2) / 2 <= idx) bi++;
    while ((size_t)bi * (bi + 1) / 2 > idx) bi--;
    int bj = (int)(idx - (size_t)bi * (bi + 1) / 2);

    extern __shared__ char dsmem[];
    uint32_t base = (smem_to_u32(dsmem) + 1023u) & ~1023u;
    float* S = (float*)((char*)dsmem + ((base - smem_to_u32(dsmem))));  // same aligned region

    const int tid = threadIdx.x;
    const int wid = tid >> 5, lane = tid & 31;
    const int wm = wid & 3;       // warp row (4 x 32 = 128 M)
    const int wn = wid >> 2;      // warp col (2 x 64 = 128 N)

    const int NC = D / 64;        // 16 chunks, single pass
    const size_t rowstride = (size_t)D * 2;  // bytes per fp16 row

    const int l_kk = tid & 7;     // 16B segment within 128B row
    const int l_r0 = tid >> 3;    // rows l_r0 + 32*i
    auto load_chunk = [&](int c) {
        const char* Esrc = (const char*)g_Eh;
        uint32_t sb = base + (uint32_t)(c % GSTAGES) * STAGE_BYTES;
        const char* ga = Esrc + (size_t)(bi * 128) * rowstride + (size_t)c * 128 + l_kk * 16;
        const char* gb = Esrc + (size_t)(bj * 128) * rowstride + (size_t)c * 128 + l_kk * 16;
#pragma unroll
        for (int i = 0; i < 4; i++) {
            int r = l_r0 + i * 32;
            uint32_t sw = (uint32_t)(r * 128) + (uint32_t)((l_kk * 16) ^ ((r & 7) << 4));
            cp_async16(sb + sw, ga + (size_t)r * rowstride);
            cp_async16(sb + A_BYTES + sw, gb + (size_t)r * rowstride);
        }
        CP_ASYNC_COMMIT();
    };

    uint32_t a_row[2], a_xor[2];
#pragma unroll
    for (int mt = 0; mt < 2; mt++) {
        int r = wm * 32 + mt * 16 + (lane & 15);
        a_row[mt] = (uint32_t)(r * 128);
        a_xor[mt] = (uint32_t)((r & 7) << 4);
    }
    const uint32_t a_cb = (uint32_t)((lane >> 4) * 16);

    uint32_t b_row[4], b_xor[4];
#pragma unroll
    for (int g = 0; g < 4; g++) {
        int r = wn * 64 + g * 16 + (lane & 7) + ((lane >> 4) & 1) * 8;
        b_row[g] = (uint32_t)(r * 128);
        b_xor[g] = (uint32_t)((r & 7) << 4);
    }
    const uint32_t b_cb = (uint32_t)(((lane >> 3) & 1) * 16);

    float acc[2][8][4];
#pragma unroll
    for (int mt = 0; mt < 2; mt++)
#pragma unroll
        for (int nt = 0; nt < 8; nt++)
#pragma unroll
            for (int x = 0; x < 4; x++) acc[mt][nt][x] = 0.0f;

    load_chunk(0);
    load_chunk(1);

    for (int c = 0; c < NC; c++) {
        CP_ASYNC_WAIT1();
        __syncthreads();
        if (c + 2 < NC) load_chunk(c + 2);

        uint32_t sA = base + (uint32_t)(c % GSTAGES) * STAGE_BYTES;
        uint32_t sB = sA + A_BYTES;

#pragma unroll
        for (int ks = 0; ks < 4; ks++) {
            uint32_t kb = (uint32_t)(ks * 32);
            uint32_t af[2][4];
#pragma unroll
            for (int mt = 0; mt < 2; mt++) {
                uint32_t addr = sA + a_row[mt] + ((kb + a_cb) ^ a_xor[mt]);
                ldmatrix_x4(af[mt][0], af[mt][1], af[mt][2], af[mt][3], addr);
            }
            uint32_t bfr[4][4];
#pragma unroll
            for (int g = 0; g < 4; g++) {
                uint32_t addr = sB + b_row[g] + ((kb + b_cb) ^ b_xor[g]);
                ldmatrix_x4(bfr[g][0], bfr[g][1], bfr[g][2], bfr[g][3], addr);
            }
#pragma unroll
            for (int mt = 0; mt < 2; mt++)
#pragma unroll
                for (int g = 0; g < 4; g++) {
                    mma_f16(acc[mt][g * 2][0], acc[mt][g * 2][1], acc[mt][g * 2][2], acc[mt][g * 2][3],
                            af[mt][0], af[mt][1], af[mt][2], af[mt][3], bfr[g][0], bfr[g][1]);
                    mma_f16(acc[mt][g * 2 + 1][0], acc[mt][g * 2 + 1][1], acc[mt][g * 2 + 1][2], acc[mt][g * 2 + 1][3],
                            af[mt][0], af[mt][1], af[mt][2], af[mt][3], bfr[g][2], bfr[g][3]);
                }
        }
    }

    // ---- Epilogue ----
    const int qr = lane >> 2;          // 0..7
    const int qc = (lane & 3) * 2;     // 0,2,4,6

    // Direct (lower-triangle) tile: row-major float2 stores (32B sectors).
#pragma unroll
    for (int mt = 0; mt < 2; mt++) {
        int gr0 = bi * 128 + wm * 32 + mt * 16 + qr;
#pragma unroll
        for (int nt = 0; nt < 8; nt++) {
            int gc = bj * 128 + wn * 64 + nt * 8 + qc;
            float* p0 = g_G + (size_t)gr0 * N + gc;
            float* p1 = g_G + (size_t)(gr0 + 8) * N + gc;
            *(float2*)p0 = make_float2(acc[mt][nt][0], acc[mt][nt][1]);
            *(float2*)p1 = make_float2(acc[mt][nt][2], acc[mt][nt][3]);
        }
    }

    // Mirror tile: stage transpose in SMEM, then coalesced float4 row stores.
    if (bi != bj) {
        __syncthreads();   // pipeline buffer dead; safe to overwrite
#pragma unroll
        for (int mt = 0; mt < 2; mt++) {
            int m0 = wm * 32 + mt * 16 + qr;       // within-tile row (M)
#pragma unroll
            for (int nt = 0; nt < 8; nt++) {
                int n0 = wn * 64 + nt * 8 + qc;    // within-tile col (N)
                S[(n0)     * SPAD + m0]     = acc[mt][nt][0];
                S[(n0 + 1) * SPAD + m0]     = acc[mt][nt][1];
                S[(n0)     * SPAD + m0 + 8] = acc[mt][nt][2];
                S[(n0 + 1) * SPAD + m0 + 8] = acc[mt][nt][3];
            }
        }
        __syncthreads();
        // 8 warps x 16 rows each; each row = 128 floats = 32 lanes x float4.
#pragma unroll
        for (int rr = 0; rr < 16; rr++) {
            int n = wid * 16 + rr;
            float4 v = *(float4*)&S[n * SPAD + lane * 4];
            *(float4*)(g_G + (size_t)(bj * 128 + n) * N + bi * 128 + lane * 4) = v;
        }
    }
}

// ===========================================================================
// Mining + loss (unchanged from passing R9 kernel: packed u64 keys,
// selection on d^2, one sqrt per row).
// ===========================================================================
typedef unsigned long long u64;

__global__ void __launch_bounds__(256) mine_kernel(const int* __restrict__ target,
                                                   int N, int D,
                                                   float* __restrict__ out) {
    int i = blockIdx.x;
    __shared__ float ds[NMAX];          // d^2 for negatives, -1 sentinel else
    __shared__ u64 rk1[256];
    __shared__ u64 rk2[256];

    const int tid = threadIdx.x;
    const int ti = target[i];
    const float sqi = g_sq[i];
    const float* Gi = g_G + (size_t)i * N;
    const float4* Gi4 = (const float4*)Gi;
    const float4* sq4 = (const float4*)g_sq;
    const int4*   tg4 = (const int4*)target;

    u64 maxpos = 0ULL;                  // no-positive sentinel
    u64 minneg = ~0ULL;                 // no-negative sentinel
    const int NV = NMAX / 4 / 256;      // 8 iterations
#pragma unroll
    for (int v = 0; v < NV; v++) {
        int idx = tid + v * 256;
        float4 g = Gi4[idx];
        float4 s = sq4[idx];
        int4   t = tg4[idx];
        unsigned j = (unsigned)(idx * 4);
        float4 d2;
        d2.x = fmaxf(sqi + s.x - 2.0f * g.x, 0.0f);
        d2.y = fmaxf(sqi + s.y - 2.0f * g.y, 0.0f);
        d2.z = fmaxf(sqi + s.z - 2.0f * g.z, 0.0f);
        d2.w = fmaxf(sqi + s.w - 2.0f * g.w, 0.0f);
        float4 r = d2;
        u64 k;
        k = ((u64)__float_as_uint(d2.x) << 32);
        if (t.x == ti) { r.x = -1.0f; if ((int)j != i) { u64 kp = k | (unsigned)~(j); if (kp > maxpos) maxpos = kp; } }
        else           { u64 kn = k | j; if (kn < minneg) minneg = kn; }
        k = ((u64)__float_as_uint(d2.y) << 32);
        if (t.y == ti) { r.y = -1.0f; if ((int)(j + 1) != i) { u64 kp = k | (unsigned)~(j + 1); if (kp > maxpos) maxpos = kp; } }
        else           { u64 kn = k | (j + 1); if (kn < minneg) minneg = kn; }
        k = ((u64)__float_as_uint(d2.z) << 32);
        if (t.z == ti) { r.z = -1.0f; if ((int)(j + 2) != i) { u64 kp = k | (unsigned)~(j + 2); if (kp > maxpos) maxpos = kp; } }
        else           { u64 kn = k | (j + 2); if (kn < minneg) minneg = kn; }
        k = ((u64)__float_as_uint(d2.w) << 32);
        if (t.w == ti) { r.w = -1.0f; if ((int)(j + 3) != i) { u64 kp = k | (unsigned)~(j + 3); if (kp > maxpos) maxpos = kp; } }
        else           { u64 kn = k | (j + 3); if (kn < minneg) minneg = kn; }
        ((float4*)ds)[idx] = r;
    }
    rk1[tid] = maxpos; rk2[tid] = minneg;
    __syncthreads();
    for (int st = 128; st > 0; st >>= 1) {
        if (tid < st) {
            if (rk1[tid + st] > rk1[tid]) rk1[tid] = rk1[tid + st];
            if (rk2[tid + st] < rk2[tid]) rk2[tid] = rk2[tid + st];
        }
        __syncthreads();
    }
    const u64 posk = rk1[0];
    const u64 negk = rk2[0];
    const float dp2 = __uint_as_float((unsigned)(posk >> 32));
    __syncthreads();

    // Pass 2: semi-hard window min over { d2 > dp2 }.
    u64 minwin = ~0ULL;
#pragma unroll
    for (int v = 0; v < NV; v++) {
        int idx = tid + v * 256;
        float4 d = ((const float4*)ds)[idx];
        unsigned j = (unsigned)(idx * 4);
        if (d.x > dp2) { u64 k = ((u64)__float_as_uint(d.x) << 32) | j;       if (k < minwin) minwin = k; }
        if (d.y > dp2) { u64 k = ((u64)__float_as_uint(d.y) << 32) | (j + 1); if (k < minwin) minwin = k; }
        if (d.z > dp2) { u64 k = ((u64)__float_as_uint(d.z) << 32) | (j + 2); if (k < minwin) minwin = k; }
        if (d.w > dp2) { u64 k = ((u64)__float_as_uint(d.w) << 32) | (j + 3); if (k < minwin) minwin = k; }
    }
    rk1[tid] = minwin;
    __syncthreads();
    for (int st = 128; st > 0; st >>= 1) {
        if (tid < st) {
            if (rk1[tid + st] < rk1[tid]) rk1[tid] = rk1[tid + st];
        }
        __syncthreads();
    }

    if (tid == 0) {
        const u64 wink = rk1[0];
        int p = (posk == 0ULL) ? 0 : (int)(~(unsigned)posk);
        const float dpv = sqrtf(fmaxf(dp2, 0.0f));
        const float hi2 = (dpv + MARGIN) * (dpv + MARGIN);
        int neg;
        if (wink != ~0ULL && __uint_as_float((unsigned)(wink >> 32)) < hi2)
            neg = (int)(unsigned)wink;
        else
            neg = (negk == ~0ULL) ? 0 : (int)(unsigned)negk;

        float si = g_s[i];
        float epsC = (float)D * EPS * EPS;

        float d2p = sqi + g_sq[p] - 2.0f * Gi[p];
        float dp = sqrtf(fmaxf(d2p + 2.0f * EPS * (si - g_s[p]) + epsC, 0.0f));
        float d2n = sqi + g_sq[neg] - 2.0f * Gi[neg];
        float dn = sqrtf(fmaxf(d2n + 2.0f * EPS * (si - g_s[neg]) + epsC, 0.0f));

        float term = fmaxf(dp - dn + MARGIN, 0.0f);
        atomicAdd(out, term / (float)N);
    }
}

// ---------------------------------------------------------------------------
extern "C" void kernel_launch(void* const* d_in, const int* in_sizes, int n_in,
                              void* d_out, int out_size) {
    const float* E = (const float*)d_in[0];   // embeddings [N, D] fp32
    const int* target = (const int*)d_in[1];  // [N] int32
    float* out = (float*)d_out;

    int N = in_sizes[1];
    int D = in_sizes[0] / N;

    prep_kernel<<<N, 256>>>(E, N, D, out);

    cudaFuncSetAttribute(gram_mma_kernel, cudaFuncAttributeMaxDynamicSharedMemorySize, GRAM_SMEM);
    int nt = N / 128;
    int ntri = nt * (nt + 1) / 2;             // 2080 triangular tile pairs
    gram_mma_kernel<<<ntri, 256, GRAM_SMEM>>>(N, D);

    mine_kernel<<<N, 256>>>(target, N, D, out);
}

// round 11
// speedup vs baseline: 2.0965x; 1.0099x over previous
#include <cuda_runtime.h>
#include <cuda_fp16.h>
#include <cstdint>

// Problem constants (fixed shapes per reference: N=8192, D=1024, 128 classes)
#define NMAX 8192
#define DMAX 1024
#define MARGIN 1.0f
#define EPS 1e-6f

// Scratch (static __device__ arrays; no allocation).
// g_G now holds CLAMPED SQUARED DISTANCES d^2 (non-negative, +0.0 only).
__device__ float g_G[(size_t)NMAX * (size_t)NMAX];   // 256 MB d^2 matrix
__device__ float g_sq[NMAX];                         // ||e_i||^2 (fp32)
__device__ float g_s[NMAX];                          // sum_k e_ik
__device__ __half g_Eh[(size_t)NMAX * DMAX];         // fp16 embeddings

// ===========================================================================
// Helpers
// ===========================================================================
__device__ __forceinline__ uint32_t smem_to_u32(const void* p) {
    uint32_t a;
    asm("{ .reg .u64 t; cvta.to.shared.u64 t, %1; cvt.u32.u64 %0, t; }" : "=r"(a) : "l"(p));
    return a;
}
__device__ __forceinline__ void cp_async16(uint32_t smem_dst, const void* gsrc) {
    asm volatile("cp.async.cg.shared.global [%0], [%1], 16;\n" :: "r"(smem_dst), "l"(gsrc));
}
#define CP_ASYNC_COMMIT() asm volatile("cp.async.commit_group;\n" ::: "memory")
#define CP_ASYNC_WAIT1()  asm volatile("cp.async.wait_group 1;\n" ::: "memory")

__device__ __forceinline__ void ldmatrix_x4(uint32_t& r0, uint32_t& r1, uint32_t& r2, uint32_t& r3,
                                            uint32_t addr) {
    asm volatile("ldmatrix.sync.aligned.m8n8.x4.shared.b16 {%0,%1,%2,%3}, [%4];"
                 : "=r"(r0), "=r"(r1), "=r"(r2), "=r"(r3) : "r"(addr));
}
__device__ __forceinline__ void mma_f16(float& c0, float& c1, float& c2, float& c3,
                                        uint32_t a0, uint32_t a1, uint32_t a2, uint32_t a3,
                                        uint32_t b0, uint32_t b1) {
    asm volatile("mma.sync.aligned.m16n8k16.row.col.f32.f16.f16.f32 "
                 "{%0,%1,%2,%3}, {%4,%5,%6,%7}, {%8,%9}, {%0,%1,%2,%3};"
                 : "+f"(c0), "+f"(c1), "+f"(c2), "+f"(c3)
                 : "r"(a0), "r"(a1), "r"(a2), "r"(a3), "r"(b0), "r"(b1));
}
// Clamp to >= 0 and force +0.0 (clear potential -0.0 sign bit) so the mine
// kernel can use the sign bit as a class flag.
__device__ __forceinline__ float clean_d2(float x) {
    return __uint_as_float(__float_as_uint(fmaxf(x, 0.0f)) & 0x7fffffffu);
}

// ===========================================================================
// Fused prep: fp32 -> fp16 convert AND row stats (sq, s). One block per row.
// Block 0 thread 0 zeroes the output scalar.
// ===========================================================================
__global__ void __launch_bounds__(256) prep_kernel(const float* __restrict__ E,
                                                   int N, int D,
                                                   float* __restrict__ out) {
    int i = blockIdx.x;
    if (i == 0 && threadIdx.x == 0) out[0] = 0.0f;
    float a = 0.0f, b = 0.0f;
    for (int k = threadIdx.x; k < D / 4; k += blockDim.x) {
        int idx = i * (D / 4) + k;
        float4 v = ((const float4*)E)[idx];
        a = fmaf(v.x, v.x, a); a = fmaf(v.y, v.y, a);
        a = fmaf(v.z, v.z, a); a = fmaf(v.w, v.w, a);
        b += v.x + v.y + v.z + v.w;
        __half2 h01 = __floats2half2_rn(v.x, v.y);
        __half2 h23 = __floats2half2_rn(v.z, v.w);
        uint2 hv;
        hv.x = *(const uint32_t*)&h01;
        hv.y = *(const uint32_t*)&h23;
        ((uint2*)g_Eh)[idx] = hv;
    }
#pragma unroll
    for (int off = 16; off > 0; off >>= 1) {
        a += __shfl_down_sync(0xffffffffu, a, off);
        b += __shfl_down_sync(0xffffffffu, b, off);
    }
    __shared__ float sa[8], sb[8];
    int w = threadIdx.x >> 5, l = threadIdx.x & 31;
    if (l == 0) { sa[w] = a; sb[w] = b; }
    __syncthreads();
    if (threadIdx.x == 0) {
        float A = 0.0f, B = 0.0f;
        int nw = blockDim.x >> 5;
        for (int x = 0; x < nw; x++) { A += sa[x]; B += sb[x]; }
        g_sq[i] = A;
        g_s[i] = B;
    }
}

// ===========================================================================
// Gram via mma.sync fp16 (HMMA), single pass, fp32 accum. 3-stage cp.async,
// CTA tile 128x128, 8 warps of 32x64, triangular 1D grid, SMEM-staged mirror.
// Epilogue converts dot -> clamped d^2 = max(sq_i + sq_j - 2*dot, 0).
// ===========================================================================
#define GSTAGES 3
#define A_BYTES (128 * 128)              /* 16 KB */
#define B_BYTES (128 * 128)              /* 16 KB */
#define STAGE_BYTES (A_BYTES + B_BYTES)  /* 32 KB */
#define GRAM_SMEM (GSTAGES * STAGE_BYTES + 1024)
#define SPAD 132

__global__ void __launch_bounds__(256) gram_mma_kernel(int N, int D) {
    unsigned idx = blockIdx.x;
    int bi = (int)((sqrt(8.0 * (double)idx + 1.0) - 1.0) * 0.5);
    while ((size_t)(bi + 1) * (bi + 2) / 2 <= idx) bi++;
    while ((size_t)bi * (bi + 1) / 2 > idx) bi--;
    int bj = (int)(idx - (size_t)bi * (bi + 1) / 2);

    extern __shared__ char dsmem[];
    uint32_t base = (smem_to_u32(dsmem) + 1023u) & ~1023u;
    float* S = (float*)((char*)dsmem + ((base - smem_to_u32(dsmem))));

    const int tid = threadIdx.x;
    const int wid = tid >> 5, lane = tid & 31;
    const int wm = wid & 3;       // warp row (4 x 32 = 128 M)
    const int wn = wid >> 2;      // warp col (2 x 64 = 128 N)

    const int NC = D / 64;        // 16 chunks
    const size_t rowstride = (size_t)D * 2;

    const int l_kk = tid & 7;
    const int l_r0 = tid >> 3;
    auto load_chunk = [&](int c) {
        const char* Esrc = (const char*)g_Eh;
        uint32_t sb = base + (uint32_t)(c % GSTAGES) * STAGE_BYTES;
        const char* ga = Esrc + (size_t)(bi * 128) * rowstride + (size_t)c * 128 + l_kk * 16;
        const char* gb = Esrc + (size_t)(bj * 128) * rowstride + (size_t)c * 128 + l_kk * 16;
#pragma unroll
        for (int i = 0; i < 4; i++) {
            int r = l_r0 + i * 32;
            uint32_t sw = (uint32_t)(r * 128) + (uint32_t)((l_kk * 16) ^ ((r & 7) << 4));
            cp_async16(sb + sw, ga + (size_t)r * rowstride);
            cp_async16(sb + A_BYTES + sw, gb + (size_t)r * rowstride);
        }
        CP_ASYNC_COMMIT();
    };

    uint32_t a_row[2], a_xor[2];
#pragma unroll
    for (int mt = 0; mt < 2; mt++) {
        int r = wm * 32 + mt * 16 + (lane & 15);
        a_row[mt] = (uint32_t)(r * 128);
        a_xor[mt] = (uint32_t)((r & 7) << 4);
    }
    const uint32_t a_cb = (uint32_t)((lane >> 4) * 16);

    uint32_t b_row[4], b_xor[4];
#pragma unroll
    for (int g = 0; g < 4; g++) {
        int r = wn * 64 + g * 16 + (lane & 7) + ((lane >> 4) & 1) * 8;
        b_row[g] = (uint32_t)(r * 128);
        b_xor[g] = (uint32_t)((r & 7) << 4);
    }
    const uint32_t b_cb = (uint32_t)(((lane >> 3) & 1) * 16);

    float acc[2][8][4];
#pragma unroll
    for (int mt = 0; mt < 2; mt++)
#pragma unroll
        for (int nt = 0; nt < 8; nt++)
#pragma unroll
            for (int x = 0; x < 4; x++) acc[mt][nt][x] = 0.0f;

    load_chunk(0);
    load_chunk(1);

    for (int c = 0; c < NC; c++) {
        CP_ASYNC_WAIT1();
        __syncthreads();
        if (c + 2 < NC) load_chunk(c + 2);

        uint32_t sA = base + (uint32_t)(c % GSTAGES) * STAGE_BYTES;
        uint32_t sB = sA + A_BYTES;

#pragma unroll
        for (int ks = 0; ks < 4; ks++) {
            uint32_t kb = (uint32_t)(ks * 32);
            uint32_t af[2][4];
#pragma unroll
            for (int mt = 0; mt < 2; mt++) {
                uint32_t addr = sA + a_row[mt] + ((kb + a_cb) ^ a_xor[mt]);
                ldmatrix_x4(af[mt][0], af[mt][1], af[mt][2], af[mt][3], addr);
            }
            uint32_t bfr[4][4];
#pragma unroll
            for (int g = 0; g < 4; g++) {
                uint32_t addr = sB + b_row[g] + ((kb + b_cb) ^ b_xor[g]);
                ldmatrix_x4(bfr[g][0], bfr[g][1], bfr[g][2], bfr[g][3], addr);
            }
#pragma unroll
            for (int mt = 0; mt < 2; mt++)
#pragma unroll
                for (int g = 0; g < 4; g++) {
                    mma_f16(acc[mt][g * 2][0], acc[mt][g * 2][1], acc[mt][g * 2][2], acc[mt][g * 2][3],
                            af[mt][0], af[mt][1], af[mt][2], af[mt][3], bfr[g][0], bfr[g][1]);
                    mma_f16(acc[mt][g * 2 + 1][0], acc[mt][g * 2 + 1][1], acc[mt][g * 2 + 1][2], acc[mt][g * 2 + 1][3],
                            af[mt][0], af[mt][1], af[mt][2], af[mt][3], bfr[g][2], bfr[g][3]);
                }
        }
    }

    // ---- Epilogue: dot -> d^2 transform, direct stores, SMEM-staged mirror.
    const int qr = lane >> 2;          // 0..7
    const int qc = (lane & 3) * 2;     // 0,2,4,6

    float sr[2][2];
#pragma unroll
    for (int mt = 0; mt < 2; mt++) {
        int r0 = bi * 128 + wm * 32 + mt * 16 + qr;
        sr[mt][0] = g_sq[r0];
        sr[mt][1] = g_sq[r0 + 8];
    }

#pragma unroll
    for (int mt = 0; mt < 2; mt++) {
        int gr0 = bi * 128 + wm * 32 + mt * 16 + qr;
#pragma unroll
        for (int nt = 0; nt < 8; nt++) {
            int gc = bj * 128 + wn * 64 + nt * 8 + qc;
            float sn0 = g_sq[gc], sn1 = g_sq[gc + 1];
            acc[mt][nt][0] = clean_d2(sr[mt][0] + sn0 - 2.0f * acc[mt][nt][0]);
            acc[mt][nt][1] = clean_d2(sr[mt][0] + sn1 - 2.0f * acc[mt][nt][1]);
            acc[mt][nt][2] = clean_d2(sr[mt][1] + sn0 - 2.0f * acc[mt][nt][2]);
            acc[mt][nt][3] = clean_d2(sr[mt][1] + sn1 - 2.0f * acc[mt][nt][3]);
            float* p0 = g_G + (size_t)gr0 * N + gc;
            float* p1 = g_G + (size_t)(gr0 + 8) * N + gc;
            *(float2*)p0 = make_float2(acc[mt][nt][0], acc[mt][nt][1]);
            *(float2*)p1 = make_float2(acc[mt][nt][2], acc[mt][nt][3]);
        }
    }

    if (bi != bj) {
        __syncthreads();   // pipeline buffer dead; safe to overwrite
#pragma unroll
        for (int mt = 0; mt < 2; mt++) {
            int m0 = wm * 32 + mt * 16 + qr;
#pragma unroll
            for (int nt = 0; nt < 8; nt++) {
                int n0 = wn * 64 + nt * 8 + qc;
                S[(n0)     * SPAD + m0]     = acc[mt][nt][0];
                S[(n0 + 1) * SPAD + m0]     = acc[mt][nt][1];
                S[(n0)     * SPAD + m0 + 8] = acc[mt][nt][2];
                S[(n0 + 1) * SPAD + m0 + 8] = acc[mt][nt][3];
            }
        }
        __syncthreads();
#pragma unroll
        for (int rr = 0; rr < 16; rr++) {
            int n = wid * 16 + rr;
            float4 v = *(float4*)&S[n * SPAD + lane * 4];
            *(float4*)(g_G + (size_t)(bj * 128 + n) * N + bi * 128 + lane * 4) = v;
        }
    }
}

// ===========================================================================
// Mining + loss. g_G holds clamped d^2 (sign bit always clear).
// Pass 1: scalar fmax (hardest positive d2) + fmin (hardest negative d2);
//         stash encoded d2 in smem: sign bit set = same class; self = ~0u.
// Pass 2: exact-bits equality recovers argmax-positive / argmin-negative
//         indices (first-index tie-break = min j); u64 key min for the
//         semi-hard window (d2 > dp2), bound checked as (sqrt(dp2)+margin)^2.
// ===========================================================================
typedef unsigned long long u64;

__global__ void __launch_bounds__(256) mine_kernel(const int* __restrict__ target,
                                                   int N, int D,
                                                   float* __restrict__ out) {
    int i = blockIdx.x;
    __shared__ unsigned ds[NMAX];       // encoded d^2
    __shared__ float rf1[256], rf2[256];
    __shared__ u64 rw[256];
    __shared__ int rp[256], rn[256];

    const int tid = threadIdx.x;
    const int ti = target[i];
    const float* Gi = g_G + (size_t)i * N;
    const uint4* Gi4 = (const uint4*)Gi;
    const int4*  tg4 = (const int4*)target;

    // ---- Pass 1 ----
    float dp2v = -1e30f;   // max positive d2
    float mn = 1e30f;      // min negative d2
    const int NV = NMAX / 4 / 256;      // 8 iterations
#pragma unroll
    for (int v = 0; v < NV; v++) {
        int idx = tid + v * 256;
        uint4 b = Gi4[idx];
        int4  t = tg4[idx];
        int j = idx * 4;
        uint4 e;
        {
            bool same = (t.x == ti);
            float d = __uint_as_float(b.x);
            dp2v = fmaxf(dp2v, (same && j != i) ? d : -1e30f);
            mn = fminf(mn, same ? 1e30f : d);
            e.x = (j == i) ? 0xFFFFFFFFu : (same ? (b.x | 0x80000000u) : b.x);
        }
        {
            bool same = (t.y == ti);
            float d = __uint_as_float(b.y);
            dp2v = fmaxf(dp2v, (same && j + 1 != i) ? d : -1e30f);
            mn = fminf(mn, same ? 1e30f : d);
            e.y = (j + 1 == i) ? 0xFFFFFFFFu : (same ? (b.y | 0x80000000u) : b.y);
        }
        {
            bool same = (t.z == ti);
            float d = __uint_as_float(b.z);
            dp2v = fmaxf(dp2v, (same && j + 2 != i) ? d : -1e30f);
            mn = fminf(mn, same ? 1e30f : d);
            e.z = (j + 2 == i) ? 0xFFFFFFFFu : (same ? (b.z | 0x80000000u) : b.z);
        }
        {
            bool same = (t.w == ti);
            float d = __uint_as_float(b.w);
            dp2v = fmaxf(dp2v, (same && j + 3 != i) ? d : -1e30f);
            mn = fminf(mn, same ? 1e30f : d);
            e.w = (j + 3 == i) ? 0xFFFFFFFFu : (same ? (b.w | 0x80000000u) : b.w);
        }
        ((uint4*)ds)[idx] = e;
    }
    rf1[tid] = dp2v; rf2[tid] = mn;
    __syncthreads();
    for (int st = 128; st > 0; st >>= 1) {
        if (tid < st) {
            rf1[tid] = fmaxf(rf1[tid], rf1[tid + st]);
            rf2[tid] = fminf(rf2[tid], rf2[tid + st]);
        }
        __syncthreads();
    }
    dp2v = rf1[0];
    mn = rf2[0];
    const unsigned dpb = __float_as_uint(dp2v);
    const unsigned mnb = __float_as_uint(mn);
    __syncthreads();

    // ---- Pass 2 ----
    u64 win = ~0ULL;
    int posj = 0x7fffffff, negj = 0x7fffffff;
#pragma unroll
    for (int v = 0; v < NV; v++) {
        int idx = tid + v * 256;
        uint4 e = ((const uint4*)ds)[idx];
        unsigned j = (unsigned)(idx * 4);
#pragma unroll
        for (int c = 0; c < 4; c++) {
            unsigned b = (c == 0) ? e.x : (c == 1) ? e.y : (c == 2) ? e.z : e.w;
            unsigned jj = j + c;
            if (b & 0x80000000u) {
                if ((b ^ 0x80000000u) == dpb && (int)jj < posj) posj = (int)jj;
            } else {
                if (b == mnb && (int)jj < negj) negj = (int)jj;
                if (__uint_as_float(b) > dp2v) {
                    u64 k = ((u64)b << 32) | jj;
                    if (k < win) win = k;
                }
            }
        }
    }
    rw[tid] = win; rp[tid] = posj; rn[tid] = negj;
    __syncthreads();
    for (int st = 128; st > 0; st >>= 1) {
        if (tid < st) {
            if (rw[tid + st] < rw[tid]) rw[tid] = rw[tid + st];
            if (rp[tid + st] < rp[tid]) rp[tid] = rp[tid + st];
            if (rn[tid + st] < rn[tid]) rn[tid] = rn[tid + st];
        }
        __syncthreads();
    }

    if (tid == 0) {
        const u64 wink = rw[0];
        int p = (rp[0] == 0x7fffffff) ? 0 : rp[0];
        const float dpv = sqrtf(fmaxf(dp2v, 0.0f));
        const float hi2 = (dpv + MARGIN) * (dpv + MARGIN);
        int neg;
        if (wink != ~0ULL && __uint_as_float((unsigned)(wink >> 32)) < hi2)
            neg = (int)(unsigned)wink;
        else
            neg = (rn[0] == 0x7fffffff) ? 0 : rn[0];

        float si = g_s[i];
        float epsC = (float)D * EPS * EPS;

        float d2p = Gi[p];     // clamped d^2 stored in G
        float dp = sqrtf(fmaxf(d2p + 2.0f * EPS * (si - g_s[p]) + epsC, 0.0f));
        float d2n = Gi[neg];
        float dn = sqrtf(fmaxf(d2n + 2.0f * EPS * (si - g_s[neg]) + epsC, 0.0f));

        float term = fmaxf(dp - dn + MARGIN, 0.0f);
        atomicAdd(out, term / (float)N);
    }
}

// ---------------------------------------------------------------------------
extern "C" void kernel_launch(void* const* d_in, const int* in_sizes, int n_in,
                              void* d_out, int out_size) {
    const float* E = (const float*)d_in[0];   // embeddings [N, D] fp32
    const int* target = (const int*)d_in[1];  // [N] int32
    float* out = (float*)d_out;

    int N = in_sizes[1];
    int D = in_sizes[0] / N;

    prep_kernel<<<N, 256>>>(E, N, D, out);

    cudaFuncSetAttribute(gram_mma_kernel, cudaFuncAttributeMaxDynamicSharedMemorySize, GRAM_SMEM);
    int nt = N / 128;
    int ntri = nt * (nt + 1) / 2;             // 2080 triangular tile pairs
    gram_mma_kernel<<<ntri, 256, GRAM_SMEM>>>(N, D);

    mine_kernel<<<N, 256>>>(target, N, D, out);
}

// round 13
// speedup vs baseline: 2.2253x; 1.0615x over previous
#include <cuda_runtime.h>
#include <cuda_fp16.h>
#include <cstdint>

// Problem constants (fixed shapes per reference: N=8192, D=1024, 128 classes)
#define NMAX 8192
#define DMAX 1024
#define MARGIN 1.0f
#define EPS 1e-6f
#define NCLS 128
#define CAP 256          /* max members per class (mean 64; huge safety margin) */

// Scratch (static __device__ arrays; no allocation).
// g_G holds CLAMPED SQUARED DISTANCES d^2 (fp32, non-negative).
__device__ float g_G[(size_t)NMAX * (size_t)NMAX];   // 256 MB d^2 matrix
__device__ float g_sq[NMAX];                         // ||e_i||^2 (fp32)
__device__ float g_s[NMAX];                          // sum_k e_ik
__device__ __half g_Eh[(size_t)NMAX * DMAX];         // fp16 embeddings
__device__ int g_cls[NCLS * CAP];                    // class member lists
__device__ int g_ccnt[NCLS];                         // class member counts

typedef unsigned long long u64;

// ===========================================================================
// Helpers
// ===========================================================================
__device__ __forceinline__ uint32_t smem_to_u32(const void* p) {
    uint32_t a;
    asm("{ .reg .u64 t; cvta.to.shared.u64 t, %1; cvt.u32.u64 %0, t; }" : "=r"(a) : "l"(p));
    return a;
}
__device__ __forceinline__ void cp_async16(uint32_t smem_dst, const void* gsrc) {
    asm volatile("cp.async.cg.shared.global [%0], [%1], 16;\n" :: "r"(smem_dst), "l"(gsrc));
}
#define CP_ASYNC_COMMIT() asm volatile("cp.async.commit_group;\n" ::: "memory")
#define CP_ASYNC_WAIT1()  asm volatile("cp.async.wait_group 1;\n" ::: "memory")

__device__ __forceinline__ void ldmatrix_x4(uint32_t& r0, uint32_t& r1, uint32_t& r2, uint32_t& r3,
                                            uint32_t addr) {
    asm volatile("ldmatrix.sync.aligned.m8n8.x4.shared.b16 {%0,%1,%2,%3}, [%4];"
                 : "=r"(r0), "=r"(r1), "=r"(r2), "=r"(r3) : "r"(addr));
}
__device__ __forceinline__ void mma_f16(float& c0, float& c1, float& c2, float& c3,
                                        uint32_t a0, uint32_t a1, uint32_t a2, uint32_t a3,
                                        uint32_t b0, uint32_t b1) {
    asm volatile("mma.sync.aligned.m16n8k16.row.col.f32.f16.f16.f32 "
                 "{%0,%1,%2,%3}, {%4,%5,%6,%7}, {%8,%9}, {%0,%1,%2,%3};"
                 : "+f"(c0), "+f"(c1), "+f"(c2), "+f"(c3)
                 : "r"(a0), "r"(a1), "r"(a2), "r"(a3), "r"(b0), "r"(b1));
}
// Clamp to >= 0; also clears any -0.0 so stored bit patterns are monotonic.
__device__ __forceinline__ float clean_d2(float x) {
    return __uint_as_float(__float_as_uint(fmaxf(x, 0.0f)) & 0x7fffffffu);
}

// ===========================================================================
// Fused prep: fp32 -> fp16 convert AND row stats (sq, s). One block per row.
// Block 0 zeroes the output scalar and the class counters.
// ===========================================================================
__global__ void __launch_bounds__(256) prep_kernel(const float* __restrict__ E,
                                                   int N, int D,
                                                   float* __restrict__ out) {
    int i = blockIdx.x;
    if (i == 0) {
        if (threadIdx.x == 0) out[0] = 0.0f;
        if (threadIdx.x < NCLS) g_ccnt[threadIdx.x] = 0;
    }
    float a = 0.0f, b = 0.0f;
    for (int k = threadIdx.x; k < D / 4; k += blockDim.x) {
        int idx = i * (D / 4) + k;
        float4 v = ((const float4*)E)[idx];
        a = fmaf(v.x, v.x, a); a = fmaf(v.y, v.y, a);
        a = fmaf(v.z, v.z, a); a = fmaf(v.w, v.w, a);
        b += v.x + v.y + v.z + v.w;
        __half2 h01 = __floats2half2_rn(v.x, v.y);
        __half2 h23 = __floats2half2_rn(v.z, v.w);
        uint2 hv;
        hv.x = *(const uint32_t*)&h01;
        hv.y = *(const uint32_t*)&h23;
        ((uint2*)g_Eh)[idx] = hv;
    }
#pragma unroll
    for (int off = 16; off > 0; off >>= 1) {
        a += __shfl_down_sync(0xffffffffu, a, off);
        b += __shfl_down_sync(0xffffffffu, b, off);
    }
    __shared__ float sa[8], sb[8];
    int w = threadIdx.x >> 5, l = threadIdx.x & 31;
    if (l == 0) { sa[w] = a; sb[w] = b; }
    __syncthreads();
    if (threadIdx.x == 0) {
        float A = 0.0f, B = 0.0f;
        int nw = blockDim.x >> 5;
        for (int x = 0; x < nw; x++) { A += sa[x]; B += sb[x]; }
        g_sq[i] = A;
        g_s[i] = B;
    }
}

// ===========================================================================
// Class list build. Slot order from atomics is arbitrary, but consumers
// reduce with order-independent keyed max/min, so results stay deterministic.
// ===========================================================================
__global__ void __launch_bounds__(256) classlist_kernel(const int* __restrict__ target, int N) {
    int j = blockIdx.x * blockDim.x + threadIdx.x;
    if (j < N) {
        int c = target[j];
        int slot = atomicAdd(&g_ccnt[c], 1);
        if (slot < CAP) g_cls[c * CAP + slot] = j;
    }
}

// ===========================================================================
// Gram via mma.sync fp16 (HMMA), single pass, fp32 accum. 3-stage cp.async,
// CTA tile 128x128, 8 warps of 32x64, triangular 1D grid, SMEM-staged mirror.
// Epilogue converts dot -> clamped d^2 (fp32 stores). [R11-passing version]
// ===========================================================================
#define GSTAGES 3
#define A_BYTES (128 * 128)              /* 16 KB */
#define B_BYTES (128 * 128)              /* 16 KB */
#define STAGE_BYTES (A_BYTES + B_BYTES)  /* 32 KB */
#define GRAM_SMEM (GSTAGES * STAGE_BYTES + 1024)
#define SPAD 132

__global__ void __launch_bounds__(256) gram_mma_kernel(int N, int D) {
    unsigned idx = blockIdx.x;
    int bi = (int)((sqrt(8.0 * (double)idx + 1.0) - 1.0) * 0.5);
    while ((size_t)(bi + 1) * (bi + 2) / 2 <= idx) bi++;
    while ((size_t)bi * (bi + 1) / 2 > idx) bi--;
    int bj = (int)(idx - (size_t)bi * (bi + 1) / 2);

    extern __shared__ char dsmem[];
    uint32_t base = (smem_to_u32(dsmem) + 1023u) & ~1023u;
    float* S = (float*)((char*)dsmem + ((base - smem_to_u32(dsmem))));

    const int tid = threadIdx.x;
    const int wid = tid >> 5, lane = tid & 31;
    const int wm = wid & 3;
    const int wn = wid >> 2;

    const int NC = D / 64;
    const size_t rowstride = (size_t)D * 2;

    const int l_kk = tid & 7;
    const int l_r0 = tid >> 3;
    auto load_chunk = [&](int c) {
        const char* Esrc = (const char*)g_Eh;
        uint32_t sb = base + (uint32_t)(c % GSTAGES) * STAGE_BYTES;
        const char* ga = Esrc + (size_t)(bi * 128) * rowstride + (size_t)c * 128 + l_kk * 16;
        const char* gb = Esrc + (size_t)(bj * 128) * rowstride + (size_t)c * 128 + l_kk * 16;
#pragma unroll
        for (int i = 0; i < 4; i++) {
            int r = l_r0 + i * 32;
            uint32_t sw = (uint32_t)(r * 128) + (uint32_t)((l_kk * 16) ^ ((r & 7) << 4));
            cp_async16(sb + sw, ga + (size_t)r * rowstride);
            cp_async16(sb + A_BYTES + sw, gb + (size_t)r * rowstride);
        }
        CP_ASYNC_COMMIT();
    };

    uint32_t a_row[2], a_xor[2];
#pragma unroll
    for (int mt = 0; mt < 2; mt++) {
        int r = wm * 32 + mt * 16 + (lane & 15);
        a_row[mt] = (uint32_t)(r * 128);
        a_xor[mt] = (uint32_t)((r & 7) << 4);
    }
    const uint32_t a_cb = (uint32_t)((lane >> 4) * 16);

    uint32_t b_row[4], b_xor[4];
#pragma unroll
    for (int g = 0; g < 4; g++) {
        int r = wn * 64 + g * 16 + (lane & 7) + ((lane >> 4) & 1) * 8;
        b_row[g] = (uint32_t)(r * 128);
        b_xor[g] = (uint32_t)((r & 7) << 4);
    }
    const uint32_t b_cb = (uint32_t)(((lane >> 3) & 1) * 16);

    float acc[2][8][4];
#pragma unroll
    for (int mt = 0; mt < 2; mt++)
#pragma unroll
        for (int nt = 0; nt < 8; nt++)
#pragma unroll
            for (int x = 0; x < 4; x++) acc[mt][nt][x] = 0.0f;

    load_chunk(0);
    load_chunk(1);

    for (int c = 0; c < NC; c++) {
        CP_ASYNC_WAIT1();
        __syncthreads();
        if (c + 2 < NC) load_chunk(c + 2);

        uint32_t sA = base + (uint32_t)(c % GSTAGES) * STAGE_BYTES;
        uint32_t sB = sA + A_BYTES;

#pragma unroll
        for (int ks = 0; ks < 4; ks++) {
            uint32_t kb = (uint32_t)(ks * 32);
            uint32_t af[2][4];
#pragma unroll
            for (int mt = 0; mt < 2; mt++) {
                uint32_t addr = sA + a_row[mt] + ((kb + a_cb) ^ a_xor[mt]);
                ldmatrix_x4(af[mt][0], af[mt][1], af[mt][2], af[mt][3], addr);
            }
            uint32_t bfr[4][4];
#pragma unroll
            for (int g = 0; g < 4; g++) {
                uint32_t addr = sB + b_row[g] + ((kb + b_cb) ^ b_xor[g]);
                ldmatrix_x4(bfr[g][0], bfr[g][1], bfr[g][2], bfr[g][3], addr);
            }
#pragma unroll
            for (int mt = 0; mt < 2; mt++)
#pragma unroll
                for (int g = 0; g < 4; g++) {
                    mma_f16(acc[mt][g * 2][0], acc[mt][g * 2][1], acc[mt][g * 2][2], acc[mt][g * 2][3],
                            af[mt][0], af[mt][1], af[mt][2], af[mt][3], bfr[g][0], bfr[g][1]);
                    mma_f16(acc[mt][g * 2 + 1][0], acc[mt][g * 2 + 1][1], acc[mt][g * 2 + 1][2], acc[mt][g * 2 + 1][3],
                            af[mt][0], af[mt][1], af[mt][2], af[mt][3], bfr[g][2], bfr[g][3]);
                }
        }
    }

    // ---- Epilogue: dot -> d^2 transform, fp32 stores, SMEM-staged mirror.
    const int qr = lane >> 2;
    const int qc = (lane & 3) * 2;

    float sr[2][2];
#pragma unroll
    for (int mt = 0; mt < 2; mt++) {
        int r0 = bi * 128 + wm * 32 + mt * 16 + qr;
        sr[mt][0] = g_sq[r0];
        sr[mt][1] = g_sq[r0 + 8];
    }

#pragma unroll
    for (int mt = 0; mt < 2; mt++) {
        int gr0 = bi * 128 + wm * 32 + mt * 16 + qr;
#pragma unroll
        for (int nt = 0; nt < 8; nt++) {
            int gc = bj * 128 + wn * 64 + nt * 8 + qc;
            float sn0 = g_sq[gc], sn1 = g_sq[gc + 1];
            acc[mt][nt][0] = clean_d2(sr[mt][0] + sn0 - 2.0f * acc[mt][nt][0]);
            acc[mt][nt][1] = clean_d2(sr[mt][0] + sn1 - 2.0f * acc[mt][nt][1]);
            acc[mt][nt][2] = clean_d2(sr[mt][1] + sn0 - 2.0f * acc[mt][nt][2]);
            acc[mt][nt][3] = clean_d2(sr[mt][1] + sn1 - 2.0f * acc[mt][nt][3]);
            float* p0 = g_G + (size_t)gr0 * N + gc;
            float* p1 = g_G + (size_t)(gr0 + 8) * N + gc;
            *(float2*)p0 = make_float2(acc[mt][nt][0], acc[mt][nt][1]);
            *(float2*)p1 = make_float2(acc[mt][nt][2], acc[mt][nt][3]);
        }
    }

    if (bi != bj) {
        __syncthreads();   // pipeline buffer dead; safe to overwrite
#pragma unroll
        for (int mt = 0; mt < 2; mt++) {
            int m0 = wm * 32 + mt * 16 + qr;
#pragma unroll
            for (int nt = 0; nt < 8; nt++) {
                int n0 = wn * 64 + nt * 8 + qc;
                S[(n0)     * SPAD + m0]     = acc[mt][nt][0];
                S[(n0 + 1) * SPAD + m0]     = acc[mt][nt][1];
                S[(n0)     * SPAD + m0 + 8] = acc[mt][nt][2];
                S[(n0 + 1) * SPAD + m0 + 8] = acc[mt][nt][3];
            }
        }
        __syncthreads();
#pragma unroll
        for (int rr = 0; rr < 16; rr++) {
            int n = wid * 16 + rr;
            float4 v = *(float4*)&S[n * SPAD + lane * 4];
            *(float4*)(g_G + (size_t)(bj * 128 + n) * N + bi * 128 + lane * 4) = v;
        }
    }
}

// ===========================================================================
// Mining + loss. G holds fp32 d^2 (non-negative -> bits monotonic unsigned).
// Pre-pass: hardest positive over the <=CAP same-class members (sparse):
//   max key = ((u64)bits << 13) | (8191 - j)  -> max d2, min index.
// Main pass (single, streaming): negatives only:
//   min key = ((u64)bits << 13) | j           -> min d2, min index
//   window min over { bits > dp2bits }; bound (sqrt(dp2)+margin)^2 at end.
// ===========================================================================
__global__ void __launch_bounds__(256) mine_kernel(const int* __restrict__ target,
                                                   int N, int D,
                                                   float* __restrict__ out) {
    int i = blockIdx.x;
    __shared__ u64 r1[256], r2[256];

    const int tid = threadIdx.x;
    const int ti = target[i];
    const float* Gi = g_G + (size_t)i * N;

    // ---- Pre-pass: hardest positive (max d2, min index) over class members.
    int cnt = g_ccnt[ti];
    if (cnt > CAP) cnt = CAP;
    u64 pk = 0ULL;   // sentinel: no positive
    for (int k = tid; k < cnt; k += 256) {
        int j = g_cls[ti * CAP + k];
        if (j != i) {
            unsigned bits = __float_as_uint(Gi[j]);
            u64 key = ((u64)bits << 13) | (u64)(8191 - j);
            if (key > pk) pk = key;
        }
    }
    r1[tid] = pk;
    __syncthreads();
    for (int st = 128; st > 0; st >>= 1) {
        if (tid < st) { if (r1[tid + st] > r1[tid]) r1[tid] = r1[tid + st]; }
        __syncthreads();
    }
    const u64 posk = r1[0];
    const unsigned dpbits = (posk == 0ULL) ? 0xFFFFFFFFu : (unsigned)(posk >> 13);
    __syncthreads();

    // ---- Main pass: single stream over the row; negatives only.
    u64 mn = ~0ULL, wn = ~0ULL;
    const uint4* Gi4 = (const uint4*)Gi;
    const int4*  tg4 = (const int4*)target;
    const int NV = NMAX / 4 / 256;      // 8 iterations
#pragma unroll
    for (int v = 0; v < NV; v++) {
        int idx = tid + v * 256;
        uint4 b = Gi4[idx];
        int4  t = tg4[idx];
        unsigned j = (unsigned)(idx * 4);
        if (t.x != ti) {
            u64 k = ((u64)b.x << 13) | j;
            if (k < mn) mn = k;
            if (b.x > dpbits && k < wn) wn = k;
        }
        if (t.y != ti) {
            u64 k = ((u64)b.y << 13) | (j + 1);
            if (k < mn) mn = k;
            if (b.y > dpbits && k < wn) wn = k;
        }
        if (t.z != ti) {
            u64 k = ((u64)b.z << 13) | (j + 2);
            if (k < mn) mn = k;
            if (b.z > dpbits && k < wn) wn = k;
        }
        if (t.w != ti) {
            u64 k = ((u64)b.w << 13) | (j + 3);
            if (k < mn) mn = k;
            if (b.w > dpbits && k < wn) wn = k;
        }
    }
    r1[tid] = mn; r2[tid] = wn;
    __syncthreads();
    for (int st = 128; st > 0; st >>= 1) {
        if (tid < st) {
            if (r1[tid + st] < r1[tid]) r1[tid] = r1[tid + st];
            if (r2[tid + st] < r2[tid]) r2[tid] = r2[tid + st];
        }
        __syncthreads();
    }

    if (tid == 0) {
        const u64 negk = r1[0], wink = r2[0];
        int p = (posk == 0ULL) ? 0 : (int)(8191 - (int)(posk & 8191ULL));
        float dp2 = (posk == 0ULL) ? 0.0f : __uint_as_float((unsigned)(posk >> 13));
        float dpv = sqrtf(dp2);
        float hi2 = (dpv + MARGIN) * (dpv + MARGIN);
        int neg;
        if (wink != ~0ULL && __uint_as_float((unsigned)(wink >> 13)) < hi2)
            neg = (int)(wink & 8191ULL);
        else
            neg = (negk == ~0ULL) ? 0 : (int)(negk & 8191ULL);

        float si = g_s[i];
        float epsC = (float)D * EPS * EPS;

        float d2p = Gi[p];
        float dp = sqrtf(fmaxf(d2p + 2.0f * EPS * (si - g_s[p]) + epsC, 0.0f));
        float d2n = Gi[neg];
        float dn = sqrtf(fmaxf(d2n + 2.0f * EPS * (si - g_s[neg]) + epsC, 0.0f));

        float term = fmaxf(dp - dn + MARGIN, 0.0f);
        atomicAdd(out, term / (float)N);
    }
}

// ---------------------------------------------------------------------------
extern "C" void kernel_launch(void* const* d_in, const int* in_sizes, int n_in,
                              void* d_out, int out_size) {
    const float* E = (const float*)d_in[0];   // embeddings [N, D] fp32
    const int* target = (const int*)d_in[1];  // [N] int32
    float* out = (float*)d_out;

    int N = in_sizes[1];
    int D = in_sizes[0] / N;

    prep_kernel<<<N, 256>>>(E, N, D, out);
    classlist_kernel<<<(N + 255) / 256, 256>>>(target, N);

    cudaFuncSetAttribute(gram_mma_kernel, cudaFuncAttributeMaxDynamicSharedMemorySize, GRAM_SMEM);
    int nt = N / 128;
    int ntri = nt * (nt + 1) / 2;             // 2080 triangular tile pairs
    gram_mma_kernel<<<ntri, 256, GRAM_SMEM>>>(N, D);

    mine_kernel<<<N, 256>>>(target, N, D, out);
}

// round 14
// speedup vs baseline: 2.3501x; 1.0561x over previous
#include <cuda_runtime.h>
#include <cuda_fp16.h>
#include <cstdint>

// Problem constants (fixed shapes per reference: N=8192, D=1024, 128 classes)
#define NMAX 8192
#define DMAX 1024
#define MARGIN 1.0f
#define EPS 1e-6f
#define NCLS 128
#define CAP 256          /* max members per class (mean 64; huge safety margin) */

typedef unsigned long long u64;

// Scratch (static __device__ arrays; no allocation). NO big G matrix anymore.
__device__ float g_sq[NMAX];                         // ||e_i||^2 (fp32)
__device__ float g_s[NMAX];                          // sum_k e_ik
__device__ __half g_Eh[(size_t)NMAX * DMAX];         // fp16 embeddings
__device__ int g_cls[NCLS * CAP];                    // class member lists
__device__ int g_ccnt[NCLS];                         // class member counts
// Keyed results: key = (d2_fp32_bits << 13) | j   (j fits in 13 bits, N=8192)
__device__ u64 g_poskey[NMAX];   // max over positives; index stored as 8191-j
__device__ u64 g_negkey[NMAX];   // min over all negatives
__device__ u64 g_winkey[NMAX];   // min over negatives with d2 > dp2
__device__ unsigned g_dpwin[NMAX]; // dp2 bits per anchor (0xFFFFFFFF = no window)

// ===========================================================================
// Helpers
// ===========================================================================
__device__ __forceinline__ uint32_t smem_to_u32(const void* p) {
    uint32_t a;
    asm("{ .reg .u64 t; cvta.to.shared.u64 t, %1; cvt.u32.u64 %0, t; }" : "=r"(a) : "l"(p));
    return a;
}
__device__ __forceinline__ void cp_async16(uint32_t smem_dst, const void* gsrc) {
    asm volatile("cp.async.cg.shared.global [%0], [%1], 16;\n" :: "r"(smem_dst), "l"(gsrc));
}
#define CP_ASYNC_COMMIT() asm volatile("cp.async.commit_group;\n" ::: "memory")
#define CP_ASYNC_WAIT1()  asm volatile("cp.async.wait_group 1;\n" ::: "memory")

__device__ __forceinline__ void ldmatrix_x4(uint32_t& r0, uint32_t& r1, uint32_t& r2, uint32_t& r3,
                                            uint32_t addr) {
    asm volatile("ldmatrix.sync.aligned.m8n8.x4.shared.b16 {%0,%1,%2,%3}, [%4];"
                 : "=r"(r0), "=r"(r1), "=r"(r2), "=r"(r3) : "r"(addr));
}
__device__ __forceinline__ void mma_f16(float& c0, float& c1, float& c2, float& c3,
                                        uint32_t a0, uint32_t a1, uint32_t a2, uint32_t a3,
                                        uint32_t b0, uint32_t b1) {
    asm volatile("mma.sync.aligned.m16n8k16.row.col.f32.f16.f16.f32 "
                 "{%0,%1,%2,%3}, {%4,%5,%6,%7}, {%8,%9}, {%0,%1,%2,%3};"
                 : "+f"(c0), "+f"(c1), "+f"(c2), "+f"(c3)
                 : "r"(a0), "r"(a1), "r"(a2), "r"(a3), "r"(b0), "r"(b1));
}
// Clamp to >= 0; clears any -0.0 so bit patterns are monotonic as unsigned.
__device__ __forceinline__ float clean_d2(float x) {
    return __uint_as_float(__float_as_uint(fmaxf(x, 0.0f)) & 0x7fffffffu);
}
__device__ __forceinline__ u64 umin64(u64 a, u64 b) { return a < b ? a : b; }
__device__ __forceinline__ u64 umax64(u64 a, u64 b) { return a > b ? a : b; }

// ===========================================================================
// Fused prep: fp32 -> fp16 convert AND row stats (sq, s). One block per row.
// Block 0 zeroes the output scalar and the class counters.
// ===========================================================================
__global__ void __launch_bounds__(256) prep_kernel(const float* __restrict__ E,
                                                   int N, int D,
                                                   float* __restrict__ out) {
    int i = blockIdx.x;
    if (i == 0) {
        if (threadIdx.x == 0) out[0] = 0.0f;
        if (threadIdx.x < NCLS) g_ccnt[threadIdx.x] = 0;
    }
    float a = 0.0f, b = 0.0f;
    for (int k = threadIdx.x; k < D / 4; k += blockDim.x) {
        int idx = i * (D / 4) + k;
        float4 v = ((const float4*)E)[idx];
        a = fmaf(v.x, v.x, a); a = fmaf(v.y, v.y, a);
        a = fmaf(v.z, v.z, a); a = fmaf(v.w, v.w, a);
        b += v.x + v.y + v.z + v.w;
        __half2 h01 = __floats2half2_rn(v.x, v.y);
        __half2 h23 = __floats2half2_rn(v.z, v.w);
        uint2 hv;
        hv.x = *(const uint32_t*)&h01;
        hv.y = *(const uint32_t*)&h23;
        ((uint2*)g_Eh)[idx] = hv;
    }
#pragma unroll
    for (int off = 16; off > 0; off >>= 1) {
        a += __shfl_down_sync(0xffffffffu, a, off);
        b += __shfl_down_sync(0xffffffffu, b, off);
    }
    __shared__ float sa[8], sb[8];
    int w = threadIdx.x >> 5, l = threadIdx.x & 31;
    if (l == 0) { sa[w] = a; sb[w] = b; }
    __syncthreads();
    if (threadIdx.x == 0) {
        float A = 0.0f, B = 0.0f;
        int nw = blockDim.x >> 5;
        for (int x = 0; x < nw; x++) { A += sa[x]; B += sb[x]; }
        g_sq[i] = A;
        g_s[i] = B;
    }
}

// ===========================================================================
// Class lists + key init. Slot order from atomics is arbitrary; consumers use
// order-independent keyed max/min, so results stay deterministic.
// ===========================================================================
__global__ void __launch_bounds__(256) classinit_kernel(const int* __restrict__ target, int N) {
    int j = blockIdx.x * blockDim.x + threadIdx.x;
    if (j < N) {
        g_negkey[j] = ~0ULL;
        g_winkey[j] = ~0ULL;
        g_poskey[j] = 0ULL;
        int c = target[j];
        int slot = atomicAdd(&g_ccnt[c], 1);
        if (slot < CAP) g_cls[c * CAP + slot] = j;
    }
}

// ===========================================================================
// Positive gram: one block per class, gathered 128x128 HMMA (B operand = A).
// Same mainloop structure as the main gram. Epilogue: per-anchor max-key
// (hardest positive, min index via 8191-j) -> atomicMax(g_poskey).
// ===========================================================================
#define PSTAGES 3
#define P_BYTES (128 * 128)
#define POS_SMEM (PSTAGES * P_BYTES + 1024)

__global__ void __launch_bounds__(256) pos_gram_kernel(int N, int D) {
    int c = blockIdx.x;
    __shared__ int midx[128];
    __shared__ float msq[128];
    int cnt = g_ccnt[c];
    if (cnt > 128) cnt = 128;
    if (cnt == 0) return;
    int tid = threadIdx.x;
    if (tid < 128) {
        int m = g_cls[c * CAP + ((tid < cnt) ? tid : 0)];  // pad with member 0
        midx[tid] = m;
        msq[tid] = g_sq[m];
    }
    __syncthreads();

    extern __shared__ char dsmem[];
    uint32_t base = (smem_to_u32(dsmem) + 1023u) & ~1023u;

    const int wid = tid >> 5, lane = tid & 31;
    const int wm = wid & 3, wn = wid >> 2;
    const int NC = D / 64;
    const size_t rowstride = (size_t)D * 2;
    const int l_kk = tid & 7, l_r0 = tid >> 3;

    auto load_chunk = [&](int ch) {
        uint32_t sb = base + (uint32_t)(ch % PSTAGES) * P_BYTES;
#pragma unroll
        for (int i = 0; i < 4; i++) {
            int r = l_r0 + i * 32;
            const char* g = (const char*)g_Eh + (size_t)midx[r] * rowstride + (size_t)ch * 128 + l_kk * 16;
            uint32_t sw = (uint32_t)(r * 128) + (uint32_t)((l_kk * 16) ^ ((r & 7) << 4));
            cp_async16(sb + sw, g);
        }
        CP_ASYNC_COMMIT();
    };

    uint32_t a_row[2], a_xor[2];
#pragma unroll
    for (int mt = 0; mt < 2; mt++) {
        int r = wm * 32 + mt * 16 + (lane & 15);
        a_row[mt] = (uint32_t)(r * 128);
        a_xor[mt] = (uint32_t)((r & 7) << 4);
    }
    const uint32_t a_cb = (uint32_t)((lane >> 4) * 16);
    uint32_t b_row[4], b_xor[4];
#pragma unroll
    for (int g = 0; g < 4; g++) {
        int r = wn * 64 + g * 16 + (lane & 7) + ((lane >> 4) & 1) * 8;
        b_row[g] = (uint32_t)(r * 128);
        b_xor[g] = (uint32_t)((r & 7) << 4);
    }
    const uint32_t b_cb = (uint32_t)(((lane >> 3) & 1) * 16);

    float acc[2][8][4];
#pragma unroll
    for (int mt = 0; mt < 2; mt++)
#pragma unroll
        for (int nt = 0; nt < 8; nt++)
#pragma unroll
            for (int x = 0; x < 4; x++) acc[mt][nt][x] = 0.0f;

    load_chunk(0);
    load_chunk(1);
    for (int ch = 0; ch < NC; ch++) {
        CP_ASYNC_WAIT1();
        __syncthreads();
        if (ch + 2 < NC) load_chunk(ch + 2);
        uint32_t sA = base + (uint32_t)(ch % PSTAGES) * P_BYTES;
#pragma unroll
        for (int ks = 0; ks < 4; ks++) {
            uint32_t kb = (uint32_t)(ks * 32);
            uint32_t af[2][4];
#pragma unroll
            for (int mt = 0; mt < 2; mt++) {
                uint32_t addr = sA + a_row[mt] + ((kb + a_cb) ^ a_xor[mt]);
                ldmatrix_x4(af[mt][0], af[mt][1], af[mt][2], af[mt][3], addr);
            }
            uint32_t bfr[4][4];
#pragma unroll
            for (int g = 0; g < 4; g++) {
                uint32_t addr = sA + b_row[g] + ((kb + b_cb) ^ b_xor[g]);
                ldmatrix_x4(bfr[g][0], bfr[g][1], bfr[g][2], bfr[g][3], addr);
            }
#pragma unroll
            for (int mt = 0; mt < 2; mt++)
#pragma unroll
                for (int g = 0; g < 4; g++) {
                    mma_f16(acc[mt][g * 2][0], acc[mt][g * 2][1], acc[mt][g * 2][2], acc[mt][g * 2][3],
                            af[mt][0], af[mt][1], af[mt][2], af[mt][3], bfr[g][0], bfr[g][1]);
                    mma_f16(acc[mt][g * 2 + 1][0], acc[mt][g * 2 + 1][1], acc[mt][g * 2 + 1][2], acc[mt][g * 2 + 1][3],
                            af[mt][0], af[mt][1], af[mt][2], af[mt][3], bfr[g][2], bfr[g][3]);
                }
        }
    }

    // Epilogue: hardest positive per row (max d2, min index).
    const int qr = lane >> 2;
    const int qc = (lane & 3) * 2;
#pragma unroll
    for (int mt = 0; mt < 2; mt++) {
#pragma unroll
        for (int h = 0; h < 2; h++) {
            int rloc = wm * 32 + mt * 16 + qr + h * 8;
            float sa = msq[rloc];
            u64 kmax = 0ULL;
#pragma unroll
            for (int nt = 0; nt < 8; nt++) {
#pragma unroll
                for (int b = 0; b < 2; b++) {
                    int cloc = wn * 64 + nt * 8 + qc + b;
                    int x = h * 2 + b;
                    if (cloc < cnt && cloc != rloc) {
                        float d2 = clean_d2(sa + msq[cloc] - 2.0f * acc[mt][nt][x]);
                        int jb = midx[cloc];
                        u64 key = ((u64)__float_as_uint(d2) << 13) | (u64)(8191 - jb);
                        kmax = umax64(kmax, key);
                    }
                }
            }
            kmax = umax64(kmax, __shfl_xor_sync(0xffffffffu, kmax, 1));
            kmax = umax64(kmax, __shfl_xor_sync(0xffffffffu, kmax, 2));
            if ((lane & 3) == 0 && rloc < cnt && kmax != 0ULL)
                atomicMax(&g_poskey[midx[rloc]], kmax);
        }
    }
}

// Derive per-anchor window bound bits (0xFFFFFFFF disables the window).
__global__ void __launch_bounds__(256) dpwin_kernel(int N) {
    int i = blockIdx.x * blockDim.x + threadIdx.x;
    if (i < N) {
        u64 pk = g_poskey[i];
        g_dpwin[i] = (pk == 0ULL) ? 0xFFFFFFFFu : (unsigned)(pk >> 13);
    }
}

// ===========================================================================
// Main gram (negatives): fp16 HMMA, 3-stage cp.async, CTA tile 128x128,
// triangular 1D grid. NO matrix stores — the epilogue reduces each tile
// directly into per-anchor negkey/winkey atomics (row side + mirrored col
// side; diagonal tiles are idempotent duplicates).
// ===========================================================================
#define GSTAGES 3
#define A_BYTES (128 * 128)
#define B_BYTES (128 * 128)
#define STAGE_BYTES (A_BYTES + B_BYTES)
#define GRAM_SMEM (GSTAGES * STAGE_BYTES + 1024)

__global__ void __launch_bounds__(256) gram_mma_kernel(const int* __restrict__ target,
                                                       int N, int D) {
    unsigned idx = blockIdx.x;
    int bi = (int)((sqrt(8.0 * (double)idx + 1.0) - 1.0) * 0.5);
    while ((size_t)(bi + 1) * (bi + 2) / 2 <= idx) bi++;
    while ((size_t)bi * (bi + 1) / 2 > idx) bi--;
    int bj = (int)(idx - (size_t)bi * (bi + 1) / 2);

    extern __shared__ char dsmem[];
    uint32_t base = (smem_to_u32(dsmem) + 1023u) & ~1023u;

    __shared__ unsigned s_tr[128], s_tc[128], s_dr[128], s_dc[128];

    const int tid = threadIdx.x;
    const int wid = tid >> 5, lane = tid & 31;
    const int wm = wid & 3;
    const int wn = wid >> 2;

    const int NC = D / 64;
    const size_t rowstride = (size_t)D * 2;

    const int l_kk = tid & 7;
    const int l_r0 = tid >> 3;
    auto load_chunk = [&](int c) {
        const char* Esrc = (const char*)g_Eh;
        uint32_t sb = base + (uint32_t)(c % GSTAGES) * STAGE_BYTES;
        const char* ga = Esrc + (size_t)(bi * 128) * rowstride + (size_t)c * 128 + l_kk * 16;
        const char* gb = Esrc + (size_t)(bj * 128) * rowstride + (size_t)c * 128 + l_kk * 16;
#pragma unroll
        for (int i = 0; i < 4; i++) {
            int r = l_r0 + i * 32;
            uint32_t sw = (uint32_t)(r * 128) + (uint32_t)((l_kk * 16) ^ ((r & 7) << 4));
            cp_async16(sb + sw, ga + (size_t)r * rowstride);
            cp_async16(sb + A_BYTES + sw, gb + (size_t)r * rowstride);
        }
        CP_ASYNC_COMMIT();
    };

    // Load per-row / per-col metadata (targets + window bounds).
    if (tid < 128) {
        s_tr[tid] = (unsigned)target[bi * 128 + tid];
        s_dr[tid] = g_dpwin[bi * 128 + tid];
    } else {
        int t2 = tid - 128;
        s_tc[t2] = (unsigned)target[bj * 128 + t2];
        s_dc[t2] = g_dpwin[bj * 128 + t2];
    }

    uint32_t a_row[2], a_xor[2];
#pragma unroll
    for (int mt = 0; mt < 2; mt++) {
        int r = wm * 32 + mt * 16 + (lane & 15);
        a_row[mt] = (uint32_t)(r * 128);
        a_xor[mt] = (uint32_t)((r & 7) << 4);
    }
    const uint32_t a_cb = (uint32_t)((lane >> 4) * 16);
    uint32_t b_row[4], b_xor[4];
#pragma unroll
    for (int g = 0; g < 4; g++) {
        int r = wn * 64 + g * 16 + (lane & 7) + ((lane >> 4) & 1) * 8;
        b_row[g] = (uint32_t)(r * 128);
        b_xor[g] = (uint32_t)((r & 7) << 4);
    }
    const uint32_t b_cb = (uint32_t)(((lane >> 3) & 1) * 16);

    float acc[2][8][4];
#pragma unroll
    for (int mt = 0; mt < 2; mt++)
#pragma unroll
        for (int nt = 0; nt < 8; nt++)
#pragma unroll
            for (int x = 0; x < 4; x++) acc[mt][nt][x] = 0.0f;

    load_chunk(0);
    load_chunk(1);

    for (int c = 0; c < NC; c++) {
        CP_ASYNC_WAIT1();
        __syncthreads();
        if (c + 2 < NC) load_chunk(c + 2);

        uint32_t sA = base + (uint32_t)(c % GSTAGES) * STAGE_BYTES;
        uint32_t sB = sA + A_BYTES;

#pragma unroll
        for (int ks = 0; ks < 4; ks++) {
            uint32_t kb = (uint32_t)(ks * 32);
            uint32_t af[2][4];
#pragma unroll
            for (int mt = 0; mt < 2; mt++) {
                uint32_t addr = sA + a_row[mt] + ((kb + a_cb) ^ a_xor[mt]);
                ldmatrix_x4(af[mt][0], af[mt][1], af[mt][2], af[mt][3], addr);
            }
            uint32_t bfr[4][4];
#pragma unroll
            for (int g = 0; g < 4; g++) {
                uint32_t addr = sB + b_row[g] + ((kb + b_cb) ^ b_xor[g]);
                ldmatrix_x4(bfr[g][0], bfr[g][1], bfr[g][2], bfr[g][3], addr);
            }
#pragma unroll
            for (int mt = 0; mt < 2; mt++)
#pragma unroll
                for (int g = 0; g < 4; g++) {
                    mma_f16(acc[mt][g * 2][0], acc[mt][g * 2][1], acc[mt][g * 2][2], acc[mt][g * 2][3],
                            af[mt][0], af[mt][1], af[mt][2], af[mt][3], bfr[g][0], bfr[g][1]);
                    mma_f16(acc[mt][g * 2 + 1][0], acc[mt][g * 2 + 1][1], acc[mt][g * 2 + 1][2], acc[mt][g * 2 + 1][3],
                            af[mt][0], af[mt][1], af[mt][2], af[mt][3], bfr[g][2], bfr[g][3]);
                }
        }
    }

    // ---- Epilogue: dot -> d^2 in place, then fused keyed reductions. ----
    const int qr = lane >> 2;
    const int qc = (lane & 3) * 2;

    float sr[2][2];
#pragma unroll
    for (int mt = 0; mt < 2; mt++) {
        int r0 = bi * 128 + wm * 32 + mt * 16 + qr;
        sr[mt][0] = g_sq[r0];
        sr[mt][1] = g_sq[r0 + 8];
    }
#pragma unroll
    for (int mt = 0; mt < 2; mt++) {
#pragma unroll
        for (int nt = 0; nt < 8; nt++) {
            int gc = bj * 128 + wn * 64 + nt * 8 + qc;
            float sn0 = g_sq[gc], sn1 = g_sq[gc + 1];
            acc[mt][nt][0] = clean_d2(sr[mt][0] + sn0 - 2.0f * acc[mt][nt][0]);
            acc[mt][nt][1] = clean_d2(sr[mt][0] + sn1 - 2.0f * acc[mt][nt][1]);
            acc[mt][nt][2] = clean_d2(sr[mt][1] + sn0 - 2.0f * acc[mt][nt][2]);
            acc[mt][nt][3] = clean_d2(sr[mt][1] + sn1 - 2.0f * acc[mt][nt][3]);
        }
    }
    __syncthreads();   // s_tr/s_tc/s_dr/s_dc visible

    // Row side: anchors = bi-block rows; candidates = bj-block cols.
#pragma unroll
    for (int mt = 0; mt < 2; mt++) {
#pragma unroll
        for (int h = 0; h < 2; h++) {
            int rloc = wm * 32 + mt * 16 + qr + h * 8;
            unsigned tr = s_tr[rloc], dw = s_dr[rloc];
            u64 kn = ~0ULL, kw = ~0ULL;
#pragma unroll
            for (int nt = 0; nt < 8; nt++) {
#pragma unroll
                for (int b = 0; b < 2; b++) {
                    int cloc = wn * 64 + nt * 8 + qc + b;
                    if (s_tc[cloc] != tr) {
                        unsigned bits = __float_as_uint(acc[mt][nt][h * 2 + b]);
                        u64 k = ((u64)bits << 13) | (unsigned)(bj * 128 + cloc);
                        kn = umin64(kn, k);
                        if (bits > dw) kw = umin64(kw, k);
                    }
                }
            }
            kn = umin64(kn, __shfl_xor_sync(0xffffffffu, kn, 1));
            kn = umin64(kn, __shfl_xor_sync(0xffffffffu, kn, 2));
            kw = umin64(kw, __shfl_xor_sync(0xffffffffu, kw, 1));
            kw = umin64(kw, __shfl_xor_sync(0xffffffffu, kw, 2));
            if ((lane & 3) == 0) {
                if (kn != ~0ULL) atomicMin(&g_negkey[bi * 128 + rloc], kn);
                if (kw != ~0ULL) atomicMin(&g_winkey[bi * 128 + rloc], kw);
            }
        }
    }

    // Col side (mirror): anchors = bj-block cols; candidates = bi-block rows.
#pragma unroll
    for (int nt = 0; nt < 8; nt++) {
#pragma unroll
        for (int b = 0; b < 2; b++) {
            int cloc = wn * 64 + nt * 8 + qc + b;
            unsigned tc = s_tc[cloc], dw = s_dc[cloc];
            u64 kn = ~0ULL, kw = ~0ULL;
#pragma unroll
            for (int mt = 0; mt < 2; mt++) {
#pragma unroll
                for (int h = 0; h < 2; h++) {
                    int rloc = wm * 32 + mt * 16 + qr + h * 8;
                    if (s_tr[rloc] != tc) {
                        unsigned bits = __float_as_uint(acc[mt][nt][h * 2 + b]);
                        u64 k = ((u64)bits << 13) | (unsigned)(bi * 128 + rloc);
                        kn = umin64(kn, k);
                        if (bits > dw) kw = umin64(kw, k);
                    }
                }
            }
            kn = umin64(kn, __shfl_xor_sync(0xffffffffu, kn, 4));
            kn = umin64(kn, __shfl_xor_sync(0xffffffffu, kn, 8));
            kn = umin64(kn, __shfl_xor_sync(0xffffffffu, kn, 16));
            kw = umin64(kw, __shfl_xor_sync(0xffffffffu, kw, 4));
            kw = umin64(kw, __shfl_xor_sync(0xffffffffu, kw, 8));
            kw = umin64(kw, __shfl_xor_sync(0xffffffffu, kw, 16));
            if (qr == 0) {
                if (kn != ~0ULL) atomicMin(&g_negkey[bj * 128 + cloc], kn);
                if (kw != ~0ULL) atomicMin(&g_winkey[bj * 128 + cloc], kw);
            }
        }
    }
}

// ===========================================================================
// Loss: per-anchor, decode keys (exact fp32 d^2 in the bits), apply torch
// eps correction, relu, mean via atomicAdd.
// ===========================================================================
__global__ void __launch_bounds__(256) loss_kernel(int N, int D, float* __restrict__ out) {
    int i = blockIdx.x * blockDim.x + threadIdx.x;
    if (i >= N) return;
    u64 posk = g_poskey[i];
    u64 negk = g_negkey[i];
    u64 wink = g_winkey[i];

    int p;
    float d2p;
    if (posk != 0ULL) {
        p = 8191 - (int)(posk & 8191ULL);
        d2p = __uint_as_float((unsigned)(posk >> 13));
    } else {
        // No positive (singleton class): reference argmax picks index 0.
        p = 0;
        const __half* a = g_Eh + (size_t)i * D;
        const __half* b = g_Eh;
        float dot = 0.0f;
        for (int k = 0; k < D; k++)
            dot = fmaf(__half2float(a[k]), __half2float(b[k]), dot);
        d2p = clean_d2(g_sq[i] + g_sq[0] - 2.0f * dot);
    }

    float dpv = sqrtf(d2p);
    float hi2 = (dpv + MARGIN) * (dpv + MARGIN);
    int neg;
    float d2n;
    // Window valid only if a positive existed (else winkey stayed ~0).
    if (posk != 0ULL && wink != ~0ULL &&
        __uint_as_float((unsigned)(wink >> 13)) < hi2) {
        neg = (int)(wink & 8191ULL);
        d2n = __uint_as_float((unsigned)(wink >> 13));
    } else if (negk != ~0ULL) {
        neg = (int)(negk & 8191ULL);
        d2n = __uint_as_float((unsigned)(negk >> 13));
    } else {
        neg = 0;
        d2n = 0.0f;
    }

    float si = g_s[i];
    float epsC = (float)D * EPS * EPS;
    float dp = sqrtf(fmaxf(d2p + 2.0f * EPS * (si - g_s[p]) + epsC, 0.0f));
    float dn = sqrtf(fmaxf(d2n + 2.0f * EPS * (si - g_s[neg]) + epsC, 0.0f));
    float term = fmaxf(dp - dn + MARGIN, 0.0f);
    atomicAdd(out, term / (float)N);
}

// ---------------------------------------------------------------------------
extern "C" void kernel_launch(void* const* d_in, const int* in_sizes, int n_in,
                              void* d_out, int out_size) {
    const float* E = (const float*)d_in[0];   // embeddings [N, D] fp32
    const int* target = (const int*)d_in[1];  // [N] int32
    float* out = (float*)d_out;

    int N = in_sizes[1];
    int D = in_sizes[0] / N;

    prep_kernel<<<N, 256>>>(E, N, D, out);
    classinit_kernel<<<(N + 255) / 256, 256>>>(target, N);

    cudaFuncSetAttribute(pos_gram_kernel, cudaFuncAttributeMaxDynamicSharedMemorySize, POS_SMEM);
    pos_gram_kernel<<<NCLS, 256, POS_SMEM>>>(N, D);

    dpwin_kernel<<<(N + 255) / 256, 256>>>(N);

    cudaFuncSetAttribute(gram_mma_kernel, cudaFuncAttributeMaxDynamicSharedMemorySize, GRAM_SMEM);
    int nt = N / 128;
    int ntri = nt * (nt + 1) / 2;             // 2080 triangular tile pairs
    gram_mma_kernel<<<ntri, 256, GRAM_SMEM>>>(target, N, D);

    loss_kernel<<<(N + 255) / 256, 256>>>(N, D, out);
}

// round 15
// speedup vs baseline: 2.4846x; 1.0572x over previous
#include <cuda_runtime.h>
#include <cuda_fp16.h>
#include <cstdint>

// Problem constants (fixed shapes per reference: N=8192, D=1024, 128 classes)
#define NMAX 8192
#define DMAX 1024
#define MARGIN 1.0f
#define EPS 1e-6f
#define NCLS 128
#define CAP 256          /* max members per class (mean 64; huge safety margin) */

typedef unsigned long long u64;
#define NOKEY64 ((((u64)0xFFFFFFFFu) << 13) | 8191ULL)   /* no-candidate sentinel */

// Scratch (static __device__ arrays; no allocation). No big G matrix.
__device__ float g_sq[NMAX];                         // ||e_i||^2 (fp32)
__device__ float g_s[NMAX];                          // sum_k e_ik
__device__ __half g_Eh[(size_t)NMAX * DMAX];         // fp16 embeddings
__device__ int g_cls[NCLS * CAP];                    // class member lists
__device__ int g_ccnt[NCLS];                         // class member counts
// Keyed results: key = (d2_fp32_bits << 13) | j   (j fits in 13 bits, N=8192)
__device__ u64 g_poskey[NMAX];   // max over positives; index stored as 8191-j
__device__ u64 g_negkey[NMAX];   // min over all negatives
__device__ u64 g_winkey[NMAX];   // min over negatives with d2 > dp2

// ===========================================================================
// Helpers
// ===========================================================================
__device__ __forceinline__ uint32_t smem_to_u32(const void* p) {
    uint32_t a;
    asm("{ .reg .u64 t; cvta.to.shared.u64 t, %1; cvt.u32.u64 %0, t; }" : "=r"(a) : "l"(p));
    return a;
}
__device__ __forceinline__ void cp_async16(uint32_t smem_dst, const void* gsrc) {
    asm volatile("cp.async.cg.shared.global [%0], [%1], 16;\n" :: "r"(smem_dst), "l"(gsrc));
}
#define CP_ASYNC_COMMIT() asm volatile("cp.async.commit_group;\n" ::: "memory")
#define CP_ASYNC_WAIT1()  asm volatile("cp.async.wait_group 1;\n" ::: "memory")

__device__ __forceinline__ void ldmatrix_x4(uint32_t& r0, uint32_t& r1, uint32_t& r2, uint32_t& r3,
                                            uint32_t addr) {
    asm volatile("ldmatrix.sync.aligned.m8n8.x4.shared.b16 {%0,%1,%2,%3}, [%4];"
                 : "=r"(r0), "=r"(r1), "=r"(r2), "=r"(r3) : "r"(addr));
}
__device__ __forceinline__ void mma_f16(float& c0, float& c1, float& c2, float& c3,
                                        uint32_t a0, uint32_t a1, uint32_t a2, uint32_t a3,
                                        uint32_t b0, uint32_t b1) {
    asm volatile("mma.sync.aligned.m16n8k16.row.col.f32.f16.f16.f32 "
                 "{%0,%1,%2,%3}, {%4,%5,%6,%7}, {%8,%9}, {%0,%1,%2,%3};"
                 : "+f"(c0), "+f"(c1), "+f"(c2), "+f"(c3)
                 : "r"(a0), "r"(a1), "r"(a2), "r"(a3), "r"(b0), "r"(b1));
}
// Clamp to >= 0; clears any -0.0 so bit patterns are monotonic as unsigned.
__device__ __forceinline__ float clean_d2(float x) {
    return __uint_as_float(__float_as_uint(fmaxf(x, 0.0f)) & 0x7fffffffu);
}
__device__ __forceinline__ u64 umin64(u64 a, u64 b) { return a < b ? a : b; }
__device__ __forceinline__ u64 umax64(u64 a, u64 b) { return a > b ? a : b; }

// ===========================================================================
// Fused prep: fp32 -> fp16 convert, row stats (sq, s), key init, class-list
// push (thread 0 of block i handles anchor i). Block 0 zeroes out/counters
// BEFORE any push via a grid-wide ordering trick: counters are zeroed by a
// separate tiny launch-free path -- instead we init counters in a dedicated
// first kernel? No: we zero g_ccnt in prep block i==0 AND do all pushes in a
// SECOND kernel? To keep ordering safe, counters are zeroed host-side by
// keeping the push in prep but zeroing via classzero_kernel first is needed.
// Simpler: counters zeroed in prep block0 is racy vs other blocks' pushes.
// => keys are initialized here (per-anchor, race-free); class push stays in a
// tiny kernel AFTER prep (but fused with nothing else).
// ===========================================================================
__global__ void __launch_bounds__(256) prep_kernel(const float* __restrict__ E,
                                                   int N, int D,
                                                   float* __restrict__ out) {
    int i = blockIdx.x;
    if (threadIdx.x == 0) {
        if (i == 0) out[0] = 0.0f;
        if (i < NCLS) g_ccnt[i] = 0;
        g_negkey[i] = ~0ULL;
        g_winkey[i] = ~0ULL;
        g_poskey[i] = 0ULL;
    }
    float a = 0.0f, b = 0.0f;
    for (int k = threadIdx.x; k < D / 4; k += blockDim.x) {
        int idx = i * (D / 4) + k;
        float4 v = ((const float4*)E)[idx];
        a = fmaf(v.x, v.x, a); a = fmaf(v.y, v.y, a);
        a = fmaf(v.z, v.z, a); a = fmaf(v.w, v.w, a);
        b += v.x + v.y + v.z + v.w;
        __half2 h01 = __floats2half2_rn(v.x, v.y);
        __half2 h23 = __floats2half2_rn(v.z, v.w);
        uint2 hv;
        hv.x = *(const uint32_t*)&h01;
        hv.y = *(const uint32_t*)&h23;
        ((uint2*)g_Eh)[idx] = hv;
    }
#pragma unroll
    for (int off = 16; off > 0; off >>= 1) {
        a += __shfl_down_sync(0xffffffffu, a, off);
        b += __shfl_down_sync(0xffffffffu, b, off);
    }
    __shared__ float sa[8], sb[8];
    int w = threadIdx.x >> 5, l = threadIdx.x & 31;
    if (l == 0) { sa[w] = a; sb[w] = b; }
    __syncthreads();
    if (threadIdx.x == 0) {
        float A = 0.0f, B = 0.0f;
        int nw = blockDim.x >> 5;
        for (int x = 0; x < nw; x++) { A += sa[x]; B += sb[x]; }
        g_sq[i] = A;
        g_s[i] = B;
    }
}

// Class list build (after prep zeroed the counters). Slot order is arbitrary;
// consumers use order-independent keyed max/min -> deterministic results.
__global__ void __launch_bounds__(256) classlist_kernel(const int* __restrict__ target, int N) {
    int j = blockIdx.x * blockDim.x + threadIdx.x;
    if (j < N) {
        int c = target[j];
        int slot = atomicAdd(&g_ccnt[c], 1);
        if (slot < CAP) g_cls[c * CAP + slot] = j;
    }
}

// ===========================================================================
// Positive gram: one block per class, gathered 128x128 HMMA (B operand = A).
// Epilogue: per-anchor max-key (hardest positive, min index via 8191-j).
// ===========================================================================
#define PSTAGES 3
#define P_BYTES (128 * 128)
#define POS_SMEM (PSTAGES * P_BYTES + 1024)

__global__ void __launch_bounds__(256) pos_gram_kernel(int N, int D) {
    int c = blockIdx.x;
    __shared__ int midx[128];
    __shared__ float msq[128];
    int cnt = g_ccnt[c];
    if (cnt > 128) cnt = 128;
    if (cnt == 0) return;
    int tid = threadIdx.x;
    if (tid < 128) {
        int m = g_cls[c * CAP + ((tid < cnt) ? tid : 0)];  // pad with member 0
        midx[tid] = m;
        msq[tid] = g_sq[m];
    }
    __syncthreads();

    extern __shared__ char dsmem[];
    uint32_t base = (smem_to_u32(dsmem) + 1023u) & ~1023u;

    const int wid = tid >> 5, lane = tid & 31;
    const int wm = wid & 3, wn = wid >> 2;
    const int NC = D / 64;
    const size_t rowstride = (size_t)D * 2;
    const int l_kk = tid & 7, l_r0 = tid >> 3;

    auto load_chunk = [&](int ch) {
        uint32_t sb = base + (uint32_t)(ch % PSTAGES) * P_BYTES;
#pragma unroll
        for (int i = 0; i < 4; i++) {
            int r = l_r0 + i * 32;
            const char* g = (const char*)g_Eh + (size_t)midx[r] * rowstride + (size_t)ch * 128 + l_kk * 16;
            uint32_t sw = (uint32_t)(r * 128) + (uint32_t)((l_kk * 16) ^ ((r & 7) << 4));
            cp_async16(sb + sw, g);
        }
        CP_ASYNC_COMMIT();
    };

    uint32_t a_row[2], a_xor[2];
#pragma unroll
    for (int mt = 0; mt < 2; mt++) {
        int r = wm * 32 + mt * 16 + (lane & 15);
        a_row[mt] = (uint32_t)(r * 128);
        a_xor[mt] = (uint32_t)((r & 7) << 4);
    }
    const uint32_t a_cb = (uint32_t)((lane >> 4) * 16);
    uint32_t b_row[4], b_xor[4];
#pragma unroll
    for (int g = 0; g < 4; g++) {
        int r = wn * 64 + g * 16 + (lane & 7) + ((lane >> 4) & 1) * 8;
        b_row[g] = (uint32_t)(r * 128);
        b_xor[g] = (uint32_t)((r & 7) << 4);
    }
    const uint32_t b_cb = (uint32_t)(((lane >> 3) & 1) * 16);

    float acc[2][8][4];
#pragma unroll
    for (int mt = 0; mt < 2; mt++)
#pragma unroll
        for (int nt = 0; nt < 8; nt++)
#pragma unroll
            for (int x = 0; x < 4; x++) acc[mt][nt][x] = 0.0f;

    load_chunk(0);
    load_chunk(1);
    for (int ch = 0; ch < NC; ch++) {
        CP_ASYNC_WAIT1();
        __syncthreads();
        if (ch + 2 < NC) load_chunk(ch + 2);
        uint32_t sA = base + (uint32_t)(ch % PSTAGES) * P_BYTES;
#pragma unroll
        for (int ks = 0; ks < 4; ks++) {
            uint32_t kb = (uint32_t)(ks * 32);
            uint32_t af[2][4];
#pragma unroll
            for (int mt = 0; mt < 2; mt++) {
                uint32_t addr = sA + a_row[mt] + ((kb + a_cb) ^ a_xor[mt]);
                ldmatrix_x4(af[mt][0], af[mt][1], af[mt][2], af[mt][3], addr);
            }
            uint32_t bfr[4][4];
#pragma unroll
            for (int g = 0; g < 4; g++) {
                uint32_t addr = sA + b_row[g] + ((kb + b_cb) ^ b_xor[g]);
                ldmatrix_x4(bfr[g][0], bfr[g][1], bfr[g][2], bfr[g][3], addr);
            }
#pragma unroll
            for (int mt = 0; mt < 2; mt++)
#pragma unroll
                for (int g = 0; g < 4; g++) {
                    mma_f16(acc[mt][g * 2][0], acc[mt][g * 2][1], acc[mt][g * 2][2], acc[mt][g * 2][3],
                            af[mt][0], af[mt][1], af[mt][2], af[mt][3], bfr[g][0], bfr[g][1]);
                    mma_f16(acc[mt][g * 2 + 1][0], acc[mt][g * 2 + 1][1], acc[mt][g * 2 + 1][2], acc[mt][g * 2 + 1][3],
                            af[mt][0], af[mt][1], af[mt][2], af[mt][3], bfr[g][2], bfr[g][3]);
                }
        }
    }

    // Epilogue: hardest positive per row (max d2, min index).
    const int qr = lane >> 2;
    const int qc = (lane & 3) * 2;
#pragma unroll
    for (int mt = 0; mt < 2; mt++) {
#pragma unroll
        for (int h = 0; h < 2; h++) {
            int rloc = wm * 32 + mt * 16 + qr + h * 8;
            float sa = msq[rloc];
            u64 kmax = 0ULL;
#pragma unroll
            for (int nt = 0; nt < 8; nt++) {
#pragma unroll
                for (int b = 0; b < 2; b++) {
                    int cloc = wn * 64 + nt * 8 + qc + b;
                    int x = h * 2 + b;
                    if (cloc < cnt && cloc != rloc) {
                        float d2 = clean_d2(sa + msq[cloc] - 2.0f * acc[mt][nt][x]);
                        int jb = midx[cloc];
                        u64 key = ((u64)__float_as_uint(d2) << 13) | (u64)(8191 - jb);
                        kmax = umax64(kmax, key);
                    }
                }
            }
            kmax = umax64(kmax, __shfl_xor_sync(0xffffffffu, kmax, 1));
            kmax = umax64(kmax, __shfl_xor_sync(0xffffffffu, kmax, 2));
            if ((lane & 3) == 0 && rloc < cnt && kmax != 0ULL)
                atomicMax(&g_poskey[midx[rloc]], kmax);
        }
    }
}

// ===========================================================================
// Main gram (negatives): fp16 HMMA, 3-stage cp.async, CTA tile 128x128,
// triangular 1D grid. No matrix stores — epilogue reduces each tile into
// per-anchor negkey/winkey atomics. Window bound decoded from g_poskey
// inline (dpwin kernel removed). Per-lane candidate loops track (bits, j)
// with strict '<' (ascending-j visit order => first-index tie-break); exact
// u64 keys only for cross-lane shuffles and atomics.
// ===========================================================================
#define GSTAGES 3
#define A_BYTES (128 * 128)
#define B_BYTES (128 * 128)
#define STAGE_BYTES (A_BYTES + B_BYTES)
#define GRAM_SMEM (GSTAGES * STAGE_BYTES + 1024)

__global__ void __launch_bounds__(256) gram_mma_kernel(const int* __restrict__ target,
                                                       int N, int D) {
    unsigned idx = blockIdx.x;
    int bi = (int)((sqrt(8.0 * (double)idx + 1.0) - 1.0) * 0.5);
    while ((size_t)(bi + 1) * (bi + 2) / 2 <= idx) bi++;
    while ((size_t)bi * (bi + 1) / 2 > idx) bi--;
    int bj = (int)(idx - (size_t)bi * (bi + 1) / 2);

    extern __shared__ char dsmem[];
    uint32_t base = (smem_to_u32(dsmem) + 1023u) & ~1023u;

    __shared__ unsigned s_tr[128], s_tc[128], s_dr[128], s_dc[128];

    const int tid = threadIdx.x;
    const int wid = tid >> 5, lane = tid & 31;
    const int wm = wid & 3;
    const int wn = wid >> 2;

    const int NC = D / 64;
    const size_t rowstride = (size_t)D * 2;

    const int l_kk = tid & 7;
    const int l_r0 = tid >> 3;
    auto load_chunk = [&](int c) {
        const char* Esrc = (const char*)g_Eh;
        uint32_t sb = base + (uint32_t)(c % GSTAGES) * STAGE_BYTES;
        const char* ga = Esrc + (size_t)(bi * 128) * rowstride + (size_t)c * 128 + l_kk * 16;
        const char* gb = Esrc + (size_t)(bj * 128) * rowstride + (size_t)c * 128 + l_kk * 16;
#pragma unroll
        for (int i = 0; i < 4; i++) {
            int r = l_r0 + i * 32;
            uint32_t sw = (uint32_t)(r * 128) + (uint32_t)((l_kk * 16) ^ ((r & 7) << 4));
            cp_async16(sb + sw, ga + (size_t)r * rowstride);
            cp_async16(sb + A_BYTES + sw, gb + (size_t)r * rowstride);
        }
        CP_ASYNC_COMMIT();
    };

    // Per-row / per-col metadata: targets + window bits from poskey.
    if (tid < 128) {
        s_tr[tid] = (unsigned)target[bi * 128 + tid];
        u64 pk = g_poskey[bi * 128 + tid];
        s_dr[tid] = (pk == 0ULL) ? 0xFFFFFFFFu : (unsigned)(pk >> 13);
    } else {
        int t2 = tid - 128;
        s_tc[t2] = (unsigned)target[bj * 128 + t2];
        u64 pk = g_poskey[bj * 128 + t2];
        s_dc[t2] = (pk == 0ULL) ? 0xFFFFFFFFu : (unsigned)(pk >> 13);
    }

    uint32_t a_row[2], a_xor[2];
#pragma unroll
    for (int mt = 0; mt < 2; mt++) {
        int r = wm * 32 + mt * 16 + (lane & 15);
        a_row[mt] = (uint32_t)(r * 128);
        a_xor[mt] = (uint32_t)((r & 7) << 4);
    }
    const uint32_t a_cb = (uint32_t)((lane >> 4) * 16);
    uint32_t b_row[4], b_xor[4];
#pragma unroll
    for (int g = 0; g < 4; g++) {
        int r = wn * 64 + g * 16 + (lane & 7) + ((lane >> 4) & 1) * 8;
        b_row[g] = (uint32_t)(r * 128);
        b_xor[g] = (uint32_t)((r & 7) << 4);
    }
    const uint32_t b_cb = (uint32_t)(((lane >> 3) & 1) * 16);

    float acc[2][8][4];
#pragma unroll
    for (int mt = 0; mt < 2; mt++)
#pragma unroll
        for (int nt = 0; nt < 8; nt++)
#pragma unroll
            for (int x = 0; x < 4; x++) acc[mt][nt][x] = 0.0f;

    load_chunk(0);
    load_chunk(1);

    for (int c = 0; c < NC; c++) {
        CP_ASYNC_WAIT1();
        __syncthreads();
        if (c + 2 < NC) load_chunk(c + 2);

        uint32_t sA = base + (uint32_t)(c % GSTAGES) * STAGE_BYTES;
        uint32_t sB = sA + A_BYTES;

#pragma unroll
        for (int ks = 0; ks < 4; ks++) {
            uint32_t kb = (uint32_t)(ks * 32);
            uint32_t af[2][4];
#pragma unroll
            for (int mt = 0; mt < 2; mt++) {
                uint32_t addr = sA + a_row[mt] + ((kb + a_cb) ^ a_xor[mt]);
                ldmatrix_x4(af[mt][0], af[mt][1], af[mt][2], af[mt][3], addr);
            }
            uint32_t bfr[4][4];
#pragma unroll
            for (int g = 0; g < 4; g++) {
                uint32_t addr = sB + b_row[g] + ((kb + b_cb) ^ b_xor[g]);
                ldmatrix_x4(bfr[g][0], bfr[g][1], bfr[g][2], bfr[g][3], addr);
            }
#pragma unroll
            for (int mt = 0; mt < 2; mt++)
#pragma unroll
                for (int g = 0; g < 4; g++) {
                    mma_f16(acc[mt][g * 2][0], acc[mt][g * 2][1], acc[mt][g * 2][2], acc[mt][g * 2][3],
                            af[mt][0], af[mt][1], af[mt][2], af[mt][3], bfr[g][0], bfr[g][1]);
                    mma_f16(acc[mt][g * 2 + 1][0], acc[mt][g * 2 + 1][1], acc[mt][g * 2 + 1][2], acc[mt][g * 2 + 1][3],
                            af[mt][0], af[mt][1], af[mt][2], af[mt][3], bfr[g][2], bfr[g][3]);
                }
        }
    }

    // ---- Epilogue: dot -> d^2 in place, then fused keyed reductions. ----
    const int qr = lane >> 2;
    const int qc = (lane & 3) * 2;

    float sr[2][2];
#pragma unroll
    for (int mt = 0; mt < 2; mt++) {
        int r0 = bi * 128 + wm * 32 + mt * 16 + qr;
        sr[mt][0] = g_sq[r0];
        sr[mt][1] = g_sq[r0 + 8];
    }
#pragma unroll
    for (int mt = 0; mt < 2; mt++) {
#pragma unroll
        for (int nt = 0; nt < 8; nt++) {
            int gc = bj * 128 + wn * 64 + nt * 8 + qc;
            float sn0 = g_sq[gc], sn1 = g_sq[gc + 1];
            acc[mt][nt][0] = clean_d2(sr[mt][0] + sn0 - 2.0f * acc[mt][nt][0]);
            acc[mt][nt][1] = clean_d2(sr[mt][0] + sn1 - 2.0f * acc[mt][nt][1]);
            acc[mt][nt][2] = clean_d2(sr[mt][1] + sn0 - 2.0f * acc[mt][nt][2]);
            acc[mt][nt][3] = clean_d2(sr[mt][1] + sn1 - 2.0f * acc[mt][nt][3]);
        }
    }
    __syncthreads();   // s_tr/s_tc/s_dr/s_dc visible

    // Row side: anchors = bi-block rows; candidates = bj-block cols (j asc).
#pragma unroll
    for (int mt = 0; mt < 2; mt++) {
#pragma unroll
        for (int h = 0; h < 2; h++) {
            int rloc = wm * 32 + mt * 16 + qr + h * 8;
            unsigned tr = s_tr[rloc], dw = s_dr[rloc];
            unsigned bn = 0xFFFFFFFFu, bw = 0xFFFFFFFFu;
            int jn = 8191, jw = 8191;
#pragma unroll
            for (int nt = 0; nt < 8; nt++) {
#pragma unroll
                for (int b = 0; b < 2; b++) {
                    int cloc = wn * 64 + nt * 8 + qc + b;
                    if (s_tc[cloc] != tr) {
                        unsigned bits = __float_as_uint(acc[mt][nt][h * 2 + b]);
                        if (bits < bn) { bn = bits; jn = bj * 128 + cloc; }
                        if (bits > dw && bits < bw) { bw = bits; jw = bj * 128 + cloc; }
                    }
                }
            }
            u64 kn = ((u64)bn << 13) | (unsigned)jn;
            u64 kw = ((u64)bw << 13) | (unsigned)jw;
            kn = umin64(kn, __shfl_xor_sync(0xffffffffu, kn, 1));
            kn = umin64(kn, __shfl_xor_sync(0xffffffffu, kn, 2));
            kw = umin64(kw, __shfl_xor_sync(0xffffffffu, kw, 1));
            kw = umin64(kw, __shfl_xor_sync(0xffffffffu, kw, 2));
            if ((lane & 3) == 0) {
                if (kn != NOKEY64) atomicMin(&g_negkey[bi * 128 + rloc], kn);
                if (kw != NOKEY64) atomicMin(&g_winkey[bi * 128 + rloc], kw);
            }
        }
    }

    // Col side (mirror): skip on diagonal tiles (symmetric => duplicate info).
    if (bi != bj) {
#pragma unroll
        for (int nt = 0; nt < 8; nt++) {
#pragma unroll
            for (int b = 0; b < 2; b++) {
                int cloc = wn * 64 + nt * 8 + qc + b;
                unsigned tc = s_tc[cloc], dw = s_dc[cloc];
                unsigned bn = 0xFFFFFFFFu, bw = 0xFFFFFFFFu;
                int jn = 8191, jw = 8191;
#pragma unroll
                for (int mt = 0; mt < 2; mt++) {
#pragma unroll
                    for (int h = 0; h < 2; h++) {   // rloc ascending: +0,+8,+16,+24
                        int rloc = wm * 32 + mt * 16 + qr + h * 8;
                        if (s_tr[rloc] != tc) {
                            unsigned bits = __float_as_uint(acc[mt][nt][h * 2 + b]);
                            if (bits < bn) { bn = bits; jn = bi * 128 + rloc; }
                            if (bits > dw && bits < bw) { bw = bits; jw = bi * 128 + rloc; }
                        }
                    }
                }
                u64 kn = ((u64)bn << 13) | (unsigned)jn;
                u64 kw = ((u64)bw << 13) | (unsigned)jw;
                kn = umin64(kn, __shfl_xor_sync(0xffffffffu, kn, 4));
                kn = umin64(kn, __shfl_xor_sync(0xffffffffu, kn, 8));
                kn = umin64(kn, __shfl_xor_sync(0xffffffffu, kn, 16));
                kw = umin64(kw, __shfl_xor_sync(0xffffffffu, kw, 4));
                kw = umin64(kw, __shfl_xor_sync(0xffffffffu, kw, 8));
                kw = umin64(kw, __shfl_xor_sync(0xffffffffu, kw, 16));
                if (qr == 0) {
                    if (kn != NOKEY64) atomicMin(&g_negkey[bj * 128 + cloc], kn);
                    if (kw != NOKEY64) atomicMin(&g_winkey[bj * 128 + cloc], kw);
                }
            }
        }
    }
}

// ===========================================================================
// Loss: per-anchor, decode keys (exact fp32 d^2 in the bits), apply torch
// eps correction, relu, mean via atomicAdd.
// ===========================================================================
__global__ void __launch_bounds__(256) loss_kernel(int N, int D, float* __restrict__ out) {
    int i = blockIdx.x * blockDim.x + threadIdx.x;
    if (i >= N) return;
    u64 posk = g_poskey[i];
    u64 negk = g_negkey[i];
    u64 wink = g_winkey[i];

    int p;
    float d2p;
    if (posk != 0ULL) {
        p = 8191 - (int)(posk & 8191ULL);
        d2p = __uint_as_float((unsigned)(posk >> 13));
    } else {
        // No positive (singleton class): reference argmax picks index 0.
        p = 0;
        const __half* a = g_Eh + (size_t)i * D;
        const __half* b = g_Eh;
        float dot = 0.0f;
        for (int k = 0; k < D; k++)
            dot = fmaf(__half2float(a[k]), __half2float(b[k]), dot);
        d2p = clean_d2(g_sq[i] + g_sq[0] - 2.0f * dot);
    }

    float dpv = sqrtf(d2p);
    float hi2 = (dpv + MARGIN) * (dpv + MARGIN);
    int neg;
    float d2n;
    // Window valid only if a positive existed (else winkey stayed untouched
    // or compares against the disabled 0xFFFFFFFF bound -> empty).
    if (posk != 0ULL && wink != ~0ULL && wink != NOKEY64 &&
        __uint_as_float((unsigned)(wink >> 13)) < hi2) {
        neg = (int)(wink & 8191ULL);
        d2n = __uint_as_float((unsigned)(wink >> 13));
    } else if (negk != ~0ULL && negk != NOKEY64) {
        neg = (int)(negk & 8191ULL);
        d2n = __uint_as_float((unsigned)(negk >> 13));
    } else {
        neg = 0;
        d2n = 0.0f;
    }

    float si = g_s[i];
    float epsC = (float)D * EPS * EPS;
    float dp = sqrtf(fmaxf(d2p + 2.0f * EPS * (si - g_s[p]) + epsC, 0.0f));
    float dn = sqrtf(fmaxf(d2n + 2.0f * EPS * (si - g_s[neg]) + epsC, 0.0f));
    float term = fmaxf(dp - dn + MARGIN, 0.0f);
    atomicAdd(out, term / (float)N);
}

// ---------------------------------------------------------------------------
extern "C" void kernel_launch(void* const* d_in, const int* in_sizes, int n_in,
                              void* d_out, int out_size) {
    const float* E = (const float*)d_in[0];   // embeddings [N, D] fp32
    const int* target = (const int*)d_in[1];  // [N] int32
    float* out = (float*)d_out;

    int N = in_sizes[1];
    int D = in_sizes[0] / N;

    prep_kernel<<<N, 256>>>(E, N, D, out);
    classlist_kernel<<<(N + 255) / 256, 256>>>(target, N);

    cudaFuncSetAttribute(pos_gram_kernel, cudaFuncAttributeMaxDynamicSharedMemorySize, POS_SMEM);
    pos_gram_kernel<<<NCLS, 256, POS_SMEM>>>(N, D);

    cudaFuncSetAttribute(gram_mma_kernel, cudaFuncAttributeMaxDynamicSharedMemorySize, GRAM_SMEM);
    int nt = N / 128;
    int ntri = nt * (nt + 1) / 2;             // 2080 triangular tile pairs
    gram_mma_kernel<<<ntri, 256, GRAM_SMEM>>>(target, N, D);

    loss_kernel<<<(N + 255) / 256, 256>>>(N, D, out);
}

// round 16
// speedup vs baseline: 2.5973x; 1.0454x over previous
#include <cuda_runtime.h>
#include <cuda_fp16.h>
#include <cstdint>

// Problem constants (fixed shapes per reference: N=8192, D=1024, 128 classes)
#define NMAX 8192
#define DMAX 1024
#define MARGIN 1.0f
#define EPS 1e-6f
#define NCLS 128
#define CAP 256          /* max members per class (mean 64; huge safety margin) */

typedef unsigned long long u64;
#define NOKEY64 ((((u64)0xFFFFFFFFu) << 13) | 8191ULL)   /* no-candidate sentinel */

// Scratch (static __device__ arrays; no allocation). No big G matrix.
__device__ float g_sq[NMAX];                         // ||e_i||^2 (fp32)
__device__ float g_s[NMAX];                          // sum_k e_ik
__device__ __half g_Eh[(size_t)NMAX * DMAX];         // fp16 embeddings
__device__ int g_cls[NCLS * CAP];                    // class member lists
__device__ int g_ccnt[NCLS];                         // class member counts
__device__ int g_posdone;                            // pos-CTA completion counter
// Keyed results: key = (d2_fp32_bits << 13) | j   (j fits in 13 bits, N=8192)
__device__ u64 g_poskey[NMAX];   // max over positives; index stored as 8191-j
__device__ u64 g_negkey[NMAX];   // min over all negatives
__device__ u64 g_winkey[NMAX];   // min over negatives with d2 > dp2

// ===========================================================================
// Helpers
// ===========================================================================
__device__ __forceinline__ uint32_t smem_to_u32(const void* p) {
    uint32_t a;
    asm("{ .reg .u64 t; cvta.to.shared.u64 t, %1; cvt.u32.u64 %0, t; }" : "=r"(a) : "l"(p));
    return a;
}
__device__ __forceinline__ void cp_async16(uint32_t smem_dst, const void* gsrc) {
    asm volatile("cp.async.cg.shared.global [%0], [%1], 16;\n" :: "r"(smem_dst), "l"(gsrc));
}
#define CP_ASYNC_COMMIT() asm volatile("cp.async.commit_group;\n" ::: "memory")
#define CP_ASYNC_WAIT1()  asm volatile("cp.async.wait_group 1;\n" ::: "memory")

__device__ __forceinline__ void ldmatrix_x4(uint32_t& r0, uint32_t& r1, uint32_t& r2, uint32_t& r3,
                                            uint32_t addr) {
    asm volatile("ldmatrix.sync.aligned.m8n8.x4.shared.b16 {%0,%1,%2,%3}, [%4];"
                 : "=r"(r0), "=r"(r1), "=r"(r2), "=r"(r3) : "r"(addr));
}
__device__ __forceinline__ void mma_f16(float& c0, float& c1, float& c2, float& c3,
                                        uint32_t a0, uint32_t a1, uint32_t a2, uint32_t a3,
                                        uint32_t b0, uint32_t b1) {
    asm volatile("mma.sync.aligned.m16n8k16.row.col.f32.f16.f16.f32 "
                 "{%0,%1,%2,%3}, {%4,%5,%6,%7}, {%8,%9}, {%0,%1,%2,%3};"
                 : "+f"(c0), "+f"(c1), "+f"(c2), "+f"(c3)
                 : "r"(a0), "r"(a1), "r"(a2), "r"(a3), "r"(b0), "r"(b1));
}
// Clamp to >= 0; clears any -0.0 so bit patterns are monotonic as unsigned.
__device__ __forceinline__ float clean_d2(float x) {
    return __uint_as_float(__float_as_uint(fmaxf(x, 0.0f)) & 0x7fffffffu);
}
__device__ __forceinline__ u64 umin64(u64 a, u64 b) { return a < b ? a : b; }
__device__ __forceinline__ u64 umax64(u64 a, u64 b) { return a > b ? a : b; }

// ===========================================================================
// Prep: fp32 -> fp16 convert, row stats, key/counter init.
// 4 rows per block, 64 threads per row, 4 float4 loads per thread (MLP=4).
// ===========================================================================
__global__ void __launch_bounds__(256) prep_kernel(const float* __restrict__ E,
                                                   int N, int D,
                                                   float* __restrict__ out) {
    int tid = threadIdx.x;
    int rloc = tid >> 6;              // 0..3 row within block
    int c = tid & 63;                 // lane within row
    int i = blockIdx.x * 4 + rloc;

    if (blockIdx.x == 0) {
        if (tid == 0) { out[0] = 0.0f; g_posdone = 0; }
        if (tid < NCLS) g_ccnt[tid] = 0;
    }
    if (c == 0) {
        g_negkey[i] = ~0ULL;
        g_winkey[i] = ~0ULL;
        g_poskey[i] = 0ULL;
    }

    const float4* row = (const float4*)(E + (size_t)i * D);
    float a = 0.0f, b = 0.0f;
    for (int k = c; k < D / 4; k += 64) {
        float4 v = row[k];
        a = fmaf(v.x, v.x, a); a = fmaf(v.y, v.y, a);
        a = fmaf(v.z, v.z, a); a = fmaf(v.w, v.w, a);
        b += v.x + v.y + v.z + v.w;
        __half2 h01 = __floats2half2_rn(v.x, v.y);
        __half2 h23 = __floats2half2_rn(v.z, v.w);
        uint2 hv;
        hv.x = *(const uint32_t*)&h01;
        hv.y = *(const uint32_t*)&h23;
        ((uint2*)g_Eh)[i * (D / 4) + k] = hv;
    }
#pragma unroll
    for (int off = 16; off > 0; off >>= 1) {
        a += __shfl_down_sync(0xffffffffu, a, off);
        b += __shfl_down_sync(0xffffffffu, b, off);
    }
    __shared__ float sa[8], sb[8];
    int w = tid >> 5;
    if ((tid & 31) == 0) { sa[w] = a; sb[w] = b; }
    __syncthreads();
    if (c == 0) {
        g_sq[i] = sa[2 * rloc] + sa[2 * rloc + 1];
        g_s[i] = sb[2 * rloc] + sb[2 * rloc + 1];
    }
}

// Class list build (after prep zeroed the counters). Slot order is arbitrary;
// consumers use order-independent keyed max/min -> deterministic results.
__global__ void __launch_bounds__(256) classlist_kernel(const int* __restrict__ target, int N) {
    int j = blockIdx.x * blockDim.x + threadIdx.x;
    if (j < N) {
        int c = target[j];
        int slot = atomicAdd(&g_ccnt[c], 1);
        if (slot < CAP) g_cls[c * CAP + slot] = j;
    }
}

// ===========================================================================
// FUSED kernel: grid = NCLS + ntri.
//  - bid < NCLS: positive gram for class bid (gathered 128x128 HMMA, B==A).
//    Signals completion via g_posdone (release: fence + bar + atomicAdd).
//    These CTAs are in wave 1 (CLC places bids in order), so gram CTAs'
//    spin-wait cannot deadlock.
//  - bid >= NCLS: negative gram tile (triangular index). Mainloop does NOT
//    depend on poskey; the epilogue spins on g_posdone (acquire) before
//    reading window bounds via __ldcg (L2, no stale L1).
// ===========================================================================
#define GSTAGES 3
#define A_BYTES (128 * 128)
#define B_BYTES (128 * 128)
#define STAGE_BYTES (A_BYTES + B_BYTES)
#define GRAM_SMEM (GSTAGES * STAGE_BYTES + 1024)
#define PSTAGES 3
#define P_BYTES (128 * 128)

__global__ void __launch_bounds__(256) fused_gram_kernel(const int* __restrict__ target,
                                                         int N, int D) {
    extern __shared__ char dsmem[];
    uint32_t base = (smem_to_u32(dsmem) + 1023u) & ~1023u;

    const int tid = threadIdx.x;
    const int wid = tid >> 5, lane = tid & 31;
    const size_t rowstride = (size_t)D * 2;
    const int l_kk = tid & 7;
    const int l_r0 = tid >> 3;
    const int qr = lane >> 2;
    const int qc = (lane & 3) * 2;

    // Common fragment address components (within-tile, pre-swizzle).
    const int wm = wid & 3;
    const int wn = wid >> 2;
    uint32_t a_row[2], a_xor[2];
#pragma unroll
    for (int mt = 0; mt < 2; mt++) {
        int r = wm * 32 + mt * 16 + (lane & 15);
        a_row[mt] = (uint32_t)(r * 128);
        a_xor[mt] = (uint32_t)((r & 7) << 4);
    }
    const uint32_t a_cb = (uint32_t)((lane >> 4) * 16);
    uint32_t b_row[4], b_xor[4];
#pragma unroll
    for (int g = 0; g < 4; g++) {
        int r = wn * 64 + g * 16 + (lane & 7) + ((lane >> 4) & 1) * 8;
        b_row[g] = (uint32_t)(r * 128);
        b_xor[g] = (uint32_t)((r & 7) << 4);
    }
    const uint32_t b_cb = (uint32_t)(((lane >> 3) & 1) * 16);

    float acc[2][8][4];
#pragma unroll
    for (int mt = 0; mt < 2; mt++)
#pragma unroll
        for (int nt = 0; nt < 8; nt++)
#pragma unroll
            for (int x = 0; x < 4; x++) acc[mt][nt][x] = 0.0f;

    const int NC = D / 64;

    if (blockIdx.x < NCLS) {
        // ================== POSITIVE GRAM (class = blockIdx.x) ==================
        int c = blockIdx.x;
        __shared__ int midx[128];
        __shared__ float msq[128];
        int cnt = g_ccnt[c];
        if (cnt > 128) cnt = 128;
        if (cnt == 0) {
            if (tid == 0) atomicAdd(&g_posdone, 1);
            return;
        }
        if (tid < 128) {
            int m = g_cls[c * CAP + ((tid < cnt) ? tid : 0)];  // pad with member 0
            midx[tid] = m;
            msq[tid] = g_sq[m];
        }
        __syncthreads();

        auto load_chunk = [&](int ch) {
            uint32_t sb = base + (uint32_t)(ch % PSTAGES) * P_BYTES;
#pragma unroll
            for (int i = 0; i < 4; i++) {
                int r = l_r0 + i * 32;
                const char* g = (const char*)g_Eh + (size_t)midx[r] * rowstride + (size_t)ch * 128 + l_kk * 16;
                uint32_t sw = (uint32_t)(r * 128) + (uint32_t)((l_kk * 16) ^ ((r & 7) << 4));
                cp_async16(sb + sw, g);
            }
            CP_ASYNC_COMMIT();
        };

        load_chunk(0);
        load_chunk(1);
        for (int ch = 0; ch < NC; ch++) {
            CP_ASYNC_WAIT1();
            __syncthreads();
            if (ch + 2 < NC) load_chunk(ch + 2);
            uint32_t sA = base + (uint32_t)(ch % PSTAGES) * P_BYTES;
#pragma unroll
            for (int ks = 0; ks < 4; ks++) {
                uint32_t kb = (uint32_t)(ks * 32);
                uint32_t af[2][4];
#pragma unroll
                for (int mt = 0; mt < 2; mt++) {
                    uint32_t addr = sA + a_row[mt] + ((kb + a_cb) ^ a_xor[mt]);
                    ldmatrix_x4(af[mt][0], af[mt][1], af[mt][2], af[mt][3], addr);
                }
                uint32_t bfr[4][4];
#pragma unroll
                for (int g = 0; g < 4; g++) {
                    uint32_t addr = sA + b_row[g] + ((kb + b_cb) ^ b_xor[g]);
                    ldmatrix_x4(bfr[g][0], bfr[g][1], bfr[g][2], bfr[g][3], addr);
                }
#pragma unroll
                for (int mt = 0; mt < 2; mt++)
#pragma unroll
                    for (int g = 0; g < 4; g++) {
                        mma_f16(acc[mt][g * 2][0], acc[mt][g * 2][1], acc[mt][g * 2][2], acc[mt][g * 2][3],
                                af[mt][0], af[mt][1], af[mt][2], af[mt][3], bfr[g][0], bfr[g][1]);
                        mma_f16(acc[mt][g * 2 + 1][0], acc[mt][g * 2 + 1][1], acc[mt][g * 2 + 1][2], acc[mt][g * 2 + 1][3],
                                af[mt][0], af[mt][1], af[mt][2], af[mt][3], bfr[g][2], bfr[g][3]);
                    }
            }
        }

        // Epilogue: hardest positive per row (max d2, min index).
#pragma unroll
        for (int mt = 0; mt < 2; mt++) {
#pragma unroll
            for (int h = 0; h < 2; h++) {
                int rloc = wm * 32 + mt * 16 + qr + h * 8;
                float sa = msq[rloc];
                u64 kmax = 0ULL;
#pragma unroll
                for (int nt = 0; nt < 8; nt++) {
#pragma unroll
                    for (int b = 0; b < 2; b++) {
                        int cloc = wn * 64 + nt * 8 + qc + b;
                        int x = h * 2 + b;
                        if (cloc < cnt && cloc != rloc) {
                            float d2 = clean_d2(sa + msq[cloc] - 2.0f * acc[mt][nt][x]);
                            int jb = midx[cloc];
                            u64 key = ((u64)__float_as_uint(d2) << 13) | (u64)(8191 - jb);
                            kmax = umax64(kmax, key);
                        }
                    }
                }
                kmax = umax64(kmax, __shfl_xor_sync(0xffffffffu, kmax, 1));
                kmax = umax64(kmax, __shfl_xor_sync(0xffffffffu, kmax, 2));
                if ((lane & 3) == 0 && rloc < cnt && kmax != 0ULL)
                    atomicMax(&g_poskey[midx[rloc]], kmax);
            }
        }
        // Release: all threads' atomics ordered before the counter bump.
        __threadfence();
        __syncthreads();
        if (tid == 0) atomicAdd(&g_posdone, 1);
        return;
    }

    // ==================== NEGATIVE GRAM (triangular tile) ====================
    unsigned idx = blockIdx.x - NCLS;
    int bi = (int)((sqrt(8.0 * (double)idx + 1.0) - 1.0) * 0.5);
    while ((size_t)(bi + 1) * (bi + 2) / 2 <= idx) bi++;
    while ((size_t)bi * (bi + 1) / 2 > idx) bi--;
    int bj = (int)(idx - (size_t)bi * (bi + 1) / 2);

    __shared__ unsigned s_tr[128], s_tc[128], s_dr[128], s_dc[128];

    auto load_chunk = [&](int c) {
        const char* Esrc = (const char*)g_Eh;
        uint32_t sb = base + (uint32_t)(c % GSTAGES) * STAGE_BYTES;
        const char* ga = Esrc + (size_t)(bi * 128) * rowstride + (size_t)c * 128 + l_kk * 16;
        const char* gb = Esrc + (size_t)(bj * 128) * rowstride + (size_t)c * 128 + l_kk * 16;
#pragma unroll
        for (int i = 0; i < 4; i++) {
            int r = l_r0 + i * 32;
            uint32_t sw = (uint32_t)(r * 128) + (uint32_t)((l_kk * 16) ^ ((r & 7) << 4));
            cp_async16(sb + sw, ga + (size_t)r * rowstride);
            cp_async16(sb + A_BYTES + sw, gb + (size_t)r * rowstride);
        }
        CP_ASYNC_COMMIT();
    };

    // Targets (no pos dependency) loaded up front.
    if (tid < 128) s_tr[tid] = (unsigned)target[bi * 128 + tid];
    else           s_tc[tid - 128] = (unsigned)target[bj * 128 + tid - 128];

    load_chunk(0);
    load_chunk(1);

    for (int c = 0; c < NC; c++) {
        CP_ASYNC_WAIT1();
        __syncthreads();
        if (c + 2 < NC) load_chunk(c + 2);

        uint32_t sA = base + (uint32_t)(c % GSTAGES) * STAGE_BYTES;
        uint32_t sB = sA + A_BYTES;

#pragma unroll
        for (int ks = 0; ks < 4; ks++) {
            uint32_t kb = (uint32_t)(ks * 32);
            uint32_t af[2][4];
#pragma unroll
            for (int mt = 0; mt < 2; mt++) {
                uint32_t addr = sA + a_row[mt] + ((kb + a_cb) ^ a_xor[mt]);
                ldmatrix_x4(af[mt][0], af[mt][1], af[mt][2], af[mt][3], addr);
            }
            uint32_t bfr[4][4];
#pragma unroll
            for (int g = 0; g < 4; g++) {
                uint32_t addr = sB + b_row[g] + ((kb + b_cb) ^ b_xor[g]);
                ldmatrix_x4(bfr[g][0], bfr[g][1], bfr[g][2], bfr[g][3], addr);
            }
#pragma unroll
            for (int mt = 0; mt < 2; mt++)
#pragma unroll
                for (int g = 0; g < 4; g++) {
                    mma_f16(acc[mt][g * 2][0], acc[mt][g * 2][1], acc[mt][g * 2][2], acc[mt][g * 2][3],
                            af[mt][0], af[mt][1], af[mt][2], af[mt][3], bfr[g][0], bfr[g][1]);
                    mma_f16(acc[mt][g * 2 + 1][0], acc[mt][g * 2 + 1][1], acc[mt][g * 2 + 1][2], acc[mt][g * 2 + 1][3],
                            af[mt][0], af[mt][1], af[mt][2], af[mt][3], bfr[g][2], bfr[g][3]);
                }
        }
    }

    // ---- dot -> d^2 in place.
    float sr[2][2];
#pragma unroll
    for (int mt = 0; mt < 2; mt++) {
        int r0 = bi * 128 + wm * 32 + mt * 16 + qr;
        sr[mt][0] = g_sq[r0];
        sr[mt][1] = g_sq[r0 + 8];
    }
#pragma unroll
    for (int mt = 0; mt < 2; mt++) {
#pragma unroll
        for (int nt = 0; nt < 8; nt++) {
            int gc = bj * 128 + wn * 64 + nt * 8 + qc;
            float sn0 = g_sq[gc], sn1 = g_sq[gc + 1];
            acc[mt][nt][0] = clean_d2(sr[mt][0] + sn0 - 2.0f * acc[mt][nt][0]);
            acc[mt][nt][1] = clean_d2(sr[mt][0] + sn1 - 2.0f * acc[mt][nt][1]);
            acc[mt][nt][2] = clean_d2(sr[mt][1] + sn0 - 2.0f * acc[mt][nt][2]);
            acc[mt][nt][3] = clean_d2(sr[mt][1] + sn1 - 2.0f * acc[mt][nt][3]);
        }
    }

    // ---- Acquire pos results, then load window bounds (L2, fresh).
    if (tid == 0) {
        while (*((volatile int*)&g_posdone) < NCLS) { }
        __threadfence();
    }
    __syncthreads();
    if (tid < 128) {
        u64 pk = __ldcg(&g_poskey[bi * 128 + tid]);
        s_dr[tid] = (pk == 0ULL) ? 0xFFFFFFFFu : (unsigned)(pk >> 13);
    } else {
        u64 pk = __ldcg(&g_poskey[bj * 128 + tid - 128]);
        s_dc[tid - 128] = (pk == 0ULL) ? 0xFFFFFFFFu : (unsigned)(pk >> 13);
    }
    __syncthreads();

    // Row side: anchors = bi-block rows; candidates = bj-block cols (j asc).
#pragma unroll
    for (int mt = 0; mt < 2; mt++) {
#pragma unroll
        for (int h = 0; h < 2; h++) {
            int rloc = wm * 32 + mt * 16 + qr + h * 8;
            unsigned tr = s_tr[rloc], dw = s_dr[rloc];
            unsigned bn = 0xFFFFFFFFu, bw = 0xFFFFFFFFu;
            int jn = 8191, jw = 8191;
#pragma unroll
            for (int nt = 0; nt < 8; nt++) {
#pragma unroll
                for (int b = 0; b < 2; b++) {
                    int cloc = wn * 64 + nt * 8 + qc + b;
                    if (s_tc[cloc] != tr) {
                        unsigned bits = __float_as_uint(acc[mt][nt][h * 2 + b]);
                        if (bits < bn) { bn = bits; jn = bj * 128 + cloc; }
                        if (bits > dw && bits < bw) { bw = bits; jw = bj * 128 + cloc; }
                    }
                }
            }
            u64 kn = ((u64)bn << 13) | (unsigned)jn;
            u64 kw = ((u64)bw << 13) | (unsigned)jw;
            kn = umin64(kn, __shfl_xor_sync(0xffffffffu, kn, 1));
            kn = umin64(kn, __shfl_xor_sync(0xffffffffu, kn, 2));
            kw = umin64(kw, __shfl_xor_sync(0xffffffffu, kw, 1));
            kw = umin64(kw, __shfl_xor_sync(0xffffffffu, kw, 2));
            if ((lane & 3) == 0) {
                if (kn != NOKEY64) atomicMin(&g_negkey[bi * 128 + rloc], kn);
                if (kw != NOKEY64) atomicMin(&g_winkey[bi * 128 + rloc], kw);
            }
        }
    }

    // Col side (mirror): skip on diagonal tiles (symmetric => duplicate info).
    if (bi != bj) {
#pragma unroll
        for (int nt = 0; nt < 8; nt++) {
#pragma unroll
            for (int b = 0; b < 2; b++) {
                int cloc = wn * 64 + nt * 8 + qc + b;
                unsigned tc = s_tc[cloc], dw = s_dc[cloc];
                unsigned bn = 0xFFFFFFFFu, bw = 0xFFFFFFFFu;
                int jn = 8191, jw = 8191;
#pragma unroll
                for (int mt = 0; mt < 2; mt++) {
#pragma unroll
                    for (int h = 0; h < 2; h++) {   // rloc ascending: +0,+8,+16,+24
                        int rloc = wm * 32 + mt * 16 + qr + h * 8;
                        if (s_tr[rloc] != tc) {
                            unsigned bits = __float_as_uint(acc[mt][nt][h * 2 + b]);
                            if (bits < bn) { bn = bits; jn = bi * 128 + rloc; }
                            if (bits > dw && bits < bw) { bw = bits; jw = bi * 128 + rloc; }
                        }
                    }
                }
                u64 kn = ((u64)bn << 13) | (unsigned)jn;
                u64 kw = ((u64)bw << 13) | (unsigned)jw;
                kn = umin64(kn, __shfl_xor_sync(0xffffffffu, kn, 4));
                kn = umin64(kn, __shfl_xor_sync(0xffffffffu, kn, 8));
                kn = umin64(kn, __shfl_xor_sync(0xffffffffu, kn, 16));
                kw = umin64(kw, __shfl_xor_sync(0xffffffffu, kw, 4));
                kw = umin64(kw, __shfl_xor_sync(0xffffffffu, kw, 8));
                kw = umin64(kw, __shfl_xor_sync(0xffffffffu, kw, 16));
                if (qr == 0) {
                    if (kn != NOKEY64) atomicMin(&g_negkey[bj * 128 + cloc], kn);
                    if (kw != NOKEY64) atomicMin(&g_winkey[bj * 128 + cloc], kw);
                }
            }
        }
    }
}

// ===========================================================================
// Loss: per-anchor, decode keys (exact fp32 d^2 in the bits), apply torch
// eps correction, relu, mean via atomicAdd.
// ===========================================================================
__global__ void __launch_bounds__(256) loss_kernel(int N, int D, float* __restrict__ out) {
    int i = blockIdx.x * blockDim.x + threadIdx.x;
    if (i >= N) return;
    u64 posk = g_poskey[i];
    u64 negk = g_negkey[i];
    u64 wink = g_winkey[i];

    int p;
    float d2p;
    if (posk != 0ULL) {
        p = 8191 - (int)(posk & 8191ULL);
        d2p = __uint_as_float((unsigned)(posk >> 13));
    } else {
        // No positive (singleton class): reference argmax picks index 0.
        p = 0;
        const __half* a = g_Eh + (size_t)i * D;
        const __half* b = g_Eh;
        float dot = 0.0f;
        for (int k = 0; k < D; k++)
            dot = fmaf(__half2float(a[k]), __half2float(b[k]), dot);
        d2p = clean_d2(g_sq[i] + g_sq[0] - 2.0f * dot);
    }

    float dpv = sqrtf(d2p);
    float hi2 = (dpv + MARGIN) * (dpv + MARGIN);
    int neg;
    float d2n;
    if (posk != 0ULL && wink != ~0ULL && wink != NOKEY64 &&
        __uint_as_float((unsigned)(wink >> 13)) < hi2) {
        neg = (int)(wink & 8191ULL);
        d2n = __uint_as_float((unsigned)(wink >> 13));
    } else if (negk != ~0ULL && negk != NOKEY64) {
        neg = (int)(negk & 8191ULL);
        d2n = __uint_as_float((unsigned)(negk >> 13));
    } else {
        neg = 0;
        d2n = 0.0f;
    }

    float si = g_s[i];
    float epsC = (float)D * EPS * EPS;
    float dp = sqrtf(fmaxf(d2p + 2.0f * EPS * (si - g_s[p]) + epsC, 0.0f));
    float dn = sqrtf(fmaxf(d2n + 2.0f * EPS * (si - g_s[neg]) + epsC, 0.0f));
    float term = fmaxf(dp - dn + MARGIN, 0.0f);
    atomicAdd(out, term / (float)N);
}

// ---------------------------------------------------------------------------
extern "C" void kernel_launch(void* const* d_in, const int* in_sizes, int n_in,
                              void* d_out, int out_size) {
    const float* E = (const float*)d_in[0];   // embeddings [N, D] fp32
    const int* target = (const int*)d_in[1];  // [N] int32
    float* out = (float*)d_out;

    int N = in_sizes[1];
    int D = in_sizes[0] / N;

    prep_kernel<<<N / 4, 256>>>(E, N, D, out);
    classlist_kernel<<<(N + 255) / 256, 256>>>(target, N);

    cudaFuncSetAttribute(fused_gram_kernel, cudaFuncAttributeMaxDynamicSharedMemorySize, GRAM_SMEM);
    int nt = N / 128;
    int ntri = nt * (nt + 1) / 2;             // 2080 triangular tile pairs
    fused_gram_kernel<<<NCLS + ntri, 256, GRAM_SMEM>>>(target, N, D);

    loss_kernel<<<(N + 255) / 256, 256>>>(N, D, out);
}

// round 17
// speedup vs baseline: 2.7118x; 1.0441x over previous
#include <cuda_runtime.h>
#include <cuda_fp16.h>
#include <cstdint>

// Problem constants (fixed shapes per reference: N=8192, D=1024, 128 classes)
#define NMAX 8192
#define DMAX 1024
#define MARGIN 1.0f
#define EPS 1e-6f
#define NCLS 128
#define CAP 256          /* max members per class (mean 64; huge safety margin) */

typedef unsigned long long u64;
#define NOKEY64 ((((u64)0xFFFFFFFFu) << 13) | 8191ULL)   /* no-candidate sentinel */

// Scratch (static __device__ arrays; no allocation). No big G matrix.
__device__ float g_sq[NMAX];                         // ||e_i||^2 (fp32)
__device__ float g_s[NMAX];                          // sum_k e_ik
__device__ __half g_Eh[(size_t)NMAX * DMAX];         // fp16 embeddings
__device__ int g_cls[NCLS * CAP];                    // class member lists
__device__ int g_ccnt[NCLS];                         // class member counts
__device__ int g_posdone;                            // pos-CTA completion counter
// Keyed results: key = (d2_fp32_bits << 13) | j   (j fits in 13 bits, N=8192)
__device__ u64 g_poskey[NMAX];   // max over positives; index stored as 8191-j
__device__ u64 g_negkey[NMAX];   // min over all negatives
__device__ u64 g_winkey[NMAX];   // min over negatives with d2 > dp2

// ===========================================================================
// Helpers
// ===========================================================================
__device__ __forceinline__ uint32_t smem_to_u32(const void* p) {
    uint32_t a;
    asm("{ .reg .u64 t; cvta.to.shared.u64 t, %1; cvt.u32.u64 %0, t; }" : "=r"(a) : "l"(p));
    return a;
}
__device__ __forceinline__ void cp_async16(uint32_t smem_dst, const void* gsrc) {
    asm volatile("cp.async.cg.shared.global [%0], [%1], 16;\n" :: "r"(smem_dst), "l"(gsrc));
}
#define CP_ASYNC_COMMIT() asm volatile("cp.async.commit_group;\n" ::: "memory")
#define CP_ASYNC_WAIT1()  asm volatile("cp.async.wait_group 1;\n" ::: "memory")

__device__ __forceinline__ void ldmatrix_x4(uint32_t& r0, uint32_t& r1, uint32_t& r2, uint32_t& r3,
                                            uint32_t addr) {
    asm volatile("ldmatrix.sync.aligned.m8n8.x4.shared.b16 {%0,%1,%2,%3}, [%4];"
                 : "=r"(r0), "=r"(r1), "=r"(r2), "=r"(r3) : "r"(addr));
}
__device__ __forceinline__ void mma_f16(float& c0, float& c1, float& c2, float& c3,
                                        uint32_t a0, uint32_t a1, uint32_t a2, uint32_t a3,
                                        uint32_t b0, uint32_t b1) {
    asm volatile("mma.sync.aligned.m16n8k16.row.col.f32.f16.f16.f32 "
                 "{%0,%1,%2,%3}, {%4,%5,%6,%7}, {%8,%9}, {%0,%1,%2,%3};"
                 : "+f"(c0), "+f"(c1), "+f"(c2), "+f"(c3)
                 : "r"(a0), "r"(a1), "r"(a2), "r"(a3), "r"(b0), "r"(b1));
}
// Clamp to >= 0; clears any -0.0 so bit patterns are monotonic as unsigned.
__device__ __forceinline__ float clean_d2(float x) {
    return __uint_as_float(__float_as_uint(fmaxf(x, 0.0f)) & 0x7fffffffu);
}
__device__ __forceinline__ u64 umin64(u64 a, u64 b) { return a < b ? a : b; }
__device__ __forceinline__ u64 umax64(u64 a, u64 b) { return a > b ? a : b; }

// ===========================================================================
// Prep: fp32 -> fp16 convert, row stats, key/counter init.
// 4 rows per block, 64 threads per row, 4 float4 loads per thread (MLP=4).
// ===========================================================================
__global__ void __launch_bounds__(256) prep_kernel(const float* __restrict__ E,
                                                   int N, int D,
                                                   float* __restrict__ out) {
    int tid = threadIdx.x;
    int rloc = tid >> 6;              // 0..3 row within block
    int c = tid & 63;                 // lane within row
    int i = blockIdx.x * 4 + rloc;

    if (blockIdx.x == 0) {
        if (tid == 0) { out[0] = 0.0f; g_posdone = 0; }
        if (tid < NCLS) g_ccnt[tid] = 0;
    }
    if (c == 0) {
        g_negkey[i] = ~0ULL;
        g_winkey[i] = ~0ULL;
        g_poskey[i] = 0ULL;
    }

    const float4* row = (const float4*)(E + (size_t)i * D);
    float a = 0.0f, b = 0.0f;
    for (int k = c; k < D / 4; k += 64) {
        float4 v = row[k];
        a = fmaf(v.x, v.x, a); a = fmaf(v.y, v.y, a);
        a = fmaf(v.z, v.z, a); a = fmaf(v.w, v.w, a);
        b += v.x + v.y + v.z + v.w;
        __half2 h01 = __floats2half2_rn(v.x, v.y);
        __half2 h23 = __floats2half2_rn(v.z, v.w);
        uint2 hv;
        hv.x = *(const uint32_t*)&h01;
        hv.y = *(const uint32_t*)&h23;
        ((uint2*)g_Eh)[i * (D / 4) + k] = hv;
    }
#pragma unroll
    for (int off = 16; off > 0; off >>= 1) {
        a += __shfl_down_sync(0xffffffffu, a, off);
        b += __shfl_down_sync(0xffffffffu, b, off);
    }
    __shared__ float sa[8], sb[8];
    int w = tid >> 5;
    if ((tid & 31) == 0) { sa[w] = a; sb[w] = b; }
    __syncthreads();
    if (c == 0) {
        g_sq[i] = sa[2 * rloc] + sa[2 * rloc + 1];
        g_s[i] = sb[2 * rloc] + sb[2 * rloc + 1];
    }
}

// Class list build (after prep zeroed the counters). Slot order is arbitrary;
// consumers use order-independent keyed max/min -> deterministic results.
__global__ void __launch_bounds__(256) classlist_kernel(const int* __restrict__ target, int N) {
    int j = blockIdx.x * blockDim.x + threadIdx.x;
    if (j < N) {
        int c = target[j];
        int slot = atomicAdd(&g_ccnt[c], 1);
        if (slot < CAP) g_cls[c * CAP + slot] = j;
    }
}

// ===========================================================================
// FUSED kernel: grid = NCLS + ntri.
//  - bid < NCLS: positive gram for class bid (gathered 128x128 HMMA, B==A).
//    Signals completion via g_posdone (release: fence + bar + atomicAdd).
//    These CTAs are in wave 1 (CLC places bids in order), so gram CTAs'
//    spin-wait cannot deadlock.
//  - bid >= NCLS: negative gram tile (triangular index). Mainloop does NOT
//    depend on poskey; the epilogue spins on g_posdone (acquire) before
//    reading window bounds via __ldcg (L2, no stale L1).
// ===========================================================================
#define GSTAGES 3
#define A_BYTES (128 * 128)
#define B_BYTES (128 * 128)
#define STAGE_BYTES (A_BYTES + B_BYTES)
#define GRAM_SMEM (GSTAGES * STAGE_BYTES + 1024)
#define PSTAGES 3
#define P_BYTES (128 * 128)

__global__ void __launch_bounds__(256) fused_gram_kernel(const int* __restrict__ target,
                                                         int N, int D) {
    extern __shared__ char dsmem[];
    uint32_t base = (smem_to_u32(dsmem) + 1023u) & ~1023u;

    const int tid = threadIdx.x;
    const int wid = tid >> 5, lane = tid & 31;
    const size_t rowstride = (size_t)D * 2;
    const int l_kk = tid & 7;
    const int l_r0 = tid >> 3;
    const int qr = lane >> 2;
    const int qc = (lane & 3) * 2;

    // Common fragment address components (within-tile, pre-swizzle).
    const int wm = wid & 3;
    const int wn = wid >> 2;
    uint32_t a_row[2], a_xor[2];
#pragma unroll
    for (int mt = 0; mt < 2; mt++) {
        int r = wm * 32 + mt * 16 + (lane & 15);
        a_row[mt] = (uint32_t)(r * 128);
        a_xor[mt] = (uint32_t)((r & 7) << 4);
    }
    const uint32_t a_cb = (uint32_t)((lane >> 4) * 16);
    uint32_t b_row[4], b_xor[4];
#pragma unroll
    for (int g = 0; g < 4; g++) {
        int r = wn * 64 + g * 16 + (lane & 7) + ((lane >> 4) & 1) * 8;
        b_row[g] = (uint32_t)(r * 128);
        b_xor[g] = (uint32_t)((r & 7) << 4);
    }
    const uint32_t b_cb = (uint32_t)(((lane >> 3) & 1) * 16);

    float acc[2][8][4];
#pragma unroll
    for (int mt = 0; mt < 2; mt++)
#pragma unroll
        for (int nt = 0; nt < 8; nt++)
#pragma unroll
            for (int x = 0; x < 4; x++) acc[mt][nt][x] = 0.0f;

    const int NC = D / 64;

    if (blockIdx.x < NCLS) {
        // ================== POSITIVE GRAM (class = blockIdx.x) ==================
        int c = blockIdx.x;
        __shared__ int midx[128];
        __shared__ float msq[128];
        int cnt = g_ccnt[c];
        if (cnt > 128) cnt = 128;
        if (cnt == 0) {
            if (tid == 0) atomicAdd(&g_posdone, 1);
            return;
        }
        if (tid < 128) {
            int m = g_cls[c * CAP + ((tid < cnt) ? tid : 0)];  // pad with member 0
            midx[tid] = m;
            msq[tid] = g_sq[m];
        }
        __syncthreads();

        auto load_chunk = [&](int ch) {
            uint32_t sb = base + (uint32_t)(ch % PSTAGES) * P_BYTES;
#pragma unroll
            for (int i = 0; i < 4; i++) {
                int r = l_r0 + i * 32;
                const char* g = (const char*)g_Eh + (size_t)midx[r] * rowstride + (size_t)ch * 128 + l_kk * 16;
                uint32_t sw = (uint32_t)(r * 128) + (uint32_t)((l_kk * 16) ^ ((r & 7) << 4));
                cp_async16(sb + sw, g);
            }
            CP_ASYNC_COMMIT();
        };

        load_chunk(0);
        load_chunk(1);
        for (int ch = 0; ch < NC; ch++) {
            CP_ASYNC_WAIT1();
            __syncthreads();
            if (ch + 2 < NC) load_chunk(ch + 2);
            uint32_t sA = base + (uint32_t)(ch % PSTAGES) * P_BYTES;
#pragma unroll
            for (int ks = 0; ks < 4; ks++) {
                uint32_t kb = (uint32_t)(ks * 32);
                uint32_t af[2][4];
#pragma unroll
                for (int mt = 0; mt < 2; mt++) {
                    uint32_t addr = sA + a_row[mt] + ((kb + a_cb) ^ a_xor[mt]);
                    ldmatrix_x4(af[mt][0], af[mt][1], af[mt][2], af[mt][3], addr);
                }
                uint32_t bfr[4][4];
#pragma unroll
                for (int g = 0; g < 4; g++) {
                    uint32_t addr = sA + b_row[g] + ((kb + b_cb) ^ b_xor[g]);
                    ldmatrix_x4(bfr[g][0], bfr[g][1], bfr[g][2], bfr[g][3], addr);
                }
#pragma unroll
                for (int mt = 0; mt < 2; mt++)
#pragma unroll
                    for (int g = 0; g < 4; g++) {
                        mma_f16(acc[mt][g * 2][0], acc[mt][g * 2][1], acc[mt][g * 2][2], acc[mt][g * 2][3],
                                af[mt][0], af[mt][1], af[mt][2], af[mt][3], bfr[g][0], bfr[g][1]);
                        mma_f16(acc[mt][g * 2 + 1][0], acc[mt][g * 2 + 1][1], acc[mt][g * 2 + 1][2], acc[mt][g * 2 + 1][3],
                                af[mt][0], af[mt][1], af[mt][2], af[mt][3], bfr[g][2], bfr[g][3]);
                    }
            }
        }

        // Epilogue: hardest positive per row (max d2, min index).
#pragma unroll
        for (int mt = 0; mt < 2; mt++) {
#pragma unroll
            for (int h = 0; h < 2; h++) {
                int rloc = wm * 32 + mt * 16 + qr + h * 8;
                float sa = msq[rloc];
                u64 kmax = 0ULL;
#pragma unroll
                for (int nt = 0; nt < 8; nt++) {
#pragma unroll
                    for (int b = 0; b < 2; b++) {
                        int cloc = wn * 64 + nt * 8 + qc + b;
                        int x = h * 2 + b;
                        if (cloc < cnt && cloc != rloc) {
                            float d2 = clean_d2(sa + msq[cloc] - 2.0f * acc[mt][nt][x]);
                            int jb = midx[cloc];
                            u64 key = ((u64)__float_as_uint(d2) << 13) | (u64)(8191 - jb);
                            kmax = umax64(kmax, key);
                        }
                    }
                }
                kmax = umax64(kmax, __shfl_xor_sync(0xffffffffu, kmax, 1));
                kmax = umax64(kmax, __shfl_xor_sync(0xffffffffu, kmax, 2));
                if ((lane & 3) == 0 && rloc < cnt && kmax != 0ULL)
                    atomicMax(&g_poskey[midx[rloc]], kmax);
            }
        }
        // Release: all threads' atomics ordered before the counter bump.
        __threadfence();
        __syncthreads();
        if (tid == 0) atomicAdd(&g_posdone, 1);
        return;
    }

    // ==================== NEGATIVE GRAM (triangular tile) ====================
    unsigned idx = blockIdx.x - NCLS;
    int bi = (int)((sqrt(8.0 * (double)idx + 1.0) - 1.0) * 0.5);
    while ((size_t)(bi + 1) * (bi + 2) / 2 <= idx) bi++;
    while ((size_t)bi * (bi + 1) / 2 > idx) bi--;
    int bj = (int)(idx - (size_t)bi * (bi + 1) / 2);

    __shared__ unsigned s_tr[128], s_tc[128], s_dr[128], s_dc[128];

    auto load_chunk = [&](int c) {
        const char* Esrc = (const char*)g_Eh;
        uint32_t sb = base + (uint32_t)(c % GSTAGES) * STAGE_BYTES;
        const char* ga = Esrc + (size_t)(bi * 128) * rowstride + (size_t)c * 128 + l_kk * 16;
        const char* gb = Esrc + (size_t)(bj * 128) * rowstride + (size_t)c * 128 + l_kk * 16;
#pragma unroll
        for (int i = 0; i < 4; i++) {
            int r = l_r0 + i * 32;
            uint32_t sw = (uint32_t)(r * 128) + (uint32_t)((l_kk * 16) ^ ((r & 7) << 4));
            cp_async16(sb + sw, ga + (size_t)r * rowstride);
            cp_async16(sb + A_BYTES + sw, gb + (size_t)r * rowstride);
        }
        CP_ASYNC_COMMIT();
    };

    // Targets (no pos dependency) loaded up front.
    if (tid < 128) s_tr[tid] = (unsigned)target[bi * 128 + tid];
    else           s_tc[tid - 128] = (unsigned)target[bj * 128 + tid - 128];

    load_chunk(0);
    load_chunk(1);

    for (int c = 0; c < NC; c++) {
        CP_ASYNC_WAIT1();
        __syncthreads();
        if (c + 2 < NC) load_chunk(c + 2);

        uint32_t sA = base + (uint32_t)(c % GSTAGES) * STAGE_BYTES;
        uint32_t sB = sA + A_BYTES;

#pragma unroll
        for (int ks = 0; ks < 4; ks++) {
            uint32_t kb = (uint32_t)(ks * 32);
            uint32_t af[2][4];
#pragma unroll
            for (int mt = 0; mt < 2; mt++) {
                uint32_t addr = sA + a_row[mt] + ((kb + a_cb) ^ a_xor[mt]);
                ldmatrix_x4(af[mt][0], af[mt][1], af[mt][2], af[mt][3], addr);
            }
            uint32_t bfr[4][4];
#pragma unroll
            for (int g = 0; g < 4; g++) {
                uint32_t addr = sB + b_row[g] + ((kb + b_cb) ^ b_xor[g]);
                ldmatrix_x4(bfr[g][0], bfr[g][1], bfr[g][2], bfr[g][3], addr);
            }
#pragma unroll
            for (int mt = 0; mt < 2; mt++)
#pragma unroll
                for (int g = 0; g < 4; g++) {
                    mma_f16(acc[mt][g * 2][0], acc[mt][g * 2][1], acc[mt][g * 2][2], acc[mt][g * 2][3],
                            af[mt][0], af[mt][1], af[mt][2], af[mt][3], bfr[g][0], bfr[g][1]);
                    mma_f16(acc[mt][g * 2 + 1][0], acc[mt][g * 2 + 1][1], acc[mt][g * 2 + 1][2], acc[mt][g * 2 + 1][3],
                            af[mt][0], af[mt][1], af[mt][2], af[mt][3], bfr[g][2], bfr[g][3]);
                }
        }
    }

    // ---- dot -> d^2 in place.
    float sr[2][2];
#pragma unroll
    for (int mt = 0; mt < 2; mt++) {
        int r0 = bi * 128 + wm * 32 + mt * 16 + qr;
        sr[mt][0] = g_sq[r0];
        sr[mt][1] = g_sq[r0 + 8];
    }
#pragma unroll
    for (int mt = 0; mt < 2; mt++) {
#pragma unroll
        for (int nt = 0; nt < 8; nt++) {
            int gc = bj * 128 + wn * 64 + nt * 8 + qc;
            float sn0 = g_sq[gc], sn1 = g_sq[gc + 1];
            acc[mt][nt][0] = clean_d2(sr[mt][0] + sn0 - 2.0f * acc[mt][nt][0]);
            acc[mt][nt][1] = clean_d2(sr[mt][0] + sn1 - 2.0f * acc[mt][nt][1]);
            acc[mt][nt][2] = clean_d2(sr[mt][1] + sn0 - 2.0f * acc[mt][nt][2]);
            acc[mt][nt][3] = clean_d2(sr[mt][1] + sn1 - 2.0f * acc[mt][nt][3]);
        }
    }

    // ---- Acquire pos results, then load window bounds (L2, fresh).
    if (tid == 0) {
        while (*((volatile int*)&g_posdone) < NCLS) { }
        __threadfence();
    }
    __syncthreads();
    if (tid < 128) {
        u64 pk = __ldcg(&g_poskey[bi * 128 + tid]);
        s_dr[tid] = (pk == 0ULL) ? 0xFFFFFFFFu : (unsigned)(pk >> 13);
    } else {
        u64 pk = __ldcg(&g_poskey[bj * 128 + tid - 128]);
        s_dc[tid - 128] = (pk == 0ULL) ? 0xFFFFFFFFu : (unsigned)(pk >> 13);
    }
    __syncthreads();

    // Row side: anchors = bi-block rows; candidates = bj-block cols (j asc).
#pragma unroll
    for (int mt = 0; mt < 2; mt++) {
#pragma unroll
        for (int h = 0; h < 2; h++) {
            int rloc = wm * 32 + mt * 16 + qr + h * 8;
            unsigned tr = s_tr[rloc], dw = s_dr[rloc];
            unsigned bn = 0xFFFFFFFFu, bw = 0xFFFFFFFFu;
            int jn = 8191, jw = 8191;
#pragma unroll
            for (int nt = 0; nt < 8; nt++) {
#pragma unroll
                for (int b = 0; b < 2; b++) {
                    int cloc = wn * 64 + nt * 8 + qc + b;
                    if (s_tc[cloc] != tr) {
                        unsigned bits = __float_as_uint(acc[mt][nt][h * 2 + b]);
                        if (bits < bn) { bn = bits; jn = bj * 128 + cloc; }
                        if (bits > dw && bits < bw) { bw = bits; jw = bj * 128 + cloc; }
                    }
                }
            }
            u64 kn = ((u64)bn << 13) | (unsigned)jn;
            u64 kw = ((u64)bw << 13) | (unsigned)jw;
            kn = umin64(kn, __shfl_xor_sync(0xffffffffu, kn, 1));
            kn = umin64(kn, __shfl_xor_sync(0xffffffffu, kn, 2));
            kw = umin64(kw, __shfl_xor_sync(0xffffffffu, kw, 1));
            kw = umin64(kw, __shfl_xor_sync(0xffffffffu, kw, 2));
            if ((lane & 3) == 0) {
                if (kn != NOKEY64) atomicMin(&g_negkey[bi * 128 + rloc], kn);
                if (kw != NOKEY64) atomicMin(&g_winkey[bi * 128 + rloc], kw);
            }
        }
    }

    // Col side (mirror): skip on diagonal tiles (symmetric => duplicate info).
    if (bi != bj) {
#pragma unroll
        for (int nt = 0; nt < 8; nt++) {
#pragma unroll
            for (int b = 0; b < 2; b++) {
                int cloc = wn * 64 + nt * 8 + qc + b;
                unsigned tc = s_tc[cloc], dw = s_dc[cloc];
                unsigned bn = 0xFFFFFFFFu, bw = 0xFFFFFFFFu;
                int jn = 8191, jw = 8191;
#pragma unroll
                for (int mt = 0; mt < 2; mt++) {
#pragma unroll
                    for (int h = 0; h < 2; h++) {   // rloc ascending: +0,+8,+16,+24
                        int rloc = wm * 32 + mt * 16 + qr + h * 8;
                        if (s_tr[rloc] != tc) {
                            unsigned bits = __float_as_uint(acc[mt][nt][h * 2 + b]);
                            if (bits < bn) { bn = bits; jn = bi * 128 + rloc; }
                            if (bits > dw && bits < bw) { bw = bits; jw = bi * 128 + rloc; }
                        }
                    }
                }
                u64 kn = ((u64)bn << 13) | (unsigned)jn;
                u64 kw = ((u64)bw << 13) | (unsigned)jw;
                kn = umin64(kn, __shfl_xor_sync(0xffffffffu, kn, 4));
                kn = umin64(kn, __shfl_xor_sync(0xffffffffu, kn, 8));
                kn = umin64(kn, __shfl_xor_sync(0xffffffffu, kn, 16));
                kw = umin64(kw, __shfl_xor_sync(0xffffffffu, kw, 4));
                kw = umin64(kw, __shfl_xor_sync(0xffffffffu, kw, 8));
                kw = umin64(kw, __shfl_xor_sync(0xffffffffu, kw, 16));
                if (qr == 0) {
                    if (kn != NOKEY64) atomicMin(&g_negkey[bj * 128 + cloc], kn);
                    if (kw != NOKEY64) atomicMin(&g_winkey[bj * 128 + cloc], kw);
                }
            }
        }
    }
}

// ===========================================================================
// Loss: per-anchor term, then hierarchical reduction (warp shuffle -> smem ->
// block sum -> ONE atomicAdd per block) to avoid same-address atomic
// serialization (was 8192 same-address atomicAdds).
// ===========================================================================
__global__ void __launch_bounds__(256) loss_kernel(int N, int D, float* __restrict__ out) {
    int i = blockIdx.x * blockDim.x + threadIdx.x;
    float term = 0.0f;
    if (i < N) {
        u64 posk = g_poskey[i];
        u64 negk = g_negkey[i];
        u64 wink = g_winkey[i];

        int p;
        float d2p;
        if (posk != 0ULL) {
            p = 8191 - (int)(posk & 8191ULL);
            d2p = __uint_as_float((unsigned)(posk >> 13));
        } else {
            // No positive (singleton class): reference argmax picks index 0.
            p = 0;
            const __half* a = g_Eh + (size_t)i * D;
            const __half* b = g_Eh;
            float dot = 0.0f;
            for (int k = 0; k < D; k++)
                dot = fmaf(__half2float(a[k]), __half2float(b[k]), dot);
            d2p = clean_d2(g_sq[i] + g_sq[0] - 2.0f * dot);
        }

        float dpv = sqrtf(d2p);
        float hi2 = (dpv + MARGIN) * (dpv + MARGIN);
        int neg;
        float d2n;
        if (posk != 0ULL && wink != ~0ULL && wink != NOKEY64 &&
            __uint_as_float((unsigned)(wink >> 13)) < hi2) {
            neg = (int)(wink & 8191ULL);
            d2n = __uint_as_float((unsigned)(wink >> 13));
        } else if (negk != ~0ULL && negk != NOKEY64) {
            neg = (int)(negk & 8191ULL);
            d2n = __uint_as_float((unsigned)(negk >> 13));
        } else {
            neg = 0;
            d2n = 0.0f;
        }

        float si = g_s[i];
        float epsC = (float)D * EPS * EPS;
        float dp = sqrtf(fmaxf(d2p + 2.0f * EPS * (si - g_s[p]) + epsC, 0.0f));
        float dn = sqrtf(fmaxf(d2n + 2.0f * EPS * (si - g_s[neg]) + epsC, 0.0f));
        term = fmaxf(dp - dn + MARGIN, 0.0f) / (float)N;
    }

    // Hierarchical reduction: warp -> smem -> block -> one atomic.
#pragma unroll
    for (int off = 16; off > 0; off >>= 1)
        term += __shfl_down_sync(0xffffffffu, term, off);
    __shared__ float ws[8];
    int w = threadIdx.x >> 5;
    if ((threadIdx.x & 31) == 0) ws[w] = term;
    __syncthreads();
    if (threadIdx.x == 0) {
        float s = 0.0f;
#pragma unroll
        for (int x = 0; x < 8; x++) s += ws[x];
        atomicAdd(out, s);
    }
}

// ---------------------------------------------------------------------------
extern "C" void kernel_launch(void* const* d_in, const int* in_sizes, int n_in,
                              void* d_out, int out_size) {
    const float* E = (const float*)d_in[0];   // embeddings [N, D] fp32
    const int* target = (const int*)d_in[1];  // [N] int32
    float* out = (float*)d_out;

    int N = in_sizes[1];
    int D = in_sizes[0] / N;

    prep_kernel<<<N / 4, 256>>>(E, N, D, out);
    classlist_kernel<<<(N + 255) / 256, 256>>>(target, N);

    cudaFuncSetAttribute(fused_gram_kernel, cudaFuncAttributeMaxDynamicSharedMemorySize, GRAM_SMEM);
    int nt = N / 128;
    int ntri = nt * (nt + 1) / 2;             // 2080 triangular tile pairs
    fused_gram_kernel<<<NCLS + ntri, 256, GRAM_SMEM>>>(target, N, D);

    loss_kernel<<<(N + 255) / 256, 256>>>(N, D, out);
}